// round 1
// baseline (speedup 1.0000x reference)
#include <cuda_runtime.h>

#define Sd 48
#define SP (Sd*Sd*Sd)      // 110592
#define Bb 2
#define Cc 128
#define CSd 64
#define NVx (Bb*SP)        // 221184

// ---------------- scratch (device globals; no allocations allowed) --------
__device__ float g_h[(size_t)Bb*Cc*SP];        // h, channel-first [B][C][sp]
__device__ float g_T[(size_t)NVx*CSd];         // t (later reused as Ycomb)
__device__ float g_P[(size_t)NVx*CSd];
__device__ float g_G[(size_t)NVx*CSd];
__device__ float g_Yd[(size_t)NVx*CSd];
__device__ float g_Yh[(size_t)NVx*CSd];
__device__ float g_Yw[(size_t)NVx*CSd];
__device__ float g_md[NVx]; __device__ float g_sd[NVx];
__device__ float g_mh[NVx]; __device__ float g_sh[NVx];
__device__ float g_mw[NVx]; __device__ float g_sw[NVx];
__device__ float g_cross[(size_t)NVx*Cc];      // cross, channel-last [vox][128]
__device__ float g_gnsum[Bb*32]; __device__ float g_gnss[Bb*32];
__device__ float g_bnsum[Cc];    __device__ float g_bnss[Cc];

// ---------------- copy input into h ---------------------------------------
__global__ __launch_bounds__(256) void copy_in(const float4* __restrict__ x) {
    size_t i = (size_t)blockIdx.x * 256 + threadIdx.x;
    if (i < (size_t)Bb*Cc*SP/4) ((float4*)g_h)[i] = x[i];
}

// ---------------- projection: TPG[vox][192] = Wcat @ h ---------------------
__global__ __launch_bounds__(256) void proj_kernel(
    const float* __restrict__ tw, const float* __restrict__ tb,
    const float* __restrict__ pw, const float* __restrict__ pb,
    const float* __restrict__ gw, const float* __restrict__ gb)
{
    __shared__ float Ws[32][192];   // [k][m]
    __shared__ float Hs[32][64];    // [k][n]
    const int b  = blockIdx.y;
    const int n0 = blockIdx.x * 64;
    const int tid = threadIdx.x;
    const int tm = tid >> 3;        // 0..31 -> 6 m each
    const int tn = tid & 7;         // 0..7  -> 8 n each
    float acc[6][8];
    #pragma unroll
    for (int i = 0; i < 6; i++)
        #pragma unroll
        for (int j = 0; j < 8; j++) acc[i][j] = 0.f;

    for (int k0 = 0; k0 < 128; k0 += 32) {
        for (int l = tid; l < 32*192; l += 256) {
            int kk = l / 192, m = l % 192;
            float v;
            if (m < 64)       v = tw[m*128 + k0 + kk];
            else if (m < 128) v = pw[(m-64)*128 + k0 + kk];
            else              v = gw[(m-128)*128 + k0 + kk];
            Ws[kk][m] = v;
        }
        for (int l = tid; l < 32*64; l += 256) {
            int kk = l >> 6, n = l & 63;
            Hs[kk][n] = g_h[(size_t)(b*Cc + k0 + kk)*SP + n0 + n];
        }
        __syncthreads();
        #pragma unroll 4
        for (int kk = 0; kk < 32; kk++) {
            float a[6];
            #pragma unroll
            for (int i = 0; i < 6; i++) a[i] = Ws[kk][tm*6 + i];
            float4 b0 = *(const float4*)&Hs[kk][tn*8];
            float4 b1 = *(const float4*)&Hs[kk][tn*8 + 4];
            float bv[8] = {b0.x,b0.y,b0.z,b0.w,b1.x,b1.y,b1.z,b1.w};
            #pragma unroll
            for (int i = 0; i < 6; i++)
                #pragma unroll
                for (int j = 0; j < 8; j++) acc[i][j] += a[i] * bv[j];
        }
        __syncthreads();
    }
    #pragma unroll
    for (int i = 0; i < 6; i++) {
        int m = tm*6 + i;
        float bias; float* dst; int mm;
        if (m < 64)       { dst = g_T; mm = m;      bias = tb[mm]; }
        else if (m < 128) { dst = g_P; mm = m - 64; bias = pb[mm]; }
        else              { dst = g_G; mm = m - 128; bias = gb[mm]; }
        #pragma unroll
        for (int j = 0; j < 8; j++) {
            int sp = n0 + tn*8 + j;
            dst[(size_t)(b*SP + sp)*64 + mm] = acc[i][j] + bias;
        }
    }
}

// ---------------- per-direction pencil attention ---------------------------
// DIR 0: D-axis (no mask), 1: H-axis (diag mask), 2: W-axis (diag mask)
template<int DIR>
__global__ __launch_bounds__(256) void attn_kernel() {
    __shared__ float Tl[48][68];
    __shared__ float Pl[48][68];
    __shared__ float Gl[48][64];
    __shared__ float Sm[48][49];
    __shared__ float rmax[48], rsum[48];

    const int pid = blockIdx.x;
    const int b = pid / (Sd*Sd);
    const int rr = pid % (Sd*Sd);
    const int u = rr / Sd, v = rr % Sd;
    size_t base; int stride;
    if (DIR == 0)      { base = (size_t)b*SP + u*Sd + v;        stride = Sd*Sd; }
    else if (DIR == 1) { base = (size_t)b*SP + u*Sd*Sd + v;     stride = Sd;    }
    else               { base = (size_t)b*SP + u*Sd*Sd + v*Sd;  stride = 1;     }
    const bool MASK = (DIR != 0);
    const int tid = threadIdx.x;

    for (int l = tid; l < 48*64; l += 256) {
        int i = l >> 6, k = l & 63;
        size_t o = (base + (size_t)i*stride)*64 + k;
        Tl[i][k] = g_T[o]; Pl[i][k] = g_P[o]; Gl[i][k] = g_G[o];
    }
    __syncthreads();

    const int ty = tid >> 4, tx = tid & 15;
    const int ib = ty*3, jb = tx*3;
    float acc[3][3] = {};
    for (int k = 0; k < 64; k += 4) {
        float4 t0 = *(const float4*)&Tl[ib  ][k];
        float4 t1 = *(const float4*)&Tl[ib+1][k];
        float4 t2 = *(const float4*)&Tl[ib+2][k];
        float4 p0 = *(const float4*)&Pl[jb  ][k];
        float4 p1 = *(const float4*)&Pl[jb+1][k];
        float4 p2 = *(const float4*)&Pl[jb+2][k];
        acc[0][0] += t0.x*p0.x + t0.y*p0.y + t0.z*p0.z + t0.w*p0.w;
        acc[0][1] += t0.x*p1.x + t0.y*p1.y + t0.z*p1.z + t0.w*p1.w;
        acc[0][2] += t0.x*p2.x + t0.y*p2.y + t0.z*p2.z + t0.w*p2.w;
        acc[1][0] += t1.x*p0.x + t1.y*p0.y + t1.z*p0.z + t1.w*p0.w;
        acc[1][1] += t1.x*p1.x + t1.y*p1.y + t1.z*p1.z + t1.w*p1.w;
        acc[1][2] += t1.x*p2.x + t1.y*p2.y + t1.z*p2.z + t1.w*p2.w;
        acc[2][0] += t2.x*p0.x + t2.y*p0.y + t2.z*p0.z + t2.w*p0.w;
        acc[2][1] += t2.x*p1.x + t2.y*p1.y + t2.z*p1.z + t2.w*p1.w;
        acc[2][2] += t2.x*p2.x + t2.y*p2.y + t2.z*p2.z + t2.w*p2.w;
    }
    #pragma unroll
    for (int r = 0; r < 3; r++)
        #pragma unroll
        for (int c = 0; c < 3; c++) {
            int i = ib + r, j = jb + c;
            float vv = acc[r][c];
            if (MASK && i == j) vv = -1e30f;
            acc[r][c] = vv;
            Sm[i][j] = vv;
        }
    __syncthreads();
    if (tid < 48) {
        float m = -3.0e38f;
        for (int j = 0; j < 48; j++) m = fmaxf(m, Sm[tid][j]);
        float s = 0.f;
        for (int j = 0; j < 48; j++) s += __expf(Sm[tid][j] - m);
        rmax[tid] = m; rsum[tid] = s;
    }
    __syncthreads();
    #pragma unroll
    for (int r = 0; r < 3; r++) {
        float m = rmax[ib + r];
        #pragma unroll
        for (int c = 0; c < 3; c++) Sm[ib + r][jb + c] = __expf(acc[r][c] - m);
    }
    __syncthreads();

    const int cb = tx*4;
    float4 o0 = {0,0,0,0}, o1 = {0,0,0,0}, o2 = {0,0,0,0};
    for (int j = 0; j < 48; j++) {
        float e0 = Sm[ib][j], e1 = Sm[ib+1][j], e2 = Sm[ib+2][j];
        float4 gv = *(const float4*)&Gl[j][cb];
        o0.x += e0*gv.x; o0.y += e0*gv.y; o0.z += e0*gv.z; o0.w += e0*gv.w;
        o1.x += e1*gv.x; o1.y += e1*gv.y; o1.z += e1*gv.z; o1.w += e1*gv.w;
        o2.x += e2*gv.x; o2.y += e2*gv.y; o2.z += e2*gv.z; o2.w += e2*gv.w;
    }
    float* Yout = (DIR==0) ? g_Yd : ((DIR==1) ? g_Yh : g_Yw);
    float* Mo   = (DIR==0) ? g_md : ((DIR==1) ? g_mh : g_mw);
    float* So   = (DIR==0) ? g_sd : ((DIR==1) ? g_sh : g_sw);
    *(float4*)&Yout[(base + (size_t)(ib  )*stride)*64 + cb] = o0;
    *(float4*)&Yout[(base + (size_t)(ib+1)*stride)*64 + cb] = o1;
    *(float4*)&Yout[(base + (size_t)(ib+2)*stride)*64 + cb] = o2;
    if (tid < 48) {
        size_t vox = base + (size_t)tid*stride;
        Mo[vox] = rmax[tid]; So[vox] = rsum[tid];
    }
}

// ---------------- flash-style combine of the 3 directions ------------------
__global__ __launch_bounds__(256) void combine_kernel() {
    int t = blockIdx.x*256 + threadIdx.x;         // NVx*16 threads, 4 floats each
    if (t >= NVx*16) return;
    int vox = t >> 4; int c4 = (t & 15) * 4;
    float md = g_md[vox], sd = g_sd[vox];
    float mh = g_mh[vox], sh = g_sh[vox];
    float mw = g_mw[vox], sw = g_sw[vox];
    float m  = fmaxf(md, fmaxf(mh, mw));
    float wd = __expf(md - m), wh = __expf(mh - m), ww = __expf(mw - m);
    float inv = 1.0f / (sd*wd + sh*wh + sw*ww);
    size_t o = (size_t)vox*64 + c4;
    float4 a = *(const float4*)&g_Yd[o];
    float4 bq = *(const float4*)&g_Yh[o];
    float4 cq = *(const float4*)&g_Yw[o];
    float4 r;
    r.x = (a.x*wd + bq.x*wh + cq.x*ww) * inv;
    r.y = (a.y*wd + bq.y*wh + cq.y*ww) * inv;
    r.z = (a.z*wd + bq.z*wh + cq.z*ww) * inv;
    r.w = (a.w*wd + bq.w*wh + cq.w*ww) * inv;
    *(float4*)&g_T[o] = r;                        // reuse g_T as Ycomb
}

// ---------------- zero stat accumulators -----------------------------------
__global__ void zero_gn() { int t = threadIdx.x; if (t < Bb*32) { g_gnsum[t]=0.f; g_gnss[t]=0.f; } }
__global__ void zero_bn() { int t = threadIdx.x; if (t < Cc)    { g_bnsum[t]=0.f; g_bnss[t]=0.f; } }

// ---------------- cross GEMM + GroupNorm partial sums ----------------------
__global__ __launch_bounds__(256) void cross_kernel(
    const float* __restrict__ rw, const float* __restrict__ rb)
{
    __shared__ float Rs[32][128];   // [k][m]
    __shared__ float Ys[64][37];    // [n][k], pitch 37
    __shared__ float gsum[32], gss[32];
    const int b = blockIdx.y, n0 = blockIdx.x * 64, tid = threadIdx.x;
    const int tm = tid >> 3, tn = tid & 7;    // 4 m, 8 n per thread
    if (tid < 32) { gsum[tid] = 0.f; gss[tid] = 0.f; }
    float acc[4][8] = {};
    for (int g0 = 0; g0 < 64; g0 += 32) {
        __syncthreads();
        for (int l = tid; l < 32*128; l += 256) {
            int kk = l >> 7, m = l & 127;
            Rs[kk][m] = rw[m*64 + g0 + kk];
        }
        for (int l = tid; l < 64*32; l += 256) {
            int kk = l & 31, n = l >> 5;
            Ys[n][kk] = g_T[(size_t)(b*SP + n0 + n)*64 + g0 + kk];
        }
        __syncthreads();
        #pragma unroll 4
        for (int kk = 0; kk < 32; kk++) {
            float rv[4], yv[8];
            #pragma unroll
            for (int i = 0; i < 4; i++) rv[i] = Rs[kk][tm*4 + i];
            #pragma unroll
            for (int j = 0; j < 8; j++) yv[j] = Ys[tn*8 + j][kk];
            #pragma unroll
            for (int i = 0; i < 4; i++)
                #pragma unroll
                for (int j = 0; j < 8; j++) acc[i][j] += rv[i] * yv[j];
        }
    }
    float b0 = rb[tm*4], b1 = rb[tm*4+1], b2 = rb[tm*4+2], b3 = rb[tm*4+3];
    float lsum = 0.f, lss = 0.f;
    #pragma unroll
    for (int j = 0; j < 8; j++) {
        int sp = n0 + tn*8 + j;
        float4 v;
        v.x = acc[0][j] + b0; v.y = acc[1][j] + b1;
        v.z = acc[2][j] + b2; v.w = acc[3][j] + b3;
        lsum += v.x + v.y + v.z + v.w;
        lss  += v.x*v.x + v.y*v.y + v.z*v.z + v.w*v.w;
        *(float4*)&g_cross[(size_t)(b*SP + sp)*128 + tm*4] = v;
    }
    atomicAdd(&gsum[tm], lsum);    // group index == tm (channels 4tm..4tm+3)
    atomicAdd(&gss[tm],  lss);
    __syncthreads();
    if (tid < 32) {
        atomicAdd(&g_gnsum[b*32 + tid], gsum[tid]);
        atomicAdd(&g_gnss[b*32 + tid],  gss[tid]);
    }
}

// ---------------- GroupNorm + residual (transpose to channel-first) --------
__global__ __launch_bounds__(256) void gnres_kernel(
    const float* __restrict__ gnw, const float* __restrict__ gnb)
{
    __shared__ float sm[32*129];
    const int b = blockIdx.y, sp0 = blockIdx.x * 32, tid = threadIdx.x;
    for (int l = tid; l < 4096; l += 256) {
        int v = l >> 7, c = l & 127;
        sm[v*129 + c] = g_cross[(size_t)(b*SP + sp0 + v)*128 + c];
    }
    __syncthreads();
    const int lane = tid & 31, w = tid >> 5;
    const float invN = 1.0f / (4.0f * SP);
    #pragma unroll
    for (int cc = 0; cc < 16; cc++) {
        int c = w + cc*8;
        int g = c >> 2;
        float mu  = g_gnsum[b*32 + g] * invN;
        float var = g_gnss[b*32 + g] * invN - mu*mu;
        float rstd = rsqrtf(var + 1e-5f);
        float val = (sm[lane*129 + c] - mu) * rstd * gnw[c] + gnb[c];
        size_t hi = (size_t)(b*Cc + c)*SP + sp0 + lane;
        g_h[hi] += val;
    }
}

// ---------------- BatchNorm stats + apply ----------------------------------
__global__ __launch_bounds__(256) void bnstats_kernel() {
    const int b = blockIdx.x >> 7, c = blockIdx.x & 127;
    const size_t base = (size_t)(b*Cc + c)*SP;
    float s = 0.f, ss = 0.f;
    for (int l = threadIdx.x; l < SP; l += 256) {
        float v = g_h[base + l]; s += v; ss += v*v;
    }
    __shared__ float rs[256], rss[256];
    rs[threadIdx.x] = s; rss[threadIdx.x] = ss;
    __syncthreads();
    for (int k = 128; k > 0; k >>= 1) {
        if (threadIdx.x < k) { rs[threadIdx.x] += rs[threadIdx.x + k]; rss[threadIdx.x] += rss[threadIdx.x + k]; }
        __syncthreads();
    }
    if (threadIdx.x == 0) { atomicAdd(&g_bnsum[c], rs[0]); atomicAdd(&g_bnss[c], rss[0]); }
}

__global__ __launch_bounds__(256) void bnapply_kernel(
    const float* __restrict__ bw, const float* __restrict__ bb, float* __restrict__ out)
{
    size_t i4 = (size_t)blockIdx.x*256 + threadIdx.x;
    if (i4 >= (size_t)Bb*Cc*SP/4) return;
    size_t i = i4 * 4;
    int c = (int)((i / SP) & 127);
    const float invN = 1.0f / ((float)Bb * SP);
    float mu  = g_bnsum[c] * invN;
    float var = g_bnss[c] * invN - mu*mu;
    float rstd = rsqrtf(var + 1e-5f);
    float wv = bw[c], bv = bb[c];
    float4 v = *(const float4*)&g_h[i];
    v.x = fmaxf((v.x - mu)*rstd*wv + bv, 0.f);
    v.y = fmaxf((v.y - mu)*rstd*wv + bv, 0.f);
    v.z = fmaxf((v.z - mu)*rstd*wv + bv, 0.f);
    v.w = fmaxf((v.w - mu)*rstd*wv + bv, 0.f);
    *(float4*)&out[i] = v;
}

// ---------------- launch ----------------------------------------------------
extern "C" void kernel_launch(void* const* d_in, const int* in_sizes, int n_in,
                              void* d_out, int out_size)
{
    const float* x   = (const float*)d_in[0];
    const float* tw  = (const float*)d_in[1];
    const float* tb  = (const float*)d_in[2];
    const float* pw  = (const float*)d_in[3];
    const float* pb  = (const float*)d_in[4];
    const float* gw  = (const float*)d_in[5];
    const float* gb  = (const float*)d_in[6];
    const float* rw  = (const float*)d_in[7];
    const float* rb  = (const float*)d_in[8];
    const float* gnw = (const float*)d_in[9];
    const float* gnb = (const float*)d_in[10];
    const float* bnw = (const float*)d_in[11];
    const float* bnb = (const float*)d_in[12];
    float* out = (float*)d_out;

    const int nvec = Bb*Cc*SP/4;
    copy_in<<<(nvec + 255)/256, 256>>>((const float4*)x);

    for (int layer = 0; layer < 2; layer++) {
        proj_kernel<<<dim3(SP/64, Bb), 256>>>(tw, tb, pw, pb, gw, gb);
        attn_kernel<0><<<Bb*Sd*Sd, 256>>>();
        attn_kernel<1><<<Bb*Sd*Sd, 256>>>();
        attn_kernel<2><<<Bb*Sd*Sd, 256>>>();
        combine_kernel<<<(NVx*16 + 255)/256, 256>>>();
        zero_gn<<<1, 64>>>();
        cross_kernel<<<dim3(SP/64, Bb), 256>>>(rw, rb);
        gnres_kernel<<<dim3(SP/32, Bb), 256>>>(gnw + layer*Cc, gnb + layer*Cc);
    }
    zero_bn<<<1, 128>>>();
    bnstats_kernel<<<Bb*Cc, 256>>>();
    bnapply_kernel<<<(nvec + 255)/256, 256>>>(bnw, bnb, out);
}

// round 4
// speedup vs baseline: 1.2253x; 1.2253x over previous
#include <cuda_runtime.h>

#define Sd 48
#define SP (Sd*Sd*Sd)      // 110592
#define Bb 2
#define Cc 128
#define NVx (Bb*SP)        // 221184

typedef unsigned long long u64;

__device__ __forceinline__ u64 pk2(float x, float y) {
    u64 r; asm("mov.b64 %0,{%1,%2};" : "=l"(r) : "f"(x), "f"(y)); return r;
}
__device__ __forceinline__ float2 up2(u64 v) {
    float2 r; asm("mov.b64 {%0,%1},%2;" : "=f"(r.x), "=f"(r.y) : "l"(v)); return r;
}
#define FMA2(d, a, b) asm("fma.rn.f32x2 %0, %1, %2, %0;" : "+l"(d) : "l"(a), "l"(b))

// ---------------- scratch --------------------------------------------------
__device__ float g_h[(size_t)Bb*Cc*SP];
__device__ float g_T[(size_t)NVx*64];
__device__ float g_P[(size_t)NVx*64];          // P; later reused as Ycomb (g-major)
__device__ float g_G[(size_t)NVx*64];
__device__ float g_Yd[(size_t)NVx*64];
__device__ float g_Yh[(size_t)NVx*64];
__device__ float g_Yw[(size_t)NVx*64];
__device__ float g_md[NVx]; __device__ float g_sd[NVx];
__device__ float g_mh[NVx]; __device__ float g_sh[NVx];
__device__ float g_mw[NVx]; __device__ float g_sw[NVx];
__device__ float g_cross[(size_t)Bb*Cc*SP];    // channel-first
__device__ float g_WT[128*192];                // k-major fused theta/phi/G weights
__device__ float g_rwT[64*128];                // k-major r_w
__device__ float g_gnsum[Bb*32]; __device__ float g_gnss[Bb*32];
__device__ float g_bnsum[Cc];    __device__ float g_bnss[Cc];

// ---------------- one-time weight transpose --------------------------------
__global__ __launch_bounds__(256) void wtrans_kernel(
    const float* __restrict__ tw, const float* __restrict__ pw,
    const float* __restrict__ gw, const float* __restrict__ rw)
{
    int idx = blockIdx.x*256 + threadIdx.x;
    if (idx < 128*192) {
        int k = idx / 192, m = idx % 192;
        float v;
        if (m < 64)       v = tw[m*128 + k];
        else if (m < 128) v = pw[(m-64)*128 + k];
        else              v = gw[(m-128)*128 + k];
        g_WT[idx] = v;
    }
    if (idx < 64*128) {
        int k = idx >> 7, m = idx & 127;
        g_rwT[idx] = rw[m*64 + k];
    }
}

// ---------------- projection: [vox][192] = Wcat @ src ----------------------
// 192 threads: tm=tid>>3 (24 groups of 8 m), tn=tid&7 (8 groups of 8 vox)
__global__ __launch_bounds__(192) void proj_kernel(
    int layer, const float* __restrict__ x,
    const float* __restrict__ tb, const float* __restrict__ pb,
    const float* __restrict__ gb)
{
    const float* src = layer ? (const float*)g_h : x;   // device-side symbol resolve
    __shared__ __align__(16) float Ws[32][192];
    __shared__ __align__(16) float Hs[32][64];
    const int b = blockIdx.y, n0 = blockIdx.x*64, tid = threadIdx.x;
    const int tm = tid >> 3, tn = tid & 7;

    u64 acc2[8][4];
    #pragma unroll
    for (int i = 0; i < 8; i++)
        #pragma unroll
        for (int j = 0; j < 4; j++) acc2[i][j] = 0ull;

    for (int k0 = 0; k0 < 128; k0 += 32) {
        #pragma unroll 4
        for (int kk = 0; kk < 32; kk++)
            Ws[kk][tid] = g_WT[(k0 + kk)*192 + tid];
        for (int l = tid; l < 32*64; l += 192) {
            int kk = l >> 6, n = l & 63;
            Hs[kk][n] = src[(size_t)(b*Cc + k0 + kk)*SP + n0 + n];
        }
        __syncthreads();
        #pragma unroll 2
        for (int kk = 0; kk < 32; kk++) {
            float4 A0 = *(const float4*)&Ws[kk][tm*8];
            float4 A1 = *(const float4*)&Ws[kk][tm*8 + 4];
            u64 a2[8];
            a2[0]=pk2(A0.x,A0.x); a2[1]=pk2(A0.y,A0.y); a2[2]=pk2(A0.z,A0.z); a2[3]=pk2(A0.w,A0.w);
            a2[4]=pk2(A1.x,A1.x); a2[5]=pk2(A1.y,A1.y); a2[6]=pk2(A1.z,A1.z); a2[7]=pk2(A1.w,A1.w);
            ulonglong2 H0 = *(const ulonglong2*)&Hs[kk][tn*8];
            ulonglong2 H1 = *(const ulonglong2*)&Hs[kk][tn*8 + 4];
            u64 b2[4] = {H0.x, H0.y, H1.x, H1.y};
            #pragma unroll
            for (int i = 0; i < 8; i++)
                #pragma unroll
                for (int j = 0; j < 4; j++) FMA2(acc2[i][j], a2[i], b2[j]);
        }
        __syncthreads();
    }

    const int m8 = tm*8;
    const float* bias = (m8 < 64) ? tb : ((m8 < 128) ? pb : gb);
    float* dst        = (m8 < 64) ? g_T : ((m8 < 128) ? g_P : g_G);
    const int mm = m8 & 63;
    float4 bv0 = *(const float4*)&bias[mm];
    float4 bv1 = *(const float4*)&bias[mm + 4];
    #pragma unroll
    for (int j = 0; j < 4; j++) {
        float2 u[8];
        #pragma unroll
        for (int i = 0; i < 8; i++) u[i] = up2(acc2[i][j]);
        size_t vA = (size_t)b*SP + n0 + tn*8 + 2*j;
        float4 v0, v1;
        v0.x=u[0].x+bv0.x; v0.y=u[1].x+bv0.y; v0.z=u[2].x+bv0.z; v0.w=u[3].x+bv0.w;
        v1.x=u[4].x+bv1.x; v1.y=u[5].x+bv1.y; v1.z=u[6].x+bv1.z; v1.w=u[7].x+bv1.w;
        *(float4*)&dst[vA*64 + mm]     = v0;
        *(float4*)&dst[vA*64 + mm + 4] = v1;
        v0.x=u[0].y+bv0.x; v0.y=u[1].y+bv0.y; v0.z=u[2].y+bv0.z; v0.w=u[3].y+bv0.w;
        v1.x=u[4].y+bv1.x; v1.y=u[5].y+bv1.y; v1.z=u[6].y+bv1.z; v1.w=u[7].y+bv1.w;
        *(float4*)&dst[(vA+1)*64 + mm]     = v0;
        *(float4*)&dst[(vA+1)*64 + mm + 4] = v1;
    }
}

// ---------------- per-direction pencil attention ----------------------------
template<int DIR>
__global__ __launch_bounds__(256) void attn_kernel() {
    __shared__ __align__(16) float Tl[48][68];
    __shared__ __align__(16) float Pl[48][68];   // P during scores, then G
    __shared__ float Sm[48][49];

    const int pid = blockIdx.x;
    const int b = pid / (Sd*Sd);
    const int rr = pid % (Sd*Sd);
    const int u = rr / Sd, v = rr % Sd;
    size_t base; int stride;
    if (DIR == 0)      { base = (size_t)b*SP + u*Sd + v;       stride = Sd*Sd; }
    else if (DIR == 1) { base = (size_t)b*SP + u*Sd*Sd + v;    stride = Sd;    }
    else               { base = (size_t)b*SP + u*Sd*Sd + v*Sd; stride = 1;     }
    const int tid = threadIdx.x;

    for (int l = tid; l < 48*64; l += 256) {
        int i = l >> 6, k = l & 63;
        size_t o = (base + (size_t)i*stride)*64 + k;
        Tl[i][k] = g_T[o]; Pl[i][k] = g_P[o];
    }
    __syncthreads();

    const int ty = tid >> 4, tx = tid & 15;
    const int ib = ty*3, jb = tx*3;

    u64 acc2[9];
    #pragma unroll
    for (int q = 0; q < 9; q++) acc2[q] = 0ull;
    #pragma unroll 4
    for (int k = 0; k < 64; k += 4) {
        ulonglong2 t0 = *(const ulonglong2*)&Tl[ib  ][k];
        ulonglong2 t1 = *(const ulonglong2*)&Tl[ib+1][k];
        ulonglong2 t2 = *(const ulonglong2*)&Tl[ib+2][k];
        ulonglong2 p0 = *(const ulonglong2*)&Pl[jb  ][k];
        ulonglong2 p1 = *(const ulonglong2*)&Pl[jb+1][k];
        ulonglong2 p2 = *(const ulonglong2*)&Pl[jb+2][k];
        FMA2(acc2[0], t0.x, p0.x); FMA2(acc2[0], t0.y, p0.y);
        FMA2(acc2[1], t0.x, p1.x); FMA2(acc2[1], t0.y, p1.y);
        FMA2(acc2[2], t0.x, p2.x); FMA2(acc2[2], t0.y, p2.y);
        FMA2(acc2[3], t1.x, p0.x); FMA2(acc2[3], t1.y, p0.y);
        FMA2(acc2[4], t1.x, p1.x); FMA2(acc2[4], t1.y, p1.y);
        FMA2(acc2[5], t1.x, p2.x); FMA2(acc2[5], t1.y, p2.y);
        FMA2(acc2[6], t2.x, p0.x); FMA2(acc2[6], t2.y, p0.y);
        FMA2(acc2[7], t2.x, p1.x); FMA2(acc2[7], t2.y, p1.y);
        FMA2(acc2[8], t2.x, p2.x); FMA2(acc2[8], t2.y, p2.y);
    }
    float sc[9];
    #pragma unroll
    for (int q = 0; q < 9; q++) { float2 w = up2(acc2[q]); sc[q] = w.x + w.y; }
    if (DIR != 0) {
        #pragma unroll
        for (int r = 0; r < 3; r++)
            #pragma unroll
            for (int c = 0; c < 3; c++)
                if (ib + r == jb + c) sc[r*3 + c] = -1e30f;
    }
    float rm[3], rs[3];
    #pragma unroll
    for (int r = 0; r < 3; r++)
        rm[r] = fmaxf(sc[r*3], fmaxf(sc[r*3+1], sc[r*3+2]));
    #pragma unroll
    for (int o = 8; o > 0; o >>= 1) {
        #pragma unroll
        for (int r = 0; r < 3; r++)
            rm[r] = fmaxf(rm[r], __shfl_xor_sync(0xffffffffu, rm[r], o));
    }
    #pragma unroll
    for (int r = 0; r < 3; r++) {
        float a = 0.f;
        #pragma unroll
        for (int c = 0; c < 3; c++) {
            float e = __expf(sc[r*3 + c] - rm[r]);
            Sm[ib + r][jb + c] = e;
            a += e;
        }
        rs[r] = a;
    }
    #pragma unroll
    for (int o = 8; o > 0; o >>= 1) {
        #pragma unroll
        for (int r = 0; r < 3; r++)
            rs[r] += __shfl_xor_sync(0xffffffffu, rs[r], o);
    }
    float* Mo = (DIR==0) ? g_md : ((DIR==1) ? g_mh : g_mw);
    float* So = (DIR==0) ? g_sd : ((DIR==1) ? g_sh : g_sw);
    if (tx == 0) {
        #pragma unroll
        for (int r = 0; r < 3; r++) {
            size_t vx = base + (size_t)(ib + r)*stride;
            Mo[vx] = rm[r]; So[vx] = rs[r];
        }
    }
    __syncthreads();                 // Sm written; Pl (P) reads done
    for (int l = tid; l < 48*64; l += 256) {
        int i = l >> 6, k = l & 63;
        Pl[i][k] = g_G[(base + (size_t)i*stride)*64 + k];
    }
    __syncthreads();

    const int cb = tx*4;
    u64 o2[6] = {0ull,0ull,0ull,0ull,0ull,0ull};
    #pragma unroll 4
    for (int j = 0; j < 48; j++) {
        float e0 = Sm[ib  ][j];
        float e1 = Sm[ib+1][j];
        float e2 = Sm[ib+2][j];
        u64 E0 = pk2(e0, e0), E1 = pk2(e1, e1), E2 = pk2(e2, e2);
        ulonglong2 gv = *(const ulonglong2*)&Pl[j][cb];
        FMA2(o2[0], E0, gv.x); FMA2(o2[1], E0, gv.y);
        FMA2(o2[2], E1, gv.x); FMA2(o2[3], E1, gv.y);
        FMA2(o2[4], E2, gv.x); FMA2(o2[5], E2, gv.y);
    }
    float* Yout = (DIR==0) ? g_Yd : ((DIR==1) ? g_Yh : g_Yw);
    #pragma unroll
    for (int r = 0; r < 3; r++) {
        float2 a = up2(o2[2*r]), bqq = up2(o2[2*r + 1]);
        float4 vv; vv.x=a.x; vv.y=a.y; vv.z=bqq.x; vv.w=bqq.y;
        *(float4*)&Yout[(base + (size_t)(ib + r)*stride)*64 + cb] = vv;
    }
}

// ---------------- combine 3 dirs + transpose to g-major --------------------
__global__ __launch_bounds__(256) void combine_kernel() {
    __shared__ __align__(16) float S[64][68];
    const int b = blockIdx.y, n0 = blockIdx.x*64, tid = threadIdx.x;
    const int v = tid >> 2, c16 = (tid & 3)*16;
    size_t vox = (size_t)b*SP + n0 + v;
    float md = g_md[vox], sd = g_sd[vox];
    float mh = g_mh[vox], sh = g_sh[vox];
    float mw = g_mw[vox], sw = g_sw[vox];
    float m  = fmaxf(md, fmaxf(mh, mw));
    float wd = __expf(md - m), wh = __expf(mh - m), ww = __expf(mw - m);
    float inv = 1.0f / (sd*wd + sh*wh + sw*ww);
    wd *= inv; wh *= inv; ww *= inv;
    #pragma unroll
    for (int q = 0; q < 4; q++) {
        int k = c16 + q*4;
        size_t o = vox*64 + k;
        float4 a = *(const float4*)&g_Yd[o];
        float4 h = *(const float4*)&g_Yh[o];
        float4 w = *(const float4*)&g_Yw[o];
        float4 r;
        r.x = a.x*wd + h.x*wh + w.x*ww;
        r.y = a.y*wd + h.y*wh + w.y*ww;
        r.z = a.z*wd + h.z*wh + w.z*ww;
        r.w = a.w*wd + h.w*wh + w.w*ww;
        *(float4*)&S[v][k] = r;
    }
    __syncthreads();
    const int w8 = tid >> 5, lane = tid & 31;
    #pragma unroll
    for (int gr = 0; gr < 8; gr++) {
        int g = w8*8 + gr;
        float2 val;
        val.x = S[lane*2][g];
        val.y = S[lane*2 + 1][g];
        *(float2*)&g_P[((size_t)b*64 + g)*SP + n0 + lane*2] = val;
    }
}

// ---------------- zero stat accumulators ------------------------------------
__global__ void zero_gn() { int t = threadIdx.x; if (t < Bb*32) { g_gnsum[t]=0.f; g_gnss[t]=0.f; } }
__global__ void zero_bn() { int t = threadIdx.x; if (t < Cc)    { g_bnsum[t]=0.f; g_bnss[t]=0.f; } }

// ---------------- cross GEMM (128ch x 128vox tile) + GN partial sums -------
__global__ __launch_bounds__(256) void cross_kernel(const float* __restrict__ rb)
{
    __shared__ __align__(16) float Rs[32][128];
    __shared__ __align__(16) float Ys[32][128];
    const int b = blockIdx.y, n0 = blockIdx.x*128, tid = threadIdx.x;
    const int tm = tid >> 4, tn = tid & 15;

    u64 acc2[8][4];
    #pragma unroll
    for (int i = 0; i < 8; i++)
        #pragma unroll
        for (int j = 0; j < 4; j++) acc2[i][j] = 0ull;

    for (int g0 = 0; g0 < 64; g0 += 32) {
        __syncthreads();
        #pragma unroll 2
        for (int it = 0; it < 16; it++) {
            int idx = it*256 + tid;
            int kk = idx >> 7, m = idx & 127;
            Rs[kk][m] = g_rwT[(g0 + kk)*128 + m];
            Ys[kk][m] = g_P[((size_t)b*64 + g0 + kk)*SP + n0 + m];
        }
        __syncthreads();
        #pragma unroll 2
        for (int kk = 0; kk < 32; kk++) {
            float4 A0 = *(const float4*)&Rs[kk][tm*8];
            float4 A1 = *(const float4*)&Rs[kk][tm*8 + 4];
            u64 a2[8];
            a2[0]=pk2(A0.x,A0.x); a2[1]=pk2(A0.y,A0.y); a2[2]=pk2(A0.z,A0.z); a2[3]=pk2(A0.w,A0.w);
            a2[4]=pk2(A1.x,A1.x); a2[5]=pk2(A1.y,A1.y); a2[6]=pk2(A1.z,A1.z); a2[7]=pk2(A1.w,A1.w);
            ulonglong2 H0 = *(const ulonglong2*)&Ys[kk][tn*8];
            ulonglong2 H1 = *(const ulonglong2*)&Ys[kk][tn*8 + 4];
            u64 b2[4] = {H0.x, H0.y, H1.x, H1.y};
            #pragma unroll
            for (int i = 0; i < 8; i++)
                #pragma unroll
                for (int j = 0; j < 4; j++) FMA2(acc2[i][j], a2[i], b2[j]);
        }
    }

    float s0 = 0.f, ss0 = 0.f, s1 = 0.f, ss1 = 0.f;
    #pragma unroll
    for (int i = 0; i < 8; i++) {
        int ch = tm*8 + i;
        float bias = rb[ch];
        float vv[8];
        #pragma unroll
        for (int j = 0; j < 4; j++) {
            float2 w = up2(acc2[i][j]);
            vv[2*j]   = w.x + bias;
            vv[2*j+1] = w.y + bias;
        }
        float ls = 0.f, lss = 0.f;
        #pragma unroll
        for (int j = 0; j < 8; j++) { ls += vv[j]; lss += vv[j]*vv[j]; }
        if (i < 4) { s0 += ls; ss0 += lss; } else { s1 += ls; ss1 += lss; }
        float4 o0 = {vv[0], vv[1], vv[2], vv[3]};
        float4 o1 = {vv[4], vv[5], vv[6], vv[7]};
        size_t ob = ((size_t)b*Cc + ch)*SP + n0 + tn*8;
        *(float4*)&g_cross[ob]     = o0;
        *(float4*)&g_cross[ob + 4] = o1;
    }
    #pragma unroll
    for (int o = 8; o > 0; o >>= 1) {
        s0  += __shfl_xor_sync(0xffffffffu, s0,  o);
        ss0 += __shfl_xor_sync(0xffffffffu, ss0, o);
        s1  += __shfl_xor_sync(0xffffffffu, s1,  o);
        ss1 += __shfl_xor_sync(0xffffffffu, ss1, o);
    }
    if (tn == 0) {
        atomicAdd(&g_gnsum[b*32 + 2*tm],     s0);
        atomicAdd(&g_gnss [b*32 + 2*tm],     ss0);
        atomicAdd(&g_gnsum[b*32 + 2*tm + 1], s1);
        atomicAdd(&g_gnss [b*32 + 2*tm + 1], ss1);
    }
}

// ---------------- GroupNorm + residual (streaming, channel-first) ----------
__global__ __launch_bounds__(256) void gnres_kernel(
    int layer, const float* __restrict__ x,
    const float* __restrict__ gnw, const float* __restrict__ gnb,
    int accum_bn)
{
    const float* resid = layer ? (const float*)g_h : x;  // device-side symbol resolve
    const int c = blockIdx.y, b = blockIdx.z, chunk = blockIdx.x;
    const size_t base = ((size_t)(b*Cc + c))*SP + (size_t)chunk*(SP/4);
    const int g = c >> 2;
    const float invN = 1.0f / (4.0f * SP);
    float mu  = g_gnsum[b*32 + g] * invN;
    float var = g_gnss[b*32 + g] * invN - mu*mu;
    float rstd = rsqrtf(var + 1e-5f);
    float w = gnw[c], bias = gnb[c];
    float s = 0.f, ss = 0.f;
    for (int j = 0; j < 27; j++) {
        size_t o = base + (size_t)j*1024 + threadIdx.x*4;
        float4 cv = *(const float4*)&g_cross[o];
        float4 rv = *(const float4*)&resid[o];
        float4 h;
        h.x = rv.x + (cv.x - mu)*rstd*w + bias;
        h.y = rv.y + (cv.y - mu)*rstd*w + bias;
        h.z = rv.z + (cv.z - mu)*rstd*w + bias;
        h.w = rv.w + (cv.w - mu)*rstd*w + bias;
        *(float4*)&g_h[o] = h;
        if (accum_bn) {
            s  += h.x + h.y + h.z + h.w;
            ss += h.x*h.x + h.y*h.y + h.z*h.z + h.w*h.w;
        }
    }
    if (accum_bn) {
        #pragma unroll
        for (int o = 16; o > 0; o >>= 1) {
            s  += __shfl_xor_sync(0xffffffffu, s,  o);
            ss += __shfl_xor_sync(0xffffffffu, ss, o);
        }
        __shared__ float ws[8], wss[8];
        int wid = threadIdx.x >> 5, lane = threadIdx.x & 31;
        if (lane == 0) { ws[wid] = s; wss[wid] = ss; }
        __syncthreads();
        if (threadIdx.x == 0) {
            float ts = 0.f, tss = 0.f;
            #pragma unroll
            for (int k = 0; k < 8; k++) { ts += ws[k]; tss += wss[k]; }
            atomicAdd(&g_bnsum[c], ts);
            atomicAdd(&g_bnss[c],  tss);
        }
    }
}

// ---------------- BatchNorm apply + ReLU ------------------------------------
__global__ __launch_bounds__(256) void bnapply_kernel(
    const float* __restrict__ bw, const float* __restrict__ bb, float* __restrict__ out)
{
    size_t i4 = (size_t)blockIdx.x*256 + threadIdx.x;
    if (i4 >= (size_t)Bb*Cc*SP/4) return;
    size_t i = i4 * 4;
    int c = (int)((i / SP) & 127);
    const float invN = 1.0f / ((float)Bb * SP);
    float mu  = g_bnsum[c] * invN;
    float var = g_bnss[c] * invN - mu*mu;
    float rstd = rsqrtf(var + 1e-5f);
    float wv = bw[c], bv = bb[c];
    float4 v = *(const float4*)&g_h[i];
    v.x = fmaxf((v.x - mu)*rstd*wv + bv, 0.f);
    v.y = fmaxf((v.y - mu)*rstd*wv + bv, 0.f);
    v.z = fmaxf((v.z - mu)*rstd*wv + bv, 0.f);
    v.w = fmaxf((v.w - mu)*rstd*wv + bv, 0.f);
    *(float4*)&out[i] = v;
}

// ---------------- launch -----------------------------------------------------
extern "C" void kernel_launch(void* const* d_in, const int* in_sizes, int n_in,
                              void* d_out, int out_size)
{
    const float* x   = (const float*)d_in[0];
    const float* tw  = (const float*)d_in[1];
    const float* tb  = (const float*)d_in[2];
    const float* pw  = (const float*)d_in[3];
    const float* pb  = (const float*)d_in[4];
    const float* gw  = (const float*)d_in[5];
    const float* gb  = (const float*)d_in[6];
    const float* rw  = (const float*)d_in[7];
    const float* rb  = (const float*)d_in[8];
    const float* gnw = (const float*)d_in[9];
    const float* gnb = (const float*)d_in[10];
    const float* bnw = (const float*)d_in[11];
    const float* bnb = (const float*)d_in[12];
    float* out = (float*)d_out;

    wtrans_kernel<<<96, 256>>>(tw, pw, gw, rw);
    zero_bn<<<1, 128>>>();

    for (int layer = 0; layer < 2; layer++) {
        proj_kernel<<<dim3(SP/64, Bb), 192>>>(layer, x, tb, pb, gb);
        attn_kernel<0><<<Bb*Sd*Sd, 256>>>();
        attn_kernel<1><<<Bb*Sd*Sd, 256>>>();
        attn_kernel<2><<<Bb*Sd*Sd, 256>>>();
        combine_kernel<<<dim3(SP/64, Bb), 256>>>();
        zero_gn<<<1, 64>>>();
        cross_kernel<<<dim3(SP/128, Bb), 256>>>(rb);
        gnres_kernel<<<dim3(4, Cc, Bb), 256>>>(layer, x, gnw + layer*Cc, gnb + layer*Cc,
                                               layer == 1 ? 1 : 0);
    }
    bnapply_kernel<<<((Bb*Cc*SP/4) + 255)/256, 256>>>(bnw, bnb, out);
}

// round 5
// speedup vs baseline: 1.3539x; 1.1050x over previous
#include <cuda_runtime.h>

#define Sd 48
#define SP (Sd*Sd*Sd)      // 110592
#define Bb 2
#define Cc 128
#define NVx (Bb*SP)        // 221184

// ---------------- scratch --------------------------------------------------
__device__ float g_h[(size_t)Bb*Cc*SP];
__device__ float g_T[(size_t)NVx*64];
__device__ float g_P[(size_t)NVx*64];          // P; later reused as Ycomb (g-major)
__device__ float g_G[(size_t)NVx*64];
__device__ float g_Yd[(size_t)NVx*64];
__device__ float g_Yh[(size_t)NVx*64];
__device__ float g_Yw[(size_t)NVx*64];
__device__ float g_md[NVx]; __device__ float g_sd[NVx];
__device__ float g_mh[NVx]; __device__ float g_sh[NVx];
__device__ float g_mw[NVx]; __device__ float g_sw[NVx];
__device__ float g_cross[(size_t)Bb*Cc*SP];    // channel-first
__device__ float g_WT[128*192];                // k-major fused theta/phi/G weights
__device__ float g_rwT[64*128];                // k-major r_w
__device__ float g_gnsum[Bb*32]; __device__ float g_gnss[Bb*32];
__device__ float g_bnsum[Cc];    __device__ float g_bnss[Cc];

// ---------------- one-time weight transpose --------------------------------
__global__ __launch_bounds__(256) void wtrans_kernel(
    const float* __restrict__ tw, const float* __restrict__ pw,
    const float* __restrict__ gw, const float* __restrict__ rw)
{
    int idx = blockIdx.x*256 + threadIdx.x;
    if (idx < 128*192) {
        int k = idx / 192, m = idx % 192;
        float v;
        if (m < 64)       v = tw[m*128 + k];
        else if (m < 128) v = pw[(m-64)*128 + k];
        else              v = gw[(m-128)*128 + k];
        g_WT[idx] = v;
    }
    if (idx < 64*128) {
        int k = idx >> 7, m = idx & 127;
        g_rwT[idx] = rw[m*64 + k];
    }
}

// ---------------- projection: [vox][192] = Wcat @ src ----------------------
__global__ __launch_bounds__(192) void proj_kernel(
    int layer, const float* __restrict__ x,
    const float* __restrict__ tb, const float* __restrict__ pb,
    const float* __restrict__ gb)
{
    const float* src = layer ? (const float*)g_h : x;   // device-side symbol resolve
    __shared__ __align__(16) float Ws[32][192];
    __shared__ __align__(16) float Hs[32][64];
    const int b = blockIdx.y, n0 = blockIdx.x*64, tid = threadIdx.x;
    const int tm = tid >> 3, tn = tid & 7;

    float acc[8][8];
    #pragma unroll
    for (int i = 0; i < 8; i++)
        #pragma unroll
        for (int j = 0; j < 8; j++) acc[i][j] = 0.f;

    for (int k0 = 0; k0 < 128; k0 += 32) {
        #pragma unroll 4
        for (int kk = 0; kk < 32; kk++)
            Ws[kk][tid] = g_WT[(k0 + kk)*192 + tid];
        for (int l = tid; l < 32*64; l += 192) {
            int kk = l >> 6, n = l & 63;
            Hs[kk][n] = src[(size_t)(b*Cc + k0 + kk)*SP + n0 + n];
        }
        __syncthreads();
        #pragma unroll 2
        for (int kk = 0; kk < 32; kk++) {
            float4 A0 = *(const float4*)&Ws[kk][tm*8];
            float4 A1 = *(const float4*)&Ws[kk][tm*8 + 4];
            float4 H0 = *(const float4*)&Hs[kk][tn*8];
            float4 H1 = *(const float4*)&Hs[kk][tn*8 + 4];
            float av[8] = {A0.x,A0.y,A0.z,A0.w,A1.x,A1.y,A1.z,A1.w};
            float hv[8] = {H0.x,H0.y,H0.z,H0.w,H1.x,H1.y,H1.z,H1.w};
            #pragma unroll
            for (int i = 0; i < 8; i++)
                #pragma unroll
                for (int j = 0; j < 8; j++) acc[i][j] += av[i] * hv[j];
        }
        __syncthreads();
    }

    const int m8 = tm*8;
    const float* bias = (m8 < 64) ? tb : ((m8 < 128) ? pb : gb);
    float* dst        = (m8 < 64) ? g_T : ((m8 < 128) ? g_P : g_G);
    const int mm = m8 & 63;
    float4 bv0 = *(const float4*)&bias[mm];
    float4 bv1 = *(const float4*)&bias[mm + 4];
    #pragma unroll
    for (int j = 0; j < 8; j++) {
        size_t vA = (size_t)b*SP + n0 + tn*8 + j;
        float4 v0, v1;
        v0.x = acc[0][j]+bv0.x; v0.y = acc[1][j]+bv0.y;
        v0.z = acc[2][j]+bv0.z; v0.w = acc[3][j]+bv0.w;
        v1.x = acc[4][j]+bv1.x; v1.y = acc[5][j]+bv1.y;
        v1.z = acc[6][j]+bv1.z; v1.w = acc[7][j]+bv1.w;
        *(float4*)&dst[vA*64 + mm]     = v0;
        *(float4*)&dst[vA*64 + mm + 4] = v1;
    }
}

// ---------------- per-direction pencil attention ----------------------------
template<int DIR>
__global__ __launch_bounds__(256) void attn_kernel() {
    __shared__ __align__(16) float Tl[48][68];
    __shared__ __align__(16) float Pl[48][68];   // P during scores, then G
    __shared__ float Sm[48][52];

    const int pid = blockIdx.x;
    const int b = pid / (Sd*Sd);
    const int rr = pid % (Sd*Sd);
    const int u = rr / Sd, v = rr % Sd;
    size_t base; int stride;
    if (DIR == 0)      { base = (size_t)b*SP + u*Sd + v;       stride = Sd*Sd; }
    else if (DIR == 1) { base = (size_t)b*SP + u*Sd*Sd + v;    stride = Sd;    }
    else               { base = (size_t)b*SP + u*Sd*Sd + v*Sd; stride = 1;     }
    const int tid = threadIdx.x;

    for (int l = tid; l < 48*64; l += 256) {
        int i = l >> 6, k = l & 63;
        size_t o = (base + (size_t)i*stride)*64 + k;
        Tl[i][k] = g_T[o]; Pl[i][k] = g_P[o];
    }
    __syncthreads();

    const int ty = tid >> 4, tx = tid & 15;
    const int ib = ty*3, jb = tx*3;

    float sc[9];
    #pragma unroll
    for (int q = 0; q < 9; q++) sc[q] = 0.f;
    #pragma unroll 4
    for (int k = 0; k < 64; k += 4) {
        float4 t0 = *(const float4*)&Tl[ib  ][k];
        float4 t1 = *(const float4*)&Tl[ib+1][k];
        float4 t2 = *(const float4*)&Tl[ib+2][k];
        float4 p0 = *(const float4*)&Pl[jb  ][k];
        float4 p1 = *(const float4*)&Pl[jb+1][k];
        float4 p2 = *(const float4*)&Pl[jb+2][k];
        sc[0] += t0.x*p0.x + t0.y*p0.y + t0.z*p0.z + t0.w*p0.w;
        sc[1] += t0.x*p1.x + t0.y*p1.y + t0.z*p1.z + t0.w*p1.w;
        sc[2] += t0.x*p2.x + t0.y*p2.y + t0.z*p2.z + t0.w*p2.w;
        sc[3] += t1.x*p0.x + t1.y*p0.y + t1.z*p0.z + t1.w*p0.w;
        sc[4] += t1.x*p1.x + t1.y*p1.y + t1.z*p1.z + t1.w*p1.w;
        sc[5] += t1.x*p2.x + t1.y*p2.y + t1.z*p2.z + t1.w*p2.w;
        sc[6] += t2.x*p0.x + t2.y*p0.y + t2.z*p0.z + t2.w*p0.w;
        sc[7] += t2.x*p1.x + t2.y*p1.y + t2.z*p1.z + t2.w*p1.w;
        sc[8] += t2.x*p2.x + t2.y*p2.y + t2.z*p2.z + t2.w*p2.w;
    }
    if (DIR != 0) {
        #pragma unroll
        for (int r = 0; r < 3; r++)
            #pragma unroll
            for (int c = 0; c < 3; c++)
                if (ib + r == jb + c) sc[r*3 + c] = -1e30f;
    }
    float rm[3], rs[3];
    #pragma unroll
    for (int r = 0; r < 3; r++)
        rm[r] = fmaxf(sc[r*3], fmaxf(sc[r*3+1], sc[r*3+2]));
    #pragma unroll
    for (int o = 8; o > 0; o >>= 1) {
        #pragma unroll
        for (int r = 0; r < 3; r++)
            rm[r] = fmaxf(rm[r], __shfl_xor_sync(0xffffffffu, rm[r], o));
    }
    #pragma unroll
    for (int r = 0; r < 3; r++) {
        float a = 0.f;
        #pragma unroll
        for (int c = 0; c < 3; c++) {
            float e = __expf(sc[r*3 + c] - rm[r]);
            Sm[ib + r][jb + c] = e;
            a += e;
        }
        rs[r] = a;
    }
    #pragma unroll
    for (int o = 8; o > 0; o >>= 1) {
        #pragma unroll
        for (int r = 0; r < 3; r++)
            rs[r] += __shfl_xor_sync(0xffffffffu, rs[r], o);
    }
    float* Mo = (DIR==0) ? g_md : ((DIR==1) ? g_mh : g_mw);
    float* So = (DIR==0) ? g_sd : ((DIR==1) ? g_sh : g_sw);
    if (tx == 0) {
        #pragma unroll
        for (int r = 0; r < 3; r++) {
            size_t vx = base + (size_t)(ib + r)*stride;
            Mo[vx] = rm[r]; So[vx] = rs[r];
        }
    }
    __syncthreads();                 // Sm written; Pl (P) reads done
    for (int l = tid; l < 48*64; l += 256) {
        int i = l >> 6, k = l & 63;
        Pl[i][k] = g_G[(base + (size_t)i*stride)*64 + k];
    }
    __syncthreads();

    const int cb = tx*4;
    float4 o0 = {0,0,0,0}, o1 = {0,0,0,0}, o2 = {0,0,0,0};
    #pragma unroll 4
    for (int j = 0; j < 48; j++) {
        float e0 = Sm[ib  ][j];
        float e1 = Sm[ib+1][j];
        float e2 = Sm[ib+2][j];
        float4 gv = *(const float4*)&Pl[j][cb];
        o0.x += e0*gv.x; o0.y += e0*gv.y; o0.z += e0*gv.z; o0.w += e0*gv.w;
        o1.x += e1*gv.x; o1.y += e1*gv.y; o1.z += e1*gv.z; o1.w += e1*gv.w;
        o2.x += e2*gv.x; o2.y += e2*gv.y; o2.z += e2*gv.z; o2.w += e2*gv.w;
    }
    float* Yout = (DIR==0) ? g_Yd : ((DIR==1) ? g_Yh : g_Yw);
    *(float4*)&Yout[(base + (size_t)(ib  )*stride)*64 + cb] = o0;
    *(float4*)&Yout[(base + (size_t)(ib+1)*stride)*64 + cb] = o1;
    *(float4*)&Yout[(base + (size_t)(ib+2)*stride)*64 + cb] = o2;
}

// ---------------- combine 3 dirs + transpose to g-major --------------------
__global__ __launch_bounds__(256) void combine_kernel() {
    __shared__ __align__(16) float S[64][68];
    const int b = blockIdx.y, n0 = blockIdx.x*64, tid = threadIdx.x;
    const int v = tid >> 2, c16 = (tid & 3)*16;
    size_t vox = (size_t)b*SP + n0 + v;
    float md = g_md[vox], sd = g_sd[vox];
    float mh = g_mh[vox], sh = g_sh[vox];
    float mw = g_mw[vox], sw = g_sw[vox];
    float m  = fmaxf(md, fmaxf(mh, mw));
    float wd = __expf(md - m), wh = __expf(mh - m), ww = __expf(mw - m);
    float inv = 1.0f / (sd*wd + sh*wh + sw*ww);
    wd *= inv; wh *= inv; ww *= inv;
    #pragma unroll
    for (int q = 0; q < 4; q++) {
        int k = c16 + q*4;
        size_t o = vox*64 + k;
        float4 a = *(const float4*)&g_Yd[o];
        float4 h = *(const float4*)&g_Yh[o];
        float4 w = *(const float4*)&g_Yw[o];
        float4 r;
        r.x = a.x*wd + h.x*wh + w.x*ww;
        r.y = a.y*wd + h.y*wh + w.y*ww;
        r.z = a.z*wd + h.z*wh + w.z*ww;
        r.w = a.w*wd + h.w*wh + w.w*ww;
        *(float4*)&S[v][k] = r;
    }
    __syncthreads();
    const int w8 = tid >> 5, lane = tid & 31;
    #pragma unroll
    for (int gr = 0; gr < 8; gr++) {
        int g = w8*8 + gr;
        float2 val;
        val.x = S[lane*2][g];
        val.y = S[lane*2 + 1][g];
        *(float2*)&g_P[((size_t)b*64 + g)*SP + n0 + lane*2] = val;
    }
}

// ---------------- zero stat accumulators ------------------------------------
__global__ void zero_gn() { int t = threadIdx.x; if (t < Bb*32) { g_gnsum[t]=0.f; g_gnss[t]=0.f; } }
__global__ void zero_bn() { int t = threadIdx.x; if (t < Cc)    { g_bnsum[t]=0.f; g_bnss[t]=0.f; } }

// ---------------- cross GEMM (128ch x 128vox tile) + GN partial sums -------
__global__ __launch_bounds__(256) void cross_kernel(const float* __restrict__ rb)
{
    __shared__ __align__(16) float Rs[32][128];
    __shared__ __align__(16) float Ys[32][128];
    const int b = blockIdx.y, n0 = blockIdx.x*128, tid = threadIdx.x;
    const int tm = tid >> 4, tn = tid & 15;

    float acc[8][8];
    #pragma unroll
    for (int i = 0; i < 8; i++)
        #pragma unroll
        for (int j = 0; j < 8; j++) acc[i][j] = 0.f;

    for (int g0 = 0; g0 < 64; g0 += 32) {
        __syncthreads();
        #pragma unroll 2
        for (int it = 0; it < 16; it++) {
            int idx = it*256 + tid;
            int kk = idx >> 7, m = idx & 127;
            Rs[kk][m] = g_rwT[(g0 + kk)*128 + m];
            Ys[kk][m] = g_P[((size_t)b*64 + g0 + kk)*SP + n0 + m];
        }
        __syncthreads();
        #pragma unroll 2
        for (int kk = 0; kk < 32; kk++) {
            float4 A0 = *(const float4*)&Rs[kk][tm*8];
            float4 A1 = *(const float4*)&Rs[kk][tm*8 + 4];
            float4 H0 = *(const float4*)&Ys[kk][tn*8];
            float4 H1 = *(const float4*)&Ys[kk][tn*8 + 4];
            float av[8] = {A0.x,A0.y,A0.z,A0.w,A1.x,A1.y,A1.z,A1.w};
            float hv[8] = {H0.x,H0.y,H0.z,H0.w,H1.x,H1.y,H1.z,H1.w};
            #pragma unroll
            for (int i = 0; i < 8; i++)
                #pragma unroll
                for (int j = 0; j < 8; j++) acc[i][j] += av[i] * hv[j];
        }
    }

    float s0 = 0.f, ss0 = 0.f, s1 = 0.f, ss1 = 0.f;
    #pragma unroll
    for (int i = 0; i < 8; i++) {
        int ch = tm*8 + i;
        float bias = rb[ch];
        float vv[8];
        float ls = 0.f, lss = 0.f;
        #pragma unroll
        for (int j = 0; j < 8; j++) {
            vv[j] = acc[i][j] + bias;
            ls += vv[j]; lss += vv[j]*vv[j];
        }
        if (i < 4) { s0 += ls; ss0 += lss; } else { s1 += ls; ss1 += lss; }
        float4 o0 = {vv[0], vv[1], vv[2], vv[3]};
        float4 o1 = {vv[4], vv[5], vv[6], vv[7]};
        size_t ob = ((size_t)b*Cc + ch)*SP + n0 + tn*8;
        *(float4*)&g_cross[ob]     = o0;
        *(float4*)&g_cross[ob + 4] = o1;
    }
    #pragma unroll
    for (int o = 8; o > 0; o >>= 1) {
        s0  += __shfl_xor_sync(0xffffffffu, s0,  o);
        ss0 += __shfl_xor_sync(0xffffffffu, ss0, o);
        s1  += __shfl_xor_sync(0xffffffffu, s1,  o);
        ss1 += __shfl_xor_sync(0xffffffffu, ss1, o);
    }
    if (tn == 0) {
        atomicAdd(&g_gnsum[b*32 + 2*tm],     s0);
        atomicAdd(&g_gnss [b*32 + 2*tm],     ss0);
        atomicAdd(&g_gnsum[b*32 + 2*tm + 1], s1);
        atomicAdd(&g_gnss [b*32 + 2*tm + 1], ss1);
    }
}

// ---------------- GroupNorm + residual (streaming, channel-first) ----------
__global__ __launch_bounds__(256) void gnres_kernel(
    int layer, const float* __restrict__ x,
    const float* __restrict__ gnw, const float* __restrict__ gnb,
    int accum_bn)
{
    const float* resid = layer ? (const float*)g_h : x;  // device-side symbol resolve
    const int c = blockIdx.y, b = blockIdx.z, chunk = blockIdx.x;
    const size_t base = ((size_t)(b*Cc + c))*SP + (size_t)chunk*(SP/4);
    const int g = c >> 2;
    const float invN = 1.0f / (4.0f * SP);
    float mu  = g_gnsum[b*32 + g] * invN;
    float var = g_gnss[b*32 + g] * invN - mu*mu;
    float rstd = rsqrtf(var + 1e-5f);
    float w = gnw[c], bias = gnb[c];
    float s = 0.f, ss = 0.f;
    for (int j = 0; j < 27; j++) {
        size_t o = base + (size_t)j*1024 + threadIdx.x*4;
        float4 cv = *(const float4*)&g_cross[o];
        float4 rv = *(const float4*)&resid[o];
        float4 h;
        h.x = rv.x + (cv.x - mu)*rstd*w + bias;
        h.y = rv.y + (cv.y - mu)*rstd*w + bias;
        h.z = rv.z + (cv.z - mu)*rstd*w + bias;
        h.w = rv.w + (cv.w - mu)*rstd*w + bias;
        *(float4*)&g_h[o] = h;
        if (accum_bn) {
            s  += h.x + h.y + h.z + h.w;
            ss += h.x*h.x + h.y*h.y + h.z*h.z + h.w*h.w;
        }
    }
    if (accum_bn) {
        #pragma unroll
        for (int o = 16; o > 0; o >>= 1) {
            s  += __shfl_xor_sync(0xffffffffu, s,  o);
            ss += __shfl_xor_sync(0xffffffffu, ss, o);
        }
        __shared__ float ws[8], wss[8];
        int wid = threadIdx.x >> 5, lane = threadIdx.x & 31;
        if (lane == 0) { ws[wid] = s; wss[wid] = ss; }
        __syncthreads();
        if (threadIdx.x == 0) {
            float ts = 0.f, tss = 0.f;
            #pragma unroll
            for (int k = 0; k < 8; k++) { ts += ws[k]; tss += wss[k]; }
            atomicAdd(&g_bnsum[c], ts);
            atomicAdd(&g_bnss[c],  tss);
        }
    }
}

// ---------------- BatchNorm apply + ReLU ------------------------------------
__global__ __launch_bounds__(256) void bnapply_kernel(
    const float* __restrict__ bw, const float* __restrict__ bb, float* __restrict__ out)
{
    size_t i4 = (size_t)blockIdx.x*256 + threadIdx.x;
    if (i4 >= (size_t)Bb*Cc*SP/4) return;
    size_t i = i4 * 4;
    int c = (int)((i / SP) & 127);
    const float invN = 1.0f / ((float)Bb * SP);
    float mu  = g_bnsum[c] * invN;
    float var = g_bnss[c] * invN - mu*mu;
    float rstd = rsqrtf(var + 1e-5f);
    float wv = bw[c], bv = bb[c];
    float4 v = *(const float4*)&g_h[i];
    v.x = fmaxf((v.x - mu)*rstd*wv + bv, 0.f);
    v.y = fmaxf((v.y - mu)*rstd*wv + bv, 0.f);
    v.z = fmaxf((v.z - mu)*rstd*wv + bv, 0.f);
    v.w = fmaxf((v.w - mu)*rstd*wv + bv, 0.f);
    *(float4*)&out[i] = v;
}

// ---------------- launch -----------------------------------------------------
extern "C" void kernel_launch(void* const* d_in, const int* in_sizes, int n_in,
                              void* d_out, int out_size)
{
    const float* x   = (const float*)d_in[0];
    const float* tw  = (const float*)d_in[1];
    const float* tb  = (const float*)d_in[2];
    const float* pw  = (const float*)d_in[3];
    const float* pb  = (const float*)d_in[4];
    const float* gw  = (const float*)d_in[5];
    const float* gb  = (const float*)d_in[6];
    const float* rw  = (const float*)d_in[7];
    const float* rb  = (const float*)d_in[8];
    const float* gnw = (const float*)d_in[9];
    const float* gnb = (const float*)d_in[10];
    const float* bnw = (const float*)d_in[11];
    const float* bnb = (const float*)d_in[12];
    float* out = (float*)d_out;

    wtrans_kernel<<<96, 256>>>(tw, pw, gw, rw);
    zero_bn<<<1, 128>>>();

    for (int layer = 0; layer < 2; layer++) {
        proj_kernel<<<dim3(SP/64, Bb), 192>>>(layer, x, tb, pb, gb);
        attn_kernel<0><<<Bb*Sd*Sd, 256>>>();
        attn_kernel<1><<<Bb*Sd*Sd, 256>>>();
        attn_kernel<2><<<Bb*Sd*Sd, 256>>>();
        combine_kernel<<<dim3(SP/64, Bb), 256>>>();
        zero_gn<<<1, 64>>>();
        cross_kernel<<<dim3(SP/128, Bb), 256>>>(rb);
        gnres_kernel<<<dim3(4, Cc, Bb), 256>>>(layer, x, gnw + layer*Cc, gnb + layer*Cc,
                                               layer == 1 ? 1 : 0);
    }
    bnapply_kernel<<<((Bb*Cc*SP/4) + 255)/256, 256>>>(bnw, bnb, out);
}

// round 6
// speedup vs baseline: 1.6232x; 1.1989x over previous
#include <cuda_runtime.h>

#define Sd 48
#define SP (Sd*Sd*Sd)      // 110592
#define Bb 2
#define Cc 128
#define NVx (Bb*SP)        // 221184

// ---------------- tf32 mma helpers -----------------------------------------
__device__ __forceinline__ float totf32(float x) {
    float r; asm("cvt.rna.tf32.f32 %0, %1;" : "=f"(r) : "f"(x)); return r;
}
__device__ __forceinline__ void mma_tf32(float* d, const unsigned* a, const unsigned* b) {
    asm volatile(
        "mma.sync.aligned.m16n8k8.row.col.f32.tf32.tf32.f32 "
        "{%0,%1,%2,%3},{%4,%5,%6,%7},{%8,%9},{%0,%1,%2,%3};"
        : "+f"(d[0]), "+f"(d[1]), "+f"(d[2]), "+f"(d[3])
        : "r"(a[0]), "r"(a[1]), "r"(a[2]), "r"(a[3]), "r"(b[0]), "r"(b[1]));
}

// ---------------- scratch --------------------------------------------------
__device__ float g_h[(size_t)Bb*Cc*SP];
__device__ float g_T[(size_t)NVx*64];
__device__ float g_P[(size_t)NVx*64];          // P; later reused as Ycomb (g-major)
__device__ float g_G[(size_t)NVx*64];
__device__ float g_Yd[(size_t)NVx*64];
__device__ float g_Yh[(size_t)NVx*64];
__device__ float g_Yw[(size_t)NVx*64];
__device__ float g_md[NVx]; __device__ float g_sd[NVx];
__device__ float g_mh[NVx]; __device__ float g_sh[NVx];
__device__ float g_mw[NVx]; __device__ float g_sw[NVx];
__device__ float g_cross[(size_t)Bb*Cc*SP];    // channel-first
__device__ float g_WT[128*192];                // k-major fused theta/phi/G weights
__device__ float g_rwT[64*128];                // k-major r_w
__device__ float g_gnsum[Bb*32]; __device__ float g_gnss[Bb*32];
__device__ float g_bnsum[Cc];    __device__ float g_bnss[Cc];

// ---------------- one-time weight transpose --------------------------------
__global__ __launch_bounds__(256) void wtrans_kernel(
    const float* __restrict__ tw, const float* __restrict__ pw,
    const float* __restrict__ gw, const float* __restrict__ rw)
{
    int idx = blockIdx.x*256 + threadIdx.x;
    if (idx < 128*192) {
        int k = idx / 192, m = idx % 192;
        float v;
        if (m < 64)       v = tw[m*128 + k];
        else if (m < 128) v = pw[(m-64)*128 + k];
        else              v = gw[(m-128)*128 + k];
        g_WT[idx] = v;
    }
    if (idx < 64*128) {
        int k = idx >> 7, m = idx & 127;
        g_rwT[idx] = rw[m*64 + k];
    }
}

// ---------------- projection (tf32 mma): [192m x 64n] tile, K=128 ----------
// 8 warps: wm=warp>>1 (m-tile 48 = 3 x m16), wn=warp&1 (n-tile 32 = 4 x n8)
__global__ __launch_bounds__(256) void proj_kernel(
    int layer, const float* __restrict__ x,
    const float* __restrict__ tb, const float* __restrict__ pb,
    const float* __restrict__ gb)
{
    const float* src = layer ? (const float*)g_h : x;
    __shared__ float As[32][200];   // [k][m], pitch%32==8 -> frag banks 8k+m
    __shared__ float Bs[32][72];    // [k][n], pitch%32==8
    const int b = blockIdx.y, n0 = blockIdx.x*64, tid = threadIdx.x;
    const int warp = tid >> 5, lane = tid & 31;
    const int grp = lane >> 2, tig = lane & 3;
    const int m_base = (warp >> 1) * 48, n_base = (warp & 1) * 32;

    float acc[3][4][4];
    #pragma unroll
    for (int mt = 0; mt < 3; mt++)
        #pragma unroll
        for (int nt = 0; nt < 4; nt++)
            #pragma unroll
            for (int q = 0; q < 4; q++) acc[mt][nt][q] = 0.f;

    for (int k0 = 0; k0 < 128; k0 += 32) {
        #pragma unroll 4
        for (int idx = tid; idx < 32*192; idx += 256) {
            int kk = idx / 192, m = idx - kk*192;
            As[kk][m] = totf32(g_WT[(k0 + kk)*192 + m]);
        }
        #pragma unroll 2
        for (int idx = tid; idx < 32*64; idx += 256) {
            int kk = idx >> 6, n = idx & 63;
            Bs[kk][n] = totf32(src[(size_t)(b*Cc + k0 + kk)*SP + n0 + n]);
        }
        __syncthreads();
        #pragma unroll
        for (int ks = 0; ks < 4; ks++) {
            unsigned bf[4][2];
            #pragma unroll
            for (int nt = 0; nt < 4; nt++) {
                bf[nt][0] = __float_as_uint(Bs[ks*8 + tig    ][n_base + nt*8 + grp]);
                bf[nt][1] = __float_as_uint(Bs[ks*8 + tig + 4][n_base + nt*8 + grp]);
            }
            #pragma unroll
            for (int mt = 0; mt < 3; mt++) {
                const int mr = m_base + mt*16 + grp;
                unsigned af[4];
                af[0] = __float_as_uint(As[ks*8 + tig    ][mr]);
                af[1] = __float_as_uint(As[ks*8 + tig    ][mr + 8]);
                af[2] = __float_as_uint(As[ks*8 + tig + 4][mr]);
                af[3] = __float_as_uint(As[ks*8 + tig + 4][mr + 8]);
                #pragma unroll
                for (int nt = 0; nt < 4; nt++) mma_tf32(acc[mt][nt], af, bf[nt]);
            }
        }
        __syncthreads();
    }

    // epilogue: bias + scatter to [vox][64] layouts of T/P/G
    #pragma unroll
    for (int mt = 0; mt < 3; mt++) {
        #pragma unroll
        for (int rr = 0; rr < 2; rr++) {
            const int r = m_base + mt*16 + rr*8 + grp;
            const float* bias; float* dst; int mm;
            if (r < 64)       { dst = g_T; mm = r;       bias = tb; }
            else if (r < 128) { dst = g_P; mm = r - 64;  bias = pb; }
            else              { dst = g_G; mm = r - 128; bias = gb; }
            const float bv = bias[mm];
            #pragma unroll
            for (int nt = 0; nt < 4; nt++) {
                const int c = n_base + nt*8 + tig*2;
                const size_t v0 = (size_t)b*SP + n0 + c;
                dst[v0*64 + mm]       = acc[mt][nt][rr*2 + 0] + bv;
                dst[(v0 + 1)*64 + mm] = acc[mt][nt][rr*2 + 1] + bv;
            }
        }
    }
}

// ---------------- per-direction pencil attention (scalar, unchanged) -------
template<int DIR>
__global__ __launch_bounds__(256) void attn_kernel() {
    __shared__ __align__(16) float Tl[48][68];
    __shared__ __align__(16) float Pl[48][68];   // P during scores, then G
    __shared__ float Sm[48][52];

    const int pid = blockIdx.x;
    const int b = pid / (Sd*Sd);
    const int rr = pid % (Sd*Sd);
    const int u = rr / Sd, v = rr % Sd;
    size_t base; int stride;
    if (DIR == 0)      { base = (size_t)b*SP + u*Sd + v;       stride = Sd*Sd; }
    else if (DIR == 1) { base = (size_t)b*SP + u*Sd*Sd + v;    stride = Sd;    }
    else               { base = (size_t)b*SP + u*Sd*Sd + v*Sd; stride = 1;     }
    const int tid = threadIdx.x;

    for (int l = tid; l < 48*64; l += 256) {
        int i = l >> 6, k = l & 63;
        size_t o = (base + (size_t)i*stride)*64 + k;
        Tl[i][k] = g_T[o]; Pl[i][k] = g_P[o];
    }
    __syncthreads();

    const int ty = tid >> 4, tx = tid & 15;
    const int ib = ty*3, jb = tx*3;

    float sc[9];
    #pragma unroll
    for (int q = 0; q < 9; q++) sc[q] = 0.f;
    #pragma unroll 4
    for (int k = 0; k < 64; k += 4) {
        float4 t0 = *(const float4*)&Tl[ib  ][k];
        float4 t1 = *(const float4*)&Tl[ib+1][k];
        float4 t2 = *(const float4*)&Tl[ib+2][k];
        float4 p0 = *(const float4*)&Pl[jb  ][k];
        float4 p1 = *(const float4*)&Pl[jb+1][k];
        float4 p2 = *(const float4*)&Pl[jb+2][k];
        sc[0] += t0.x*p0.x + t0.y*p0.y + t0.z*p0.z + t0.w*p0.w;
        sc[1] += t0.x*p1.x + t0.y*p1.y + t0.z*p1.z + t0.w*p1.w;
        sc[2] += t0.x*p2.x + t0.y*p2.y + t0.z*p2.z + t0.w*p2.w;
        sc[3] += t1.x*p0.x + t1.y*p0.y + t1.z*p0.z + t1.w*p0.w;
        sc[4] += t1.x*p1.x + t1.y*p1.y + t1.z*p1.z + t1.w*p1.w;
        sc[5] += t1.x*p2.x + t1.y*p2.y + t1.z*p2.z + t1.w*p2.w;
        sc[6] += t2.x*p0.x + t2.y*p0.y + t2.z*p0.z + t2.w*p0.w;
        sc[7] += t2.x*p1.x + t2.y*p1.y + t2.z*p1.z + t2.w*p1.w;
        sc[8] += t2.x*p2.x + t2.y*p2.y + t2.z*p2.z + t2.w*p2.w;
    }
    if (DIR != 0) {
        #pragma unroll
        for (int r = 0; r < 3; r++)
            #pragma unroll
            for (int c = 0; c < 3; c++)
                if (ib + r == jb + c) sc[r*3 + c] = -1e30f;
    }
    float rm[3], rs[3];
    #pragma unroll
    for (int r = 0; r < 3; r++)
        rm[r] = fmaxf(sc[r*3], fmaxf(sc[r*3+1], sc[r*3+2]));
    #pragma unroll
    for (int o = 8; o > 0; o >>= 1) {
        #pragma unroll
        for (int r = 0; r < 3; r++)
            rm[r] = fmaxf(rm[r], __shfl_xor_sync(0xffffffffu, rm[r], o));
    }
    #pragma unroll
    for (int r = 0; r < 3; r++) {
        float a = 0.f;
        #pragma unroll
        for (int c = 0; c < 3; c++) {
            float e = __expf(sc[r*3 + c] - rm[r]);
            Sm[ib + r][jb + c] = e;
            a += e;
        }
        rs[r] = a;
    }
    #pragma unroll
    for (int o = 8; o > 0; o >>= 1) {
        #pragma unroll
        for (int r = 0; r < 3; r++)
            rs[r] += __shfl_xor_sync(0xffffffffu, rs[r], o);
    }
    float* Mo = (DIR==0) ? g_md : ((DIR==1) ? g_mh : g_mw);
    float* So = (DIR==0) ? g_sd : ((DIR==1) ? g_sh : g_sw);
    if (tx == 0) {
        #pragma unroll
        for (int r = 0; r < 3; r++) {
            size_t vx = base + (size_t)(ib + r)*stride;
            Mo[vx] = rm[r]; So[vx] = rs[r];
        }
    }
    __syncthreads();                 // Sm written; Pl (P) reads done
    for (int l = tid; l < 48*64; l += 256) {
        int i = l >> 6, k = l & 63;
        Pl[i][k] = g_G[(base + (size_t)i*stride)*64 + k];
    }
    __syncthreads();

    const int cb = tx*4;
    float4 o0 = {0,0,0,0}, o1 = {0,0,0,0}, o2 = {0,0,0,0};
    #pragma unroll 4
    for (int j = 0; j < 48; j++) {
        float e0 = Sm[ib  ][j];
        float e1 = Sm[ib+1][j];
        float e2 = Sm[ib+2][j];
        float4 gv = *(const float4*)&Pl[j][cb];
        o0.x += e0*gv.x; o0.y += e0*gv.y; o0.z += e0*gv.z; o0.w += e0*gv.w;
        o1.x += e1*gv.x; o1.y += e1*gv.y; o1.z += e1*gv.z; o1.w += e1*gv.w;
        o2.x += e2*gv.x; o2.y += e2*gv.y; o2.z += e2*gv.z; o2.w += e2*gv.w;
    }
    float* Yout = (DIR==0) ? g_Yd : ((DIR==1) ? g_Yh : g_Yw);
    *(float4*)&Yout[(base + (size_t)(ib  )*stride)*64 + cb] = o0;
    *(float4*)&Yout[(base + (size_t)(ib+1)*stride)*64 + cb] = o1;
    *(float4*)&Yout[(base + (size_t)(ib+2)*stride)*64 + cb] = o2;
}

// ---------------- combine 3 dirs + transpose to g-major --------------------
__global__ __launch_bounds__(256) void combine_kernel() {
    __shared__ __align__(16) float S[64][68];
    const int b = blockIdx.y, n0 = blockIdx.x*64, tid = threadIdx.x;
    const int v = tid >> 2, c16 = (tid & 3)*16;
    size_t vox = (size_t)b*SP + n0 + v;
    float md = g_md[vox], sd = g_sd[vox];
    float mh = g_mh[vox], sh = g_sh[vox];
    float mw = g_mw[vox], sw = g_sw[vox];
    float m  = fmaxf(md, fmaxf(mh, mw));
    float wd = __expf(md - m), wh = __expf(mh - m), ww = __expf(mw - m);
    float inv = 1.0f / (sd*wd + sh*wh + sw*ww);
    wd *= inv; wh *= inv; ww *= inv;
    #pragma unroll
    for (int q = 0; q < 4; q++) {
        int k = c16 + q*4;
        size_t o = vox*64 + k;
        float4 a = *(const float4*)&g_Yd[o];
        float4 h = *(const float4*)&g_Yh[o];
        float4 w = *(const float4*)&g_Yw[o];
        float4 r;
        r.x = a.x*wd + h.x*wh + w.x*ww;
        r.y = a.y*wd + h.y*wh + w.y*ww;
        r.z = a.z*wd + h.z*wh + w.z*ww;
        r.w = a.w*wd + h.w*wh + w.w*ww;
        *(float4*)&S[v][k] = r;
    }
    __syncthreads();
    const int w8 = tid >> 5, lane = tid & 31;
    #pragma unroll
    for (int gr = 0; gr < 8; gr++) {
        int g = w8*8 + gr;
        float2 val;
        val.x = S[lane*2][g];
        val.y = S[lane*2 + 1][g];
        *(float2*)&g_P[((size_t)b*64 + g)*SP + n0 + lane*2] = val;
    }
}

// ---------------- zero stat accumulators ------------------------------------
__global__ void zero_gn() { int t = threadIdx.x; if (t < Bb*32) { g_gnsum[t]=0.f; g_gnss[t]=0.f; } }
__global__ void zero_bn() { int t = threadIdx.x; if (t < Cc)    { g_bnsum[t]=0.f; g_bnss[t]=0.f; } }

// ---------------- cross GEMM (tf32 mma): [128ch x 64vox], K=64 + GN sums ---
// 8 warps: wm=warp>>1 (m-tile 32 = 2 x m16), wn=warp&1 (n-tile 32 = 4 x n8)
__global__ __launch_bounds__(256) void cross_kernel(const float* __restrict__ rb)
{
    __shared__ float As[64][136];   // rw [k=g][m=ch], pitch%32==8
    __shared__ float Bs[32][72];    // Y  [k][n],      pitch%32==8
    __shared__ float gsum[32], gss[32];
    const int b = blockIdx.y, n0 = blockIdx.x*64, tid = threadIdx.x;
    const int warp = tid >> 5, lane = tid & 31;
    const int grp = lane >> 2, tig = lane & 3;
    const int m_base = (warp >> 1) * 32, n_base = (warp & 1) * 32;

    float acc[2][4][4];
    #pragma unroll
    for (int mt = 0; mt < 2; mt++)
        #pragma unroll
        for (int nt = 0; nt < 4; nt++)
            #pragma unroll
            for (int q = 0; q < 4; q++) acc[mt][nt][q] = 0.f;

    #pragma unroll 4
    for (int idx = tid; idx < 64*128; idx += 256) {
        int k = idx >> 7, m = idx & 127;
        As[k][m] = totf32(g_rwT[idx]);
    }
    if (tid < 32) { gsum[tid] = 0.f; gss[tid] = 0.f; }

    for (int g0 = 0; g0 < 64; g0 += 32) {
        #pragma unroll 2
        for (int idx = tid; idx < 32*64; idx += 256) {
            int kk = idx >> 6, n = idx & 63;
            Bs[kk][n] = totf32(g_P[((size_t)b*64 + g0 + kk)*SP + n0 + n]);
        }
        __syncthreads();
        #pragma unroll
        for (int ks = 0; ks < 4; ks++) {
            unsigned bf[4][2];
            #pragma unroll
            for (int nt = 0; nt < 4; nt++) {
                bf[nt][0] = __float_as_uint(Bs[ks*8 + tig    ][n_base + nt*8 + grp]);
                bf[nt][1] = __float_as_uint(Bs[ks*8 + tig + 4][n_base + nt*8 + grp]);
            }
            #pragma unroll
            for (int mt = 0; mt < 2; mt++) {
                const int mr = m_base + mt*16 + grp;
                unsigned af[4];
                af[0] = __float_as_uint(As[g0 + ks*8 + tig    ][mr]);
                af[1] = __float_as_uint(As[g0 + ks*8 + tig    ][mr + 8]);
                af[2] = __float_as_uint(As[g0 + ks*8 + tig + 4][mr]);
                af[3] = __float_as_uint(As[g0 + ks*8 + tig + 4][mr + 8]);
                #pragma unroll
                for (int nt = 0; nt < 4; nt++) mma_tf32(acc[mt][nt], af, bf[nt]);
            }
        }
        __syncthreads();
    }

    // epilogue: bias + store channel-first + GN partial sums
    #pragma unroll
    for (int mt = 0; mt < 2; mt++) {
        #pragma unroll
        for (int rr = 0; rr < 2; rr++) {
            const int r = m_base + mt*16 + rr*8 + grp;
            const float bv = rb[r];
            float ps = 0.f, pss = 0.f;
            #pragma unroll
            for (int nt = 0; nt < 4; nt++) {
                const int c = n_base + nt*8 + tig*2;
                float v0 = acc[mt][nt][rr*2 + 0] + bv;
                float v1 = acc[mt][nt][rr*2 + 1] + bv;
                size_t ob = ((size_t)b*Cc + r)*SP + n0 + c;
                g_cross[ob]     = v0;
                g_cross[ob + 1] = v1;
                ps += v0 + v1; pss += v0*v0 + v1*v1;
            }
            ps  += __shfl_xor_sync(0xffffffffu, ps, 1);
            ps  += __shfl_xor_sync(0xffffffffu, ps, 2);
            pss += __shfl_xor_sync(0xffffffffu, pss, 1);
            pss += __shfl_xor_sync(0xffffffffu, pss, 2);
            if (tig == 0) {
                atomicAdd(&gsum[r >> 2], ps);
                atomicAdd(&gss [r >> 2], pss);
            }
        }
    }
    __syncthreads();
    if (tid < 32) {
        atomicAdd(&g_gnsum[b*32 + tid], gsum[tid]);
        atomicAdd(&g_gnss [b*32 + tid], gss[tid]);
    }
}

// ---------------- GroupNorm + residual (streaming, channel-first) ----------
__global__ __launch_bounds__(256) void gnres_kernel(
    int layer, const float* __restrict__ x,
    const float* __restrict__ gnw, const float* __restrict__ gnb,
    int accum_bn)
{
    const float* resid = layer ? (const float*)g_h : x;  // device-side symbol resolve
    const int c = blockIdx.y, b = blockIdx.z, chunk = blockIdx.x;
    const size_t base = ((size_t)(b*Cc + c))*SP + (size_t)chunk*(SP/4);
    const int g = c >> 2;
    const float invN = 1.0f / (4.0f * SP);
    float mu  = g_gnsum[b*32 + g] * invN;
    float var = g_gnss[b*32 + g] * invN - mu*mu;
    float rstd = rsqrtf(var + 1e-5f);
    float w = gnw[c], bias = gnb[c];
    float s = 0.f, ss = 0.f;
    for (int j = 0; j < 27; j++) {
        size_t o = base + (size_t)j*1024 + threadIdx.x*4;
        float4 cv = *(const float4*)&g_cross[o];
        float4 rv = *(const float4*)&resid[o];
        float4 h;
        h.x = rv.x + (cv.x - mu)*rstd*w + bias;
        h.y = rv.y + (cv.y - mu)*rstd*w + bias;
        h.z = rv.z + (cv.z - mu)*rstd*w + bias;
        h.w = rv.w + (cv.w - mu)*rstd*w + bias;
        *(float4*)&g_h[o] = h;
        if (accum_bn) {
            s  += h.x + h.y + h.z + h.w;
            ss += h.x*h.x + h.y*h.y + h.z*h.z + h.w*h.w;
        }
    }
    if (accum_bn) {
        #pragma unroll
        for (int o = 16; o > 0; o >>= 1) {
            s  += __shfl_xor_sync(0xffffffffu, s,  o);
            ss += __shfl_xor_sync(0xffffffffu, ss, o);
        }
        __shared__ float ws[8], wss[8];
        int wid = threadIdx.x >> 5, lane = threadIdx.x & 31;
        if (lane == 0) { ws[wid] = s; wss[wid] = ss; }
        __syncthreads();
        if (threadIdx.x == 0) {
            float ts = 0.f, tss = 0.f;
            #pragma unroll
            for (int k = 0; k < 8; k++) { ts += ws[k]; tss += wss[k]; }
            atomicAdd(&g_bnsum[c], ts);
            atomicAdd(&g_bnss[c],  tss);
        }
    }
}

// ---------------- BatchNorm apply + ReLU ------------------------------------
__global__ __launch_bounds__(256) void bnapply_kernel(
    const float* __restrict__ bw, const float* __restrict__ bb, float* __restrict__ out)
{
    size_t i4 = (size_t)blockIdx.x*256 + threadIdx.x;
    if (i4 >= (size_t)Bb*Cc*SP/4) return;
    size_t i = i4 * 4;
    int c = (int)((i / SP) & 127);
    const float invN = 1.0f / ((float)Bb * SP);
    float mu  = g_bnsum[c] * invN;
    float var = g_bnss[c] * invN - mu*mu;
    float rstd = rsqrtf(var + 1e-5f);
    float wv = bw[c], bv = bb[c];
    float4 v = *(const float4*)&g_h[i];
    v.x = fmaxf((v.x - mu)*rstd*wv + bv, 0.f);
    v.y = fmaxf((v.y - mu)*rstd*wv + bv, 0.f);
    v.z = fmaxf((v.z - mu)*rstd*wv + bv, 0.f);
    v.w = fmaxf((v.w - mu)*rstd*wv + bv, 0.f);
    *(float4*)&out[i] = v;
}

// ---------------- launch -----------------------------------------------------
extern "C" void kernel_launch(void* const* d_in, const int* in_sizes, int n_in,
                              void* d_out, int out_size)
{
    const float* x   = (const float*)d_in[0];
    const float* tw  = (const float*)d_in[1];
    const float* tb  = (const float*)d_in[2];
    const float* pw  = (const float*)d_in[3];
    const float* pb  = (const float*)d_in[4];
    const float* gw  = (const float*)d_in[5];
    const float* gb  = (const float*)d_in[6];
    const float* rw  = (const float*)d_in[7];
    const float* rb  = (const float*)d_in[8];
    const float* gnw = (const float*)d_in[9];
    const float* gnb = (const float*)d_in[10];
    const float* bnw = (const float*)d_in[11];
    const float* bnb = (const float*)d_in[12];
    float* out = (float*)d_out;

    wtrans_kernel<<<96, 256>>>(tw, pw, gw, rw);
    zero_bn<<<1, 128>>>();

    for (int layer = 0; layer < 2; layer++) {
        proj_kernel<<<dim3(SP/64, Bb), 256>>>(layer, x, tb, pb, gb);
        attn_kernel<0><<<Bb*Sd*Sd, 256>>>();
        attn_kernel<1><<<Bb*Sd*Sd, 256>>>();
        attn_kernel<2><<<Bb*Sd*Sd, 256>>>();
        combine_kernel<<<dim3(SP/64, Bb), 256>>>();
        zero_gn<<<1, 64>>>();
        cross_kernel<<<dim3(SP/64, Bb), 256>>>(rb);
        gnres_kernel<<<dim3(4, Cc, Bb), 256>>>(layer, x, gnw + layer*Cc, gnb + layer*Cc,
                                               layer == 1 ? 1 : 0);
    }
    bnapply_kernel<<<((Bb*Cc*SP/4) + 255)/256, 256>>>(bnw, bnb, out);
}

// round 7
// speedup vs baseline: 2.3963x; 1.4763x over previous
#include <cuda_runtime.h>

#define Sd 48
#define SP (Sd*Sd*Sd)      // 110592
#define Bb 2
#define Cc 128
#define NVx (Bb*SP)        // 221184

// ---------------- tf32 mma helpers -----------------------------------------
__device__ __forceinline__ float totf32(float x) {
    float r; asm("cvt.rna.tf32.f32 %0, %1;" : "=f"(r) : "f"(x)); return r;
}
__device__ __forceinline__ void mma_tf32(float* d, const unsigned* a, const unsigned* b) {
    asm volatile(
        "mma.sync.aligned.m16n8k8.row.col.f32.tf32.tf32.f32 "
        "{%0,%1,%2,%3},{%4,%5,%6,%7},{%8,%9},{%0,%1,%2,%3};"
        : "+f"(d[0]), "+f"(d[1]), "+f"(d[2]), "+f"(d[3])
        : "r"(a[0]), "r"(a[1]), "r"(a[2]), "r"(a[3]), "r"(b[0]), "r"(b[1]));
}
#define BITS(x) __float_as_uint(x)

// ---------------- scratch --------------------------------------------------
__device__ float g_h[(size_t)Bb*Cc*SP];
__device__ float g_T[(size_t)NVx*64];
__device__ float g_P[(size_t)NVx*64];
__device__ float g_G[(size_t)NVx*64];
__device__ float g_Yd[(size_t)NVx*64];         // D-dir partial, vox-major
__device__ float g_Yh[(size_t)NVx*64];         // H-dir partial, vox-major
__device__ float g_Yw[(size_t)NVx*64];         // final combined Y, g-major
__device__ float g_md[NVx]; __device__ float g_sd[NVx];
__device__ float g_mh[NVx]; __device__ float g_sh[NVx];
__device__ float g_cross[(size_t)Bb*Cc*SP];    // channel-first
__device__ float g_WT[128*192];                // k-major fused theta/phi/G weights
__device__ float g_rwT[64*128];                // k-major r_w
__device__ float g_gnsum[Bb*32]; __device__ float g_gnss[Bb*32];
__device__ float g_bnsum[Cc];    __device__ float g_bnss[Cc];

// ---------------- one-time weight transpose --------------------------------
__global__ __launch_bounds__(256) void wtrans_kernel(
    const float* __restrict__ tw, const float* __restrict__ pw,
    const float* __restrict__ gw, const float* __restrict__ rw)
{
    int idx = blockIdx.x*256 + threadIdx.x;
    if (idx < 128*192) {
        int k = idx / 192, m = idx % 192;
        float v;
        if (m < 64)       v = tw[m*128 + k];
        else if (m < 128) v = pw[(m-64)*128 + k];
        else              v = gw[(m-128)*128 + k];
        g_WT[idx] = v;
    }
    if (idx < 64*128) {
        int k = idx >> 7, m = idx & 127;
        g_rwT[idx] = rw[m*64 + k];
    }
}

// ---------------- projection (tf32 mma): [192m x 64n] tile, K=128 ----------
__global__ __launch_bounds__(256) void proj_kernel(
    int layer, const float* __restrict__ x,
    const float* __restrict__ tb, const float* __restrict__ pb,
    const float* __restrict__ gb)
{
    const float* src = layer ? (const float*)g_h : x;
    __shared__ float As[32][200];   // [k][m], pitch%32==8
    __shared__ float Bs[32][72];    // [k][n], pitch%32==8
    const int b = blockIdx.y, n0 = blockIdx.x*64, tid = threadIdx.x;
    const int warp = tid >> 5, lane = tid & 31;
    const int grp = lane >> 2, tig = lane & 3;
    const int m_base = (warp >> 1) * 48, n_base = (warp & 1) * 32;

    float acc[3][4][4];
    #pragma unroll
    for (int mt = 0; mt < 3; mt++)
        #pragma unroll
        for (int nt = 0; nt < 4; nt++)
            #pragma unroll
            for (int q = 0; q < 4; q++) acc[mt][nt][q] = 0.f;

    for (int k0 = 0; k0 < 128; k0 += 32) {
        #pragma unroll 4
        for (int idx = tid; idx < 32*192; idx += 256) {
            int kk = idx / 192, m = idx - kk*192;
            As[kk][m] = totf32(g_WT[(k0 + kk)*192 + m]);
        }
        #pragma unroll 2
        for (int idx = tid; idx < 32*64; idx += 256) {
            int kk = idx >> 6, n = idx & 63;
            Bs[kk][n] = totf32(src[(size_t)(b*Cc + k0 + kk)*SP + n0 + n]);
        }
        __syncthreads();
        #pragma unroll
        for (int ks = 0; ks < 4; ks++) {
            unsigned bf[4][2];
            #pragma unroll
            for (int nt = 0; nt < 4; nt++) {
                bf[nt][0] = BITS(Bs[ks*8 + tig    ][n_base + nt*8 + grp]);
                bf[nt][1] = BITS(Bs[ks*8 + tig + 4][n_base + nt*8 + grp]);
            }
            #pragma unroll
            for (int mt = 0; mt < 3; mt++) {
                const int mr = m_base + mt*16 + grp;
                unsigned af[4];
                af[0] = BITS(As[ks*8 + tig    ][mr]);
                af[1] = BITS(As[ks*8 + tig    ][mr + 8]);
                af[2] = BITS(As[ks*8 + tig + 4][mr]);
                af[3] = BITS(As[ks*8 + tig + 4][mr + 8]);
                #pragma unroll
                for (int nt = 0; nt < 4; nt++) mma_tf32(acc[mt][nt], af, bf[nt]);
            }
        }
        __syncthreads();
    }

    #pragma unroll
    for (int mt = 0; mt < 3; mt++) {
        #pragma unroll
        for (int rr = 0; rr < 2; rr++) {
            const int r = m_base + mt*16 + rr*8 + grp;
            const float* bias; float* dst; int mm;
            if (r < 64)       { dst = g_T; mm = r;       bias = tb; }
            else if (r < 128) { dst = g_P; mm = r - 64;  bias = pb; }
            else              { dst = g_G; mm = r - 128; bias = gb; }
            const float bv = bias[mm];
            #pragma unroll
            for (int nt = 0; nt < 4; nt++) {
                const int c = n_base + nt*8 + tig*2;
                const size_t v0 = (size_t)b*SP + n0 + c;
                dst[v0*64 + mm]       = acc[mt][nt][rr*2 + 0] + bv;
                dst[(v0 + 1)*64 + mm] = acc[mt][nt][rr*2 + 1] + bv;
            }
        }
    }
}

// ---------------- pencil attention (tf32 mma) -------------------------------
// DIR 0: D-axis (unmasked). DIR 1: H-axis (diag mask). DIR 2: W-axis (diag
// mask) + fused 3-way combine, writing final Y g-major into g_Yw.
// Block: 192 threads (6 warps), one 48-long pencil per block.
template<int DIR>
__global__ __launch_bounds__(192) void attn_kernel() {
    __shared__ float Tl[48*68];     // T (tf32) -> raw scores -> exp-hi
    __shared__ float Pl[48*68];     // P (tf32) -> exp-lo
    __shared__ float Gh[48*72];     // G (tf32) -> (DIR2) combined-Y staging
    __shared__ float rmS[48], rsS[48];

    const int pid = blockIdx.x;
    const int b = pid / (Sd*Sd);
    const int rr = pid % (Sd*Sd);
    const int u = rr / Sd, v = rr % Sd;
    size_t base; int stride;
    if (DIR == 0)      { base = (size_t)b*SP + u*Sd + v;       stride = Sd*Sd; }
    else if (DIR == 1) { base = (size_t)b*SP + u*Sd*Sd + v;    stride = Sd;    }
    else               { base = (size_t)b*SP + u*Sd*Sd + v*Sd; stride = 1;     }
    const int tid = threadIdx.x;
    const int warp = tid >> 5, lane = tid & 31;
    const int grp = lane >> 2, tig = lane & 3;

    // ---- load T,P,G (convert to tf32) ----
    for (int l = tid; l < 48*16; l += 192) {
        int i = l >> 4, k4 = (l & 15) * 4;
        size_t o = (base + (size_t)i*stride)*64 + k4;
        float4 tv = *(const float4*)&g_T[o];
        float4 pv = *(const float4*)&g_P[o];
        float4 gv = *(const float4*)&g_G[o];
        tv.x = totf32(tv.x); tv.y = totf32(tv.y); tv.z = totf32(tv.z); tv.w = totf32(tv.w);
        pv.x = totf32(pv.x); pv.y = totf32(pv.y); pv.z = totf32(pv.z); pv.w = totf32(pv.w);
        gv.x = totf32(gv.x); gv.y = totf32(gv.y); gv.z = totf32(gv.z); gv.w = totf32(gv.w);
        *(float4*)&Tl[i*68 + k4] = tv;
        *(float4*)&Pl[i*68 + k4] = pv;
        *(float4*)&Gh[i*72 + k4] = gv;
    }
    __syncthreads();

    // ---- scores: S[48,48] = T @ P^T.  warp: m-tile=warp>>1, n-half=(warp&1)*24
    const int mr = (warp >> 1)*16 + grp;
    float sacc[3][4];
    #pragma unroll
    for (int nt = 0; nt < 3; nt++)
        #pragma unroll
        for (int q = 0; q < 4; q++) sacc[nt][q] = 0.f;
    #pragma unroll
    for (int ks = 0; ks < 8; ks++) {
        unsigned af[4];
        af[0] = BITS(Tl[ mr     *68 + ks*8 + tig    ]);
        af[1] = BITS(Tl[(mr + 8)*68 + ks*8 + tig    ]);
        af[2] = BITS(Tl[ mr     *68 + ks*8 + tig + 4]);
        af[3] = BITS(Tl[(mr + 8)*68 + ks*8 + tig + 4]);
        #pragma unroll
        for (int nt = 0; nt < 3; nt++) {
            const int nr = (warp & 1)*24 + nt*8 + grp;
            unsigned bf[2];
            bf[0] = BITS(Pl[nr*68 + ks*8 + tig    ]);
            bf[1] = BITS(Pl[nr*68 + ks*8 + tig + 4]);
            mma_tf32(sacc[nt], af, bf);
        }
    }
    __syncthreads();     // all T/P fragment reads complete

    // ---- write raw scores (+diag mask) into Tl ----
    #pragma unroll
    for (int nt = 0; nt < 3; nt++) {
        const int j0 = (warp & 1)*24 + nt*8 + tig*2;
        float c0 = sacc[nt][0], c1 = sacc[nt][1], c2 = sacc[nt][2], c3 = sacc[nt][3];
        if (DIR != 0) {
            if (mr     == j0    ) c0 = -1e30f;
            if (mr     == j0 + 1) c1 = -1e30f;
            if (mr + 8 == j0    ) c2 = -1e30f;
            if (mr + 8 == j0 + 1) c3 = -1e30f;
        }
        Tl[ mr     *68 + j0] = c0; Tl[ mr     *68 + j0 + 1] = c1;
        Tl[(mr + 8)*68 + j0] = c2; Tl[(mr + 8)*68 + j0 + 1] = c3;
    }
    __syncthreads();

    // ---- softmax: 4 threads per row, 12 cols each; exp split hi/lo --------
    {
        const int r = tid >> 2, q = tid & 3;
        float vals[12];
        float mx = -3.0e38f;
        #pragma unroll
        for (int j = 0; j < 12; j++) {
            vals[j] = Tl[r*68 + q*12 + j];
            mx = fmaxf(mx, vals[j]);
        }
        mx = fmaxf(mx, __shfl_xor_sync(0xffffffffu, mx, 1));
        mx = fmaxf(mx, __shfl_xor_sync(0xffffffffu, mx, 2));
        float sm = 0.f;
        #pragma unroll
        for (int j = 0; j < 12; j++) {
            float e = __expf(vals[j] - mx);
            sm += e;
            float hi = totf32(e);
            Tl[r*68 + q*12 + j] = hi;
            Pl[r*68 + q*12 + j] = totf32(e - hi);
        }
        sm += __shfl_xor_sync(0xffffffffu, sm, 1);
        sm += __shfl_xor_sync(0xffffffffu, sm, 2);
        if (DIR == 2) {
            if (q == 0) { rmS[r] = mx; rsS[r] = sm; }
        } else if (q == 0) {
            size_t vx = base + (size_t)r*stride;
            if (DIR == 0) { g_md[vx] = mx; g_sd[vx] = sm; }
            else          { g_mh[vx] = mx; g_sh[vx] = sm; }
        }
    }
    __syncthreads();

    // ---- AV: Y[48,64] = S @ G (S = hi + lo, G rounded once) ---------------
    float yacc[4][4];
    #pragma unroll
    for (int nt = 0; nt < 4; nt++)
        #pragma unroll
        for (int q = 0; q < 4; q++) yacc[nt][q] = 0.f;
    #pragma unroll
    for (int ks = 0; ks < 6; ks++) {
        unsigned ah[4], al[4];
        ah[0] = BITS(Tl[ mr     *68 + ks*8 + tig    ]);
        ah[1] = BITS(Tl[(mr + 8)*68 + ks*8 + tig    ]);
        ah[2] = BITS(Tl[ mr     *68 + ks*8 + tig + 4]);
        ah[3] = BITS(Tl[(mr + 8)*68 + ks*8 + tig + 4]);
        al[0] = BITS(Pl[ mr     *68 + ks*8 + tig    ]);
        al[1] = BITS(Pl[(mr + 8)*68 + ks*8 + tig    ]);
        al[2] = BITS(Pl[ mr     *68 + ks*8 + tig + 4]);
        al[3] = BITS(Pl[(mr + 8)*68 + ks*8 + tig + 4]);
        #pragma unroll
        for (int nt = 0; nt < 4; nt++) {
            const int nr = (warp & 1)*32 + nt*8 + grp;
            unsigned bf[2];
            bf[0] = BITS(Gh[(ks*8 + tig    )*72 + nr]);
            bf[1] = BITS(Gh[(ks*8 + tig + 4)*72 + nr]);
            mma_tf32(yacc[nt], ah, bf);
            mma_tf32(yacc[nt], al, bf);
        }
    }

    if (DIR != 2) {
        float* Yout = (DIR == 0) ? g_Yd : g_Yh;
        #pragma unroll
        for (int nt = 0; nt < 4; nt++) {
            const int c = (warp & 1)*32 + nt*8 + tig*2;
            float2 v0 = {yacc[nt][0], yacc[nt][1]};
            float2 v1 = {yacc[nt][2], yacc[nt][3]};
            *(float2*)&Yout[(base + (size_t)mr*stride)*64 + c]       = v0;
            *(float2*)&Yout[(base + (size_t)(mr + 8)*stride)*64 + c] = v1;
        }
    } else {
        __syncthreads();     // Gh fragment reads complete; reuse as Y staging
        #pragma unroll
        for (int nt = 0; nt < 4; nt++) {
            const int c = (warp & 1)*32 + nt*8 + tig*2;
            Gh[ mr     *72 + c] = yacc[nt][0]; Gh[ mr     *72 + c + 1] = yacc[nt][1];
            Gh[(mr + 8)*72 + c] = yacc[nt][2]; Gh[(mr + 8)*72 + c + 1] = yacc[nt][3];
        }
        __syncthreads();
        // fused 3-way combine; output g-major into g_Yw
        const int i = tid >> 2, q = tid & 3;
        const size_t vox = base + i;
        float md = g_md[vox], sd = g_sd[vox];
        float mh = g_mh[vox], sh = g_sh[vox];
        float mw = rmS[i],    sw = rsS[i];
        float m  = fmaxf(md, fmaxf(mh, mw));
        float wd = __expf(md - m), wh = __expf(mh - m), ww = __expf(mw - m);
        float inv = 1.0f / (sd*wd + sh*wh + sw*ww);
        wd *= inv; wh *= inv; ww *= inv;
        const size_t sp0 = base - (size_t)b*SP;
        #pragma unroll
        for (int jj = 0; jj < 4; jj++) {
            const int g = q*16 + jj*4;
            float4 a  = *(const float4*)&g_Yd[vox*64 + g];
            float4 h4 = *(const float4*)&g_Yh[vox*64 + g];
            g_Yw[((size_t)(b*64 + g    ))*SP + sp0 + i] = a.x*wd + h4.x*wh + Gh[i*72 + g    ]*ww;
            g_Yw[((size_t)(b*64 + g + 1))*SP + sp0 + i] = a.y*wd + h4.y*wh + Gh[i*72 + g + 1]*ww;
            g_Yw[((size_t)(b*64 + g + 2))*SP + sp0 + i] = a.z*wd + h4.z*wh + Gh[i*72 + g + 2]*ww;
            g_Yw[((size_t)(b*64 + g + 3))*SP + sp0 + i] = a.w*wd + h4.w*wh + Gh[i*72 + g + 3]*ww;
        }
    }
}

// ---------------- zero stat accumulators ------------------------------------
__global__ void zero_gn() { int t = threadIdx.x; if (t < Bb*32) { g_gnsum[t]=0.f; g_gnss[t]=0.f; } }
__global__ void zero_bn() { int t = threadIdx.x; if (t < Cc)    { g_bnsum[t]=0.f; g_bnss[t]=0.f; } }

// ---------------- cross GEMM (tf32 mma): [128ch x 64vox], K=64 + GN sums ---
__global__ __launch_bounds__(256) void cross_kernel(const float* __restrict__ rb)
{
    __shared__ float As[64][136];   // rw [k=g][m=ch], pitch%32==8
    __shared__ float Bs[32][72];    // Y  [k][n],      pitch%32==8
    __shared__ float gsum[32], gss[32];
    const int b = blockIdx.y, n0 = blockIdx.x*64, tid = threadIdx.x;
    const int warp = tid >> 5, lane = tid & 31;
    const int grp = lane >> 2, tig = lane & 3;
    const int m_base = (warp >> 1) * 32, n_base = (warp & 1) * 32;

    float acc[2][4][4];
    #pragma unroll
    for (int mt = 0; mt < 2; mt++)
        #pragma unroll
        for (int nt = 0; nt < 4; nt++)
            #pragma unroll
            for (int q = 0; q < 4; q++) acc[mt][nt][q] = 0.f;

    #pragma unroll 4
    for (int idx = tid; idx < 64*128; idx += 256) {
        int k = idx >> 7, m = idx & 127;
        As[k][m] = totf32(g_rwT[idx]);
    }
    if (tid < 32) { gsum[tid] = 0.f; gss[tid] = 0.f; }

    for (int g0 = 0; g0 < 64; g0 += 32) {
        #pragma unroll 2
        for (int idx = tid; idx < 32*64; idx += 256) {
            int kk = idx >> 6, n = idx & 63;
            Bs[kk][n] = totf32(g_Yw[((size_t)b*64 + g0 + kk)*SP + n0 + n]);
        }
        __syncthreads();
        #pragma unroll
        for (int ks = 0; ks < 4; ks++) {
            unsigned bf[4][2];
            #pragma unroll
            for (int nt = 0; nt < 4; nt++) {
                bf[nt][0] = BITS(Bs[ks*8 + tig    ][n_base + nt*8 + grp]);
                bf[nt][1] = BITS(Bs[ks*8 + tig + 4][n_base + nt*8 + grp]);
            }
            #pragma unroll
            for (int mt = 0; mt < 2; mt++) {
                const int mr = m_base + mt*16 + grp;
                unsigned af[4];
                af[0] = BITS(As[g0 + ks*8 + tig    ][mr]);
                af[1] = BITS(As[g0 + ks*8 + tig    ][mr + 8]);
                af[2] = BITS(As[g0 + ks*8 + tig + 4][mr]);
                af[3] = BITS(As[g0 + ks*8 + tig + 4][mr + 8]);
                #pragma unroll
                for (int nt = 0; nt < 4; nt++) mma_tf32(acc[mt][nt], af, bf[nt]);
            }
        }
        __syncthreads();
    }

    #pragma unroll
    for (int mt = 0; mt < 2; mt++) {
        #pragma unroll
        for (int rr = 0; rr < 2; rr++) {
            const int r = m_base + mt*16 + rr*8 + grp;
            const float bv = rb[r];
            float ps = 0.f, pss = 0.f;
            #pragma unroll
            for (int nt = 0; nt < 4; nt++) {
                const int c = n_base + nt*8 + tig*2;
                float v0 = acc[mt][nt][rr*2 + 0] + bv;
                float v1 = acc[mt][nt][rr*2 + 1] + bv;
                size_t ob = ((size_t)b*Cc + r)*SP + n0 + c;
                g_cross[ob]     = v0;
                g_cross[ob + 1] = v1;
                ps += v0 + v1; pss += v0*v0 + v1*v1;
            }
            ps  += __shfl_xor_sync(0xffffffffu, ps, 1);
            ps  += __shfl_xor_sync(0xffffffffu, ps, 2);
            pss += __shfl_xor_sync(0xffffffffu, pss, 1);
            pss += __shfl_xor_sync(0xffffffffu, pss, 2);
            if (tig == 0) {
                atomicAdd(&gsum[r >> 2], ps);
                atomicAdd(&gss [r >> 2], pss);
            }
        }
    }
    __syncthreads();
    if (tid < 32) {
        atomicAdd(&g_gnsum[b*32 + tid], gsum[tid]);
        atomicAdd(&g_gnss [b*32 + tid], gss[tid]);
    }
}

// ---------------- GroupNorm + residual (streaming, channel-first) ----------
__global__ __launch_bounds__(256) void gnres_kernel(
    int layer, const float* __restrict__ x,
    const float* __restrict__ gnw, const float* __restrict__ gnb,
    int accum_bn)
{
    const float* resid = layer ? (const float*)g_h : x;
    const int c = blockIdx.y, b = blockIdx.z, chunk = blockIdx.x;
    const size_t base = ((size_t)(b*Cc + c))*SP + (size_t)chunk*(SP/4);
    const int g = c >> 2;
    const float invN = 1.0f / (4.0f * SP);
    float mu  = g_gnsum[b*32 + g] * invN;
    float var = g_gnss[b*32 + g] * invN - mu*mu;
    float rstd = rsqrtf(var + 1e-5f);
    float w = gnw[c], bias = gnb[c];
    float s = 0.f, ss = 0.f;
    for (int j = 0; j < 27; j++) {
        size_t o = base + (size_t)j*1024 + threadIdx.x*4;
        float4 cv = *(const float4*)&g_cross[o];
        float4 rv = *(const float4*)&resid[o];
        float4 h;
        h.x = rv.x + (cv.x - mu)*rstd*w + bias;
        h.y = rv.y + (cv.y - mu)*rstd*w + bias;
        h.z = rv.z + (cv.z - mu)*rstd*w + bias;
        h.w = rv.w + (cv.w - mu)*rstd*w + bias;
        *(float4*)&g_h[o] = h;
        if (accum_bn) {
            s  += h.x + h.y + h.z + h.w;
            ss += h.x*h.x + h.y*h.y + h.z*h.z + h.w*h.w;
        }
    }
    if (accum_bn) {
        #pragma unroll
        for (int o = 16; o > 0; o >>= 1) {
            s  += __shfl_xor_sync(0xffffffffu, s,  o);
            ss += __shfl_xor_sync(0xffffffffu, ss, o);
        }
        __shared__ float ws[8], wss[8];
        int wid = threadIdx.x >> 5, lane = threadIdx.x & 31;
        if (lane == 0) { ws[wid] = s; wss[wid] = ss; }
        __syncthreads();
        if (threadIdx.x == 0) {
            float ts = 0.f, tss = 0.f;
            #pragma unroll
            for (int k = 0; k < 8; k++) { ts += ws[k]; tss += wss[k]; }
            atomicAdd(&g_bnsum[c], ts);
            atomicAdd(&g_bnss[c],  tss);
        }
    }
}

// ---------------- BatchNorm apply + ReLU ------------------------------------
__global__ __launch_bounds__(256) void bnapply_kernel(
    const float* __restrict__ bw, const float* __restrict__ bb, float* __restrict__ out)
{
    size_t i4 = (size_t)blockIdx.x*256 + threadIdx.x;
    if (i4 >= (size_t)Bb*Cc*SP/4) return;
    size_t i = i4 * 4;
    int c = (int)((i / SP) & 127);
    const float invN = 1.0f / ((float)Bb * SP);
    float mu  = g_bnsum[c] * invN;
    float var = g_bnss[c] * invN - mu*mu;
    float rstd = rsqrtf(var + 1e-5f);
    float wv = bw[c], bv = bb[c];
    float4 v = *(const float4*)&g_h[i];
    v.x = fmaxf((v.x - mu)*rstd*wv + bv, 0.f);
    v.y = fmaxf((v.y - mu)*rstd*wv + bv, 0.f);
    v.z = fmaxf((v.z - mu)*rstd*wv + bv, 0.f);
    v.w = fmaxf((v.w - mu)*rstd*wv + bv, 0.f);
    *(float4*)&out[i] = v;
}

// ---------------- launch -----------------------------------------------------
extern "C" void kernel_launch(void* const* d_in, const int* in_sizes, int n_in,
                              void* d_out, int out_size)
{
    const float* x   = (const float*)d_in[0];
    const float* tw  = (const float*)d_in[1];
    const float* tb  = (const float*)d_in[2];
    const float* pw  = (const float*)d_in[3];
    const float* pb  = (const float*)d_in[4];
    const float* gw  = (const float*)d_in[5];
    const float* gb  = (const float*)d_in[6];
    const float* rw  = (const float*)d_in[7];
    const float* rb  = (const float*)d_in[8];
    const float* gnw = (const float*)d_in[9];
    const float* gnb = (const float*)d_in[10];
    const float* bnw = (const float*)d_in[11];
    const float* bnb = (const float*)d_in[12];
    float* out = (float*)d_out;

    wtrans_kernel<<<96, 256>>>(tw, pw, gw, rw);
    zero_bn<<<1, 128>>>();

    for (int layer = 0; layer < 2; layer++) {
        proj_kernel<<<dim3(SP/64, Bb), 256>>>(layer, x, tb, pb, gb);
        attn_kernel<0><<<Bb*Sd*Sd, 192>>>();
        attn_kernel<1><<<Bb*Sd*Sd, 192>>>();
        attn_kernel<2><<<Bb*Sd*Sd, 192>>>();
        zero_gn<<<1, 64>>>();
        cross_kernel<<<dim3(SP/64, Bb), 256>>>(rb);
        gnres_kernel<<<dim3(4, Cc, Bb), 256>>>(layer, x, gnw + layer*Cc, gnb + layer*Cc,
                                               layer == 1 ? 1 : 0);
    }
    bnapply_kernel<<<((Bb*Cc*SP/4) + 255)/256, 256>>>(bnw, bnb, out);
}

// round 8
// speedup vs baseline: 2.6233x; 1.0947x over previous
#include <cuda_runtime.h>
#include <cuda_fp16.h>

#define Sd 48
#define SP (Sd*Sd*Sd)      // 110592
#define Bb 2
#define Cc 128
#define NVx (Bb*SP)        // 221184

// ---------------- tf32 mma helpers -----------------------------------------
__device__ __forceinline__ float totf32(float x) {
    float r; asm("cvt.rna.tf32.f32 %0, %1;" : "=f"(r) : "f"(x)); return r;
}
__device__ __forceinline__ void mma_tf32(float* d, const unsigned* a, const unsigned* b) {
    asm volatile(
        "mma.sync.aligned.m16n8k8.row.col.f32.tf32.tf32.f32 "
        "{%0,%1,%2,%3},{%4,%5,%6,%7},{%8,%9},{%0,%1,%2,%3};"
        : "+f"(d[0]), "+f"(d[1]), "+f"(d[2]), "+f"(d[3])
        : "r"(a[0]), "r"(a[1]), "r"(a[2]), "r"(a[3]), "r"(b[0]), "r"(b[1]));
}
#define BITS(x) __float_as_uint(x)
__device__ __forceinline__ float2 h2f2(unsigned u) {
    __half2 h = *reinterpret_cast<__half2*>(&u);
    return __half22float2(h);
}

// ---------------- scratch --------------------------------------------------
__device__ float  g_h[(size_t)Bb*Cc*SP];
__device__ __half g_T[(size_t)NVx*64];         // fp16: same mantissa as tf32
__device__ __half g_P[(size_t)NVx*64];
__device__ __half g_G[(size_t)NVx*64];
__device__ __half g_Yd[(size_t)NVx*64];        // D-dir partial, vox-major
__device__ __half g_Yh[(size_t)NVx*64];        // H-dir partial, vox-major
__device__ __half g_Yw[(size_t)NVx*64];        // final combined Y, g-major
__device__ float g_md[NVx]; __device__ float g_sd[NVx];
__device__ float g_mh[NVx]; __device__ float g_sh[NVx];
__device__ float g_cross[(size_t)Bb*Cc*SP];    // channel-first
__device__ float g_WT[128*192];                // k-major fused theta/phi/G weights
__device__ float g_rwT[64*128];                // k-major r_w
__device__ float g_gnsum[Bb*32]; __device__ float g_gnss[Bb*32];
__device__ float g_bnsum[Cc];    __device__ float g_bnss[Cc];

// ---------------- one-time weight transpose --------------------------------
__global__ __launch_bounds__(256) void wtrans_kernel(
    const float* __restrict__ tw, const float* __restrict__ pw,
    const float* __restrict__ gw, const float* __restrict__ rw)
{
    int idx = blockIdx.x*256 + threadIdx.x;
    if (idx < 128*192) {
        int k = idx / 192, m = idx % 192;
        float v;
        if (m < 64)       v = tw[m*128 + k];
        else if (m < 128) v = pw[(m-64)*128 + k];
        else              v = gw[(m-128)*128 + k];
        g_WT[idx] = v;
    }
    if (idx < 64*128) {
        int k = idx >> 7, m = idx & 127;
        g_rwT[idx] = rw[m*64 + k];
    }
}

// ---------------- projection (tf32 mma): [192m x 64n] tile, K=128 ----------
__global__ __launch_bounds__(256) void proj_kernel(
    int layer, const float* __restrict__ x,
    const float* __restrict__ tb, const float* __restrict__ pb,
    const float* __restrict__ gb)
{
    const float* src = layer ? (const float*)g_h : x;
    __shared__ float As[32][200];   // [k][m], pitch%32==8
    __shared__ float Bs[32][72];    // [k][n], pitch%32==8
    const int b = blockIdx.y, n0 = blockIdx.x*64, tid = threadIdx.x;
    const int warp = tid >> 5, lane = tid & 31;
    const int grp = lane >> 2, tig = lane & 3;
    const int m_base = (warp >> 1) * 48, n_base = (warp & 1) * 32;

    float acc[3][4][4];
    #pragma unroll
    for (int mt = 0; mt < 3; mt++)
        #pragma unroll
        for (int nt = 0; nt < 4; nt++)
            #pragma unroll
            for (int q = 0; q < 4; q++) acc[mt][nt][q] = 0.f;

    for (int k0 = 0; k0 < 128; k0 += 32) {
        #pragma unroll 4
        for (int idx = tid; idx < 32*192; idx += 256) {
            int kk = idx / 192, m = idx - kk*192;
            As[kk][m] = totf32(g_WT[(k0 + kk)*192 + m]);
        }
        #pragma unroll 2
        for (int idx = tid; idx < 32*64; idx += 256) {
            int kk = idx >> 6, n = idx & 63;
            Bs[kk][n] = totf32(src[(size_t)(b*Cc + k0 + kk)*SP + n0 + n]);
        }
        __syncthreads();
        #pragma unroll
        for (int ks = 0; ks < 4; ks++) {
            unsigned bf[4][2];
            #pragma unroll
            for (int nt = 0; nt < 4; nt++) {
                bf[nt][0] = BITS(Bs[ks*8 + tig    ][n_base + nt*8 + grp]);
                bf[nt][1] = BITS(Bs[ks*8 + tig + 4][n_base + nt*8 + grp]);
            }
            #pragma unroll
            for (int mt = 0; mt < 3; mt++) {
                const int mr = m_base + mt*16 + grp;
                unsigned af[4];
                af[0] = BITS(As[ks*8 + tig    ][mr]);
                af[1] = BITS(As[ks*8 + tig    ][mr + 8]);
                af[2] = BITS(As[ks*8 + tig + 4][mr]);
                af[3] = BITS(As[ks*8 + tig + 4][mr + 8]);
                #pragma unroll
                for (int nt = 0; nt < 4; nt++) mma_tf32(acc[mt][nt], af, bf[nt]);
            }
        }
        __syncthreads();
    }

    #pragma unroll
    for (int mt = 0; mt < 3; mt++) {
        #pragma unroll
        for (int rr = 0; rr < 2; rr++) {
            const int r = m_base + mt*16 + rr*8 + grp;
            const float* bias; __half* dst; int mm;
            if (r < 64)       { dst = g_T; mm = r;       bias = tb; }
            else if (r < 128) { dst = g_P; mm = r - 64;  bias = pb; }
            else              { dst = g_G; mm = r - 128; bias = gb; }
            const float bv = bias[mm];
            #pragma unroll
            for (int nt = 0; nt < 4; nt++) {
                const int c = n_base + nt*8 + tig*2;
                const size_t v0 = (size_t)b*SP + n0 + c;
                dst[v0*64 + mm]       = __float2half(acc[mt][nt][rr*2 + 0] + bv);
                dst[(v0 + 1)*64 + mm] = __float2half(acc[mt][nt][rr*2 + 1] + bv);
            }
        }
    }
}

// ---------------- pencil attention (tf32 mma, fp16 gmem) --------------------
// DIR 0: D-axis (unmasked). DIR 1: H-axis (diag mask). DIR 2: W-axis (diag
// mask) + fused 3-way combine, writing final Y g-major (fp16) into g_Yw.
template<int DIR>
__global__ __launch_bounds__(192) void attn_kernel() {
    __shared__ float Tl[48*68];     // T -> raw scores -> exp-hi
    __shared__ float Pl[48*68];     // P -> exp-lo
    __shared__ float Gh[48*72];     // G -> (DIR2) combined-Y staging
    __shared__ float rmS[48], rsS[48];

    const int pid = blockIdx.x;
    const int b = pid / (Sd*Sd);
    const int rr = pid % (Sd*Sd);
    const int u = rr / Sd, v = rr % Sd;
    size_t base; int stride;
    if (DIR == 0)      { base = (size_t)b*SP + u*Sd + v;       stride = Sd*Sd; }
    else if (DIR == 1) { base = (size_t)b*SP + u*Sd*Sd + v;    stride = Sd;    }
    else               { base = (size_t)b*SP + u*Sd*Sd + v*Sd; stride = 1;     }
    const int tid = threadIdx.x;
    const int warp = tid >> 5, lane = tid & 31;
    const int grp = lane >> 2, tig = lane & 3;

    // ---- load T,P,G (fp16 -> fp32; values already tf32-exact) ----
    for (int l = tid; l < 48*8; l += 192) {
        int i = l >> 3, k8 = (l & 7) * 8;
        size_t o = (base + (size_t)i*stride)*64 + k8;
        uint4 tv = *(const uint4*)&g_T[o];
        uint4 pv = *(const uint4*)&g_P[o];
        uint4 gv = *(const uint4*)&g_G[o];
        *(float2*)&Tl[i*68 + k8    ] = h2f2(tv.x);
        *(float2*)&Tl[i*68 + k8 + 2] = h2f2(tv.y);
        *(float2*)&Tl[i*68 + k8 + 4] = h2f2(tv.z);
        *(float2*)&Tl[i*68 + k8 + 6] = h2f2(tv.w);
        *(float2*)&Pl[i*68 + k8    ] = h2f2(pv.x);
        *(float2*)&Pl[i*68 + k8 + 2] = h2f2(pv.y);
        *(float2*)&Pl[i*68 + k8 + 4] = h2f2(pv.z);
        *(float2*)&Pl[i*68 + k8 + 6] = h2f2(pv.w);
        *(float2*)&Gh[i*72 + k8    ] = h2f2(gv.x);
        *(float2*)&Gh[i*72 + k8 + 2] = h2f2(gv.y);
        *(float2*)&Gh[i*72 + k8 + 4] = h2f2(gv.z);
        *(float2*)&Gh[i*72 + k8 + 6] = h2f2(gv.w);
    }
    __syncthreads();

    // ---- scores: S[48,48] = T @ P^T ----
    const int mr = (warp >> 1)*16 + grp;
    float sacc[3][4];
    #pragma unroll
    for (int nt = 0; nt < 3; nt++)
        #pragma unroll
        for (int q = 0; q < 4; q++) sacc[nt][q] = 0.f;
    #pragma unroll
    for (int ks = 0; ks < 8; ks++) {
        unsigned af[4];
        af[0] = BITS(Tl[ mr     *68 + ks*8 + tig    ]);
        af[1] = BITS(Tl[(mr + 8)*68 + ks*8 + tig    ]);
        af[2] = BITS(Tl[ mr     *68 + ks*8 + tig + 4]);
        af[3] = BITS(Tl[(mr + 8)*68 + ks*8 + tig + 4]);
        #pragma unroll
        for (int nt = 0; nt < 3; nt++) {
            const int nr = (warp & 1)*24 + nt*8 + grp;
            unsigned bf[2];
            bf[0] = BITS(Pl[nr*68 + ks*8 + tig    ]);
            bf[1] = BITS(Pl[nr*68 + ks*8 + tig + 4]);
            mma_tf32(sacc[nt], af, bf);
        }
    }
    __syncthreads();

    // ---- write raw scores (+diag mask) into Tl ----
    #pragma unroll
    for (int nt = 0; nt < 3; nt++) {
        const int j0 = (warp & 1)*24 + nt*8 + tig*2;
        float c0 = sacc[nt][0], c1 = sacc[nt][1], c2 = sacc[nt][2], c3 = sacc[nt][3];
        if (DIR != 0) {
            if (mr     == j0    ) c0 = -1e30f;
            if (mr     == j0 + 1) c1 = -1e30f;
            if (mr + 8 == j0    ) c2 = -1e30f;
            if (mr + 8 == j0 + 1) c3 = -1e30f;
        }
        Tl[ mr     *68 + j0] = c0; Tl[ mr     *68 + j0 + 1] = c1;
        Tl[(mr + 8)*68 + j0] = c2; Tl[(mr + 8)*68 + j0 + 1] = c3;
    }
    __syncthreads();

    // ---- softmax: 4 threads per row, 12 cols each; exp split hi/lo --------
    {
        const int r = tid >> 2, q = tid & 3;
        float vals[12];
        float mx = -3.0e38f;
        #pragma unroll
        for (int j = 0; j < 12; j++) {
            vals[j] = Tl[r*68 + q*12 + j];
            mx = fmaxf(mx, vals[j]);
        }
        mx = fmaxf(mx, __shfl_xor_sync(0xffffffffu, mx, 1));
        mx = fmaxf(mx, __shfl_xor_sync(0xffffffffu, mx, 2));
        float sm = 0.f;
        #pragma unroll
        for (int j = 0; j < 12; j++) {
            float e = __expf(vals[j] - mx);
            sm += e;
            float hi = totf32(e);
            Tl[r*68 + q*12 + j] = hi;
            Pl[r*68 + q*12 + j] = totf32(e - hi);
        }
        sm += __shfl_xor_sync(0xffffffffu, sm, 1);
        sm += __shfl_xor_sync(0xffffffffu, sm, 2);
        if (DIR == 2) {
            if (q == 0) { rmS[r] = mx; rsS[r] = sm; }
        } else if (q == 0) {
            size_t vx = base + (size_t)r*stride;
            if (DIR == 0) { g_md[vx] = mx; g_sd[vx] = sm; }
            else          { g_mh[vx] = mx; g_sh[vx] = sm; }
        }
    }
    __syncthreads();

    // ---- AV: Y[48,64] = S @ G (S = hi + lo) --------------------------------
    float yacc[4][4];
    #pragma unroll
    for (int nt = 0; nt < 4; nt++)
        #pragma unroll
        for (int q = 0; q < 4; q++) yacc[nt][q] = 0.f;
    #pragma unroll
    for (int ks = 0; ks < 6; ks++) {
        unsigned ah[4], al[4];
        ah[0] = BITS(Tl[ mr     *68 + ks*8 + tig    ]);
        ah[1] = BITS(Tl[(mr + 8)*68 + ks*8 + tig    ]);
        ah[2] = BITS(Tl[ mr     *68 + ks*8 + tig + 4]);
        ah[3] = BITS(Tl[(mr + 8)*68 + ks*8 + tig + 4]);
        al[0] = BITS(Pl[ mr     *68 + ks*8 + tig    ]);
        al[1] = BITS(Pl[(mr + 8)*68 + ks*8 + tig    ]);
        al[2] = BITS(Pl[ mr     *68 + ks*8 + tig + 4]);
        al[3] = BITS(Pl[(mr + 8)*68 + ks*8 + tig + 4]);
        #pragma unroll
        for (int nt = 0; nt < 4; nt++) {
            const int nr = (warp & 1)*32 + nt*8 + grp;
            unsigned bf[2];
            bf[0] = BITS(Gh[(ks*8 + tig    )*72 + nr]);
            bf[1] = BITS(Gh[(ks*8 + tig + 4)*72 + nr]);
            mma_tf32(yacc[nt], ah, bf);
            mma_tf32(yacc[nt], al, bf);
        }
    }

    if (DIR != 2) {
        __half* Yout = (DIR == 0) ? g_Yd : g_Yh;
        #pragma unroll
        for (int nt = 0; nt < 4; nt++) {
            const int c = (warp & 1)*32 + nt*8 + tig*2;
            *(__half2*)&Yout[(base + (size_t)mr*stride)*64 + c] =
                __floats2half2_rn(yacc[nt][0], yacc[nt][1]);
            *(__half2*)&Yout[(base + (size_t)(mr + 8)*stride)*64 + c] =
                __floats2half2_rn(yacc[nt][2], yacc[nt][3]);
        }
    } else {
        __syncthreads();     // Gh fragment reads complete; reuse as Y staging
        #pragma unroll
        for (int nt = 0; nt < 4; nt++) {
            const int c = (warp & 1)*32 + nt*8 + tig*2;
            Gh[ mr     *72 + c] = yacc[nt][0]; Gh[ mr     *72 + c + 1] = yacc[nt][1];
            Gh[(mr + 8)*72 + c] = yacc[nt][2]; Gh[(mr + 8)*72 + c + 1] = yacc[nt][3];
        }
        __syncthreads();
        // fused 3-way combine; output g-major (fp16) into g_Yw
        const int i = tid >> 2, q = tid & 3;
        const size_t vox = base + i;
        float md = g_md[vox], sd = g_sd[vox];
        float mh = g_mh[vox], sh = g_sh[vox];
        float mw = rmS[i],    sw = rsS[i];
        float m  = fmaxf(md, fmaxf(mh, mw));
        float wd = __expf(md - m), wh = __expf(mh - m), ww = __expf(mw - m);
        float inv = 1.0f / (sd*wd + sh*wh + sw*ww);
        wd *= inv; wh *= inv; ww *= inv;
        const size_t sp0 = base - (size_t)b*SP;
        #pragma unroll
        for (int jj = 0; jj < 4; jj++) {
            const int g = q*16 + jj*4;
            uint2 au = *(const uint2*)&g_Yd[vox*64 + g];
            uint2 hu = *(const uint2*)&g_Yh[vox*64 + g];
            float2 a0 = h2f2(au.x), a1 = h2f2(au.y);
            float2 h0 = h2f2(hu.x), h1 = h2f2(hu.y);
            g_Yw[((size_t)(b*64 + g    ))*SP + sp0 + i] =
                __float2half(a0.x*wd + h0.x*wh + Gh[i*72 + g    ]*ww);
            g_Yw[((size_t)(b*64 + g + 1))*SP + sp0 + i] =
                __float2half(a0.y*wd + h0.y*wh + Gh[i*72 + g + 1]*ww);
            g_Yw[((size_t)(b*64 + g + 2))*SP + sp0 + i] =
                __float2half(a1.x*wd + h1.x*wh + Gh[i*72 + g + 2]*ww);
            g_Yw[((size_t)(b*64 + g + 3))*SP + sp0 + i] =
                __float2half(a1.y*wd + h1.y*wh + Gh[i*72 + g + 3]*ww);
        }
    }
}

// ---------------- zero stat accumulators ------------------------------------
__global__ void zero_gn() { int t = threadIdx.x; if (t < Bb*32) { g_gnsum[t]=0.f; g_gnss[t]=0.f; } }
__global__ void zero_bn() { int t = threadIdx.x; if (t < Cc)    { g_bnsum[t]=0.f; g_bnss[t]=0.f; } }

// ---------------- cross GEMM (tf32 mma): [128ch x 64vox], K=64 + GN sums ---
__global__ __launch_bounds__(256) void cross_kernel(const float* __restrict__ rb)
{
    __shared__ float As[64][136];   // rw [k=g][m=ch], pitch%32==8
    __shared__ float Bs[32][72];    // Y  [k][n],      pitch%32==8
    __shared__ float gsum[32], gss[32];
    const int b = blockIdx.y, n0 = blockIdx.x*64, tid = threadIdx.x;
    const int warp = tid >> 5, lane = tid & 31;
    const int grp = lane >> 2, tig = lane & 3;
    const int m_base = (warp >> 1) * 32, n_base = (warp & 1) * 32;

    float acc[2][4][4];
    #pragma unroll
    for (int mt = 0; mt < 2; mt++)
        #pragma unroll
        for (int nt = 0; nt < 4; nt++)
            #pragma unroll
            for (int q = 0; q < 4; q++) acc[mt][nt][q] = 0.f;

    #pragma unroll 4
    for (int idx = tid; idx < 64*128; idx += 256) {
        int k = idx >> 7, m = idx & 127;
        As[k][m] = totf32(g_rwT[idx]);
    }
    if (tid < 32) { gsum[tid] = 0.f; gss[tid] = 0.f; }

    for (int g0 = 0; g0 < 64; g0 += 32) {
        // fp16 loads: 8 halves per thread (exact in fp32/tf32)
        {
            int idx = tid;  // 256 threads, 256 chunks of 8
            int kk = idx >> 3, n8 = (idx & 7) * 8;
            uint4 yv = *(const uint4*)&g_Yw[((size_t)b*64 + g0 + kk)*SP + n0 + n8];
            *(float2*)&Bs[kk][n8    ] = h2f2(yv.x);
            *(float2*)&Bs[kk][n8 + 2] = h2f2(yv.y);
            *(float2*)&Bs[kk][n8 + 4] = h2f2(yv.z);
            *(float2*)&Bs[kk][n8 + 6] = h2f2(yv.w);
        }
        __syncthreads();
        #pragma unroll
        for (int ks = 0; ks < 4; ks++) {
            unsigned bf[4][2];
            #pragma unroll
            for (int nt = 0; nt < 4; nt++) {
                bf[nt][0] = BITS(Bs[ks*8 + tig    ][n_base + nt*8 + grp]);
                bf[nt][1] = BITS(Bs[ks*8 + tig + 4][n_base + nt*8 + grp]);
            }
            #pragma unroll
            for (int mt = 0; mt < 2; mt++) {
                const int mr = m_base + mt*16 + grp;
                unsigned af[4];
                af[0] = BITS(As[g0 + ks*8 + tig    ][mr]);
                af[1] = BITS(As[g0 + ks*8 + tig    ][mr + 8]);
                af[2] = BITS(As[g0 + ks*8 + tig + 4][mr]);
                af[3] = BITS(As[g0 + ks*8 + tig + 4][mr + 8]);
                #pragma unroll
                for (int nt = 0; nt < 4; nt++) mma_tf32(acc[mt][nt], af, bf[nt]);
            }
        }
        __syncthreads();
    }

    #pragma unroll
    for (int mt = 0; mt < 2; mt++) {
        #pragma unroll
        for (int rr = 0; rr < 2; rr++) {
            const int r = m_base + mt*16 + rr*8 + grp;
            const float bv = rb[r];
            float ps = 0.f, pss = 0.f;
            #pragma unroll
            for (int nt = 0; nt < 4; nt++) {
                const int c = n_base + nt*8 + tig*2;
                float v0 = acc[mt][nt][rr*2 + 0] + bv;
                float v1 = acc[mt][nt][rr*2 + 1] + bv;
                size_t ob = ((size_t)b*Cc + r)*SP + n0 + c;
                g_cross[ob]     = v0;
                g_cross[ob + 1] = v1;
                ps += v0 + v1; pss += v0*v0 + v1*v1;
            }
            ps  += __shfl_xor_sync(0xffffffffu, ps, 1);
            ps  += __shfl_xor_sync(0xffffffffu, ps, 2);
            pss += __shfl_xor_sync(0xffffffffu, pss, 1);
            pss += __shfl_xor_sync(0xffffffffu, pss, 2);
            if (tig == 0) {
                atomicAdd(&gsum[r >> 2], ps);
                atomicAdd(&gss [r >> 2], pss);
            }
        }
    }
    __syncthreads();
    if (tid < 32) {
        atomicAdd(&g_gnsum[b*32 + tid], gsum[tid]);
        atomicAdd(&g_gnss [b*32 + tid], gss[tid]);
    }
}

// ---------------- GroupNorm + residual (streaming, channel-first) ----------
__global__ __launch_bounds__(256) void gnres_kernel(
    int layer, const float* __restrict__ x,
    const float* __restrict__ gnw, const float* __restrict__ gnb,
    int accum_bn)
{
    const float* resid = layer ? (const float*)g_h : x;
    const int c = blockIdx.y, b = blockIdx.z, chunk = blockIdx.x;
    const size_t base = ((size_t)(b*Cc + c))*SP + (size_t)chunk*(SP/4);
    const int g = c >> 2;
    const float invN = 1.0f / (4.0f * SP);
    float mu  = g_gnsum[b*32 + g] * invN;
    float var = g_gnss[b*32 + g] * invN - mu*mu;
    float rstd = rsqrtf(var + 1e-5f);
    float w = gnw[c], bias = gnb[c];
    float s = 0.f, ss = 0.f;
    for (int j = 0; j < 27; j++) {
        size_t o = base + (size_t)j*1024 + threadIdx.x*4;
        float4 cv = *(const float4*)&g_cross[o];
        float4 rv = *(const float4*)&resid[o];
        float4 h;
        h.x = rv.x + (cv.x - mu)*rstd*w + bias;
        h.y = rv.y + (cv.y - mu)*rstd*w + bias;
        h.z = rv.z + (cv.z - mu)*rstd*w + bias;
        h.w = rv.w + (cv.w - mu)*rstd*w + bias;
        *(float4*)&g_h[o] = h;
        if (accum_bn) {
            s  += h.x + h.y + h.z + h.w;
            ss += h.x*h.x + h.y*h.y + h.z*h.z + h.w*h.w;
        }
    }
    if (accum_bn) {
        #pragma unroll
        for (int o = 16; o > 0; o >>= 1) {
            s  += __shfl_xor_sync(0xffffffffu, s,  o);
            ss += __shfl_xor_sync(0xffffffffu, ss, o);
        }
        __shared__ float ws[8], wss[8];
        int wid = threadIdx.x >> 5, lane = threadIdx.x & 31;
        if (lane == 0) { ws[wid] = s; wss[wid] = ss; }
        __syncthreads();
        if (threadIdx.x == 0) {
            float ts = 0.f, tss = 0.f;
            #pragma unroll
            for (int k = 0; k < 8; k++) { ts += ws[k]; tss += wss[k]; }
            atomicAdd(&g_bnsum[c], ts);
            atomicAdd(&g_bnss[c],  tss);
        }
    }
}

// ---------------- BatchNorm apply + ReLU ------------------------------------
__global__ __launch_bounds__(256) void bnapply_kernel(
    const float* __restrict__ bw, const float* __restrict__ bb, float* __restrict__ out)
{
    size_t i4 = (size_t)blockIdx.x*256 + threadIdx.x;
    if (i4 >= (size_t)Bb*Cc*SP/4) return;
    size_t i = i4 * 4;
    int c = (int)((i / SP) & 127);
    const float invN = 1.0f / ((float)Bb * SP);
    float mu  = g_bnsum[c] * invN;
    float var = g_bnss[c] * invN - mu*mu;
    float rstd = rsqrtf(var + 1e-5f);
    float wv = bw[c], bv = bb[c];
    float4 v = *(const float4*)&g_h[i];
    v.x = fmaxf((v.x - mu)*rstd*wv + bv, 0.f);
    v.y = fmaxf((v.y - mu)*rstd*wv + bv, 0.f);
    v.z = fmaxf((v.z - mu)*rstd*wv + bv, 0.f);
    v.w = fmaxf((v.w - mu)*rstd*wv + bv, 0.f);
    *(float4*)&out[i] = v;
}

// ---------------- launch -----------------------------------------------------
extern "C" void kernel_launch(void* const* d_in, const int* in_sizes, int n_in,
                              void* d_out, int out_size)
{
    const float* x   = (const float*)d_in[0];
    const float* tw  = (const float*)d_in[1];
    const float* tb  = (const float*)d_in[2];
    const float* pw  = (const float*)d_in[3];
    const float* pb  = (const float*)d_in[4];
    const float* gw  = (const float*)d_in[5];
    const float* gb  = (const float*)d_in[6];
    const float* rw  = (const float*)d_in[7];
    const float* rb  = (const float*)d_in[8];
    const float* gnw = (const float*)d_in[9];
    const float* gnb = (const float*)d_in[10];
    const float* bnw = (const float*)d_in[11];
    const float* bnb = (const float*)d_in[12];
    float* out = (float*)d_out;

    wtrans_kernel<<<96, 256>>>(tw, pw, gw, rw);
    zero_bn<<<1, 128>>>();

    for (int layer = 0; layer < 2; layer++) {
        proj_kernel<<<dim3(SP/64, Bb), 256>>>(layer, x, tb, pb, gb);
        attn_kernel<0><<<Bb*Sd*Sd, 192>>>();
        attn_kernel<1><<<Bb*Sd*Sd, 192>>>();
        attn_kernel<2><<<Bb*Sd*Sd, 192>>>();
        zero_gn<<<1, 64>>>();
        cross_kernel<<<dim3(SP/64, Bb), 256>>>(rb);
        gnres_kernel<<<dim3(4, Cc, Bb), 256>>>(layer, x, gnw + layer*Cc, gnb + layer*Cc,
                                               layer == 1 ? 1 : 0);
    }
    bnapply_kernel<<<((Bb*Cc*SP/4) + 255)/256, 256>>>(bnw, bnb, out);
}

// round 9
// speedup vs baseline: 2.7677x; 1.0550x over previous
#include <cuda_runtime.h>
#include <cuda_fp16.h>

#define Sd 48
#define SP (Sd*Sd*Sd)      // 110592
#define Bb 2
#define Cc 128
#define NVx (Bb*SP)        // 221184

// ---------------- mma helpers -----------------------------------------------
__device__ __forceinline__ float totf32(float x) {
    float r; asm("cvt.rna.tf32.f32 %0, %1;" : "=f"(r) : "f"(x)); return r;
}
__device__ __forceinline__ void mma_tf32(float* d, const unsigned* a, const unsigned* b) {
    asm volatile(
        "mma.sync.aligned.m16n8k8.row.col.f32.tf32.tf32.f32 "
        "{%0,%1,%2,%3},{%4,%5,%6,%7},{%8,%9},{%0,%1,%2,%3};"
        : "+f"(d[0]), "+f"(d[1]), "+f"(d[2]), "+f"(d[3])
        : "r"(a[0]), "r"(a[1]), "r"(a[2]), "r"(a[3]), "r"(b[0]), "r"(b[1]));
}
__device__ __forceinline__ void mma_f16(float* d, const unsigned* a, const unsigned* b) {
    asm volatile(
        "mma.sync.aligned.m16n8k16.row.col.f32.f16.f16.f32 "
        "{%0,%1,%2,%3},{%4,%5,%6,%7},{%8,%9},{%0,%1,%2,%3};"
        : "+f"(d[0]), "+f"(d[1]), "+f"(d[2]), "+f"(d[3])
        : "r"(a[0]), "r"(a[1]), "r"(a[2]), "r"(a[3]), "r"(b[0]), "r"(b[1]));
}
#define BITS(x) __float_as_uint(x)
__device__ __forceinline__ float2 h2f2(unsigned u) {
    __half2 h = *reinterpret_cast<__half2*>(&u);
    return __half22float2(h);
}

// ---------------- scratch --------------------------------------------------
__device__ float  g_h[(size_t)Bb*Cc*SP];
__device__ __half g_T[(size_t)NVx*64];
__device__ __half g_P[(size_t)NVx*64];
__device__ __half g_G[(size_t)NVx*64];
__device__ __half g_Yd[(size_t)NVx*64];        // D-dir partial, vox-major
__device__ __half g_Yh[(size_t)NVx*64];        // H-dir partial, vox-major
__device__ __half g_Yw[(size_t)NVx*64];        // final combined Y, g-major
__device__ float g_md[NVx]; __device__ float g_sd[NVx];
__device__ float g_mh[NVx]; __device__ float g_sh[NVx];
__device__ float g_cross[(size_t)Bb*Cc*SP];    // channel-first
__device__ float g_WT[128*192];                // k-major fused theta/phi/G weights
__device__ float g_rwT[64*128];                // k-major r_w
__device__ float g_gnsum[Bb*32]; __device__ float g_gnss[Bb*32];
__device__ float g_bnsum[Cc];    __device__ float g_bnss[Cc];

// ---------------- one-time weight transpose --------------------------------
__global__ __launch_bounds__(256) void wtrans_kernel(
    const float* __restrict__ tw, const float* __restrict__ pw,
    const float* __restrict__ gw, const float* __restrict__ rw)
{
    int idx = blockIdx.x*256 + threadIdx.x;
    if (idx < 128*192) {
        int k = idx / 192, m = idx % 192;
        float v;
        if (m < 64)       v = tw[m*128 + k];
        else if (m < 128) v = pw[(m-64)*128 + k];
        else              v = gw[(m-128)*128 + k];
        g_WT[idx] = v;
    }
    if (idx < 64*128) {
        int k = idx >> 7, m = idx & 127;
        g_rwT[idx] = rw[m*64 + k];
    }
}

// ---------------- projection (tf32 mma): [192m x 64n] tile, K=128 ----------
__global__ __launch_bounds__(256) void proj_kernel(
    int layer, const float* __restrict__ x,
    const float* __restrict__ tb, const float* __restrict__ pb,
    const float* __restrict__ gb)
{
    const float* src = layer ? (const float*)g_h : x;
    __shared__ float As[32][200];   // [k][m], pitch%32==8
    __shared__ float Bs[32][72];    // [k][n], pitch%32==8
    const int b = blockIdx.y, n0 = blockIdx.x*64, tid = threadIdx.x;
    const int warp = tid >> 5, lane = tid & 31;
    const int grp = lane >> 2, tig = lane & 3;
    const int m_base = (warp >> 1) * 48, n_base = (warp & 1) * 32;

    float acc[3][4][4];
    #pragma unroll
    for (int mt = 0; mt < 3; mt++)
        #pragma unroll
        for (int nt = 0; nt < 4; nt++)
            #pragma unroll
            for (int q = 0; q < 4; q++) acc[mt][nt][q] = 0.f;

    for (int k0 = 0; k0 < 128; k0 += 32) {
        #pragma unroll 4
        for (int idx = tid; idx < 32*192; idx += 256) {
            int kk = idx / 192, m = idx - kk*192;
            As[kk][m] = totf32(g_WT[(k0 + kk)*192 + m]);
        }
        #pragma unroll 2
        for (int idx = tid; idx < 32*64; idx += 256) {
            int kk = idx >> 6, n = idx & 63;
            Bs[kk][n] = totf32(src[(size_t)(b*Cc + k0 + kk)*SP + n0 + n]);
        }
        __syncthreads();
        #pragma unroll
        for (int ks = 0; ks < 4; ks++) {
            unsigned bf[4][2];
            #pragma unroll
            for (int nt = 0; nt < 4; nt++) {
                bf[nt][0] = BITS(Bs[ks*8 + tig    ][n_base + nt*8 + grp]);
                bf[nt][1] = BITS(Bs[ks*8 + tig + 4][n_base + nt*8 + grp]);
            }
            #pragma unroll
            for (int mt = 0; mt < 3; mt++) {
                const int mr = m_base + mt*16 + grp;
                unsigned af[4];
                af[0] = BITS(As[ks*8 + tig    ][mr]);
                af[1] = BITS(As[ks*8 + tig    ][mr + 8]);
                af[2] = BITS(As[ks*8 + tig + 4][mr]);
                af[3] = BITS(As[ks*8 + tig + 4][mr + 8]);
                #pragma unroll
                for (int nt = 0; nt < 4; nt++) mma_tf32(acc[mt][nt], af, bf[nt]);
            }
        }
        __syncthreads();
    }

    #pragma unroll
    for (int mt = 0; mt < 3; mt++) {
        #pragma unroll
        for (int rr = 0; rr < 2; rr++) {
            const int r = m_base + mt*16 + rr*8 + grp;
            const float* bias; __half* dst; int mm;
            if (r < 64)       { dst = g_T; mm = r;       bias = tb; }
            else if (r < 128) { dst = g_P; mm = r - 64;  bias = pb; }
            else              { dst = g_G; mm = r - 128; bias = gb; }
            const float bv = bias[mm];
            #pragma unroll
            for (int nt = 0; nt < 4; nt++) {
                const int c = n_base + nt*8 + tig*2;
                const size_t v0 = (size_t)b*SP + n0 + c;
                dst[v0*64 + mm]       = __float2half(acc[mt][nt][rr*2 + 0] + bv);
                dst[(v0 + 1)*64 + mm] = __float2half(acc[mt][nt][rr*2 + 1] + bv);
            }
        }
    }
}

// ---------------- pencil attention (fp16 mma m16n8k16) ----------------------
// DIR 0: D-axis (unmasked). DIR 1: H-axis (diag mask). DIR 2: W-axis (diag
// mask) + fused 3-way combine, writing final Y g-major (fp16) into g_Yw.
template<int DIR>
__global__ __launch_bounds__(192) void attn_kernel() {
    __shared__ __half Tl[48*72];    // T -> probs hi
    __shared__ __half Pl[48*72];    // P -> probs lo
    __shared__ __half Gl[64*72];    // G transposed: [c][j]
    __shared__ float  Sf[48*68];    // raw scores -> (DIR2) Y staging
    __shared__ float  rmS[48], rsS[48];

    const int pid = blockIdx.x;
    const int b = pid / (Sd*Sd);
    const int rr = pid % (Sd*Sd);
    const int u = rr / Sd, v = rr % Sd;
    size_t base; int stride;
    if (DIR == 0)      { base = (size_t)b*SP + u*Sd + v;       stride = Sd*Sd; }
    else if (DIR == 1) { base = (size_t)b*SP + u*Sd*Sd + v;    stride = Sd;    }
    else               { base = (size_t)b*SP + u*Sd*Sd + v*Sd; stride = 1;     }
    const int tid = threadIdx.x;
    const int warp = tid >> 5, lane = tid & 31;
    const int grp = lane >> 2, tig = lane & 3;

    // ---- load T,P ([i][k] halves) ----
    for (int l = tid; l < 48*8; l += 192) {
        int i = l >> 3, k8 = (l & 7) * 8;
        size_t o = (base + (size_t)i*stride)*64 + k8;
        uint4 tv = *(const uint4*)&g_T[o];
        uint4 pv = *(const uint4*)&g_P[o];
        *(uint4*)&Tl[i*72 + k8] = tv;
        *(uint4*)&Pl[i*72 + k8] = pv;
    }
    // ---- load G transposed: Gl[c][i] (same-word half-merges, conflict-free)
    for (int l = tid; l < 48*8; l += 192) {
        int i = l % 48, c8 = (l / 48) * 8;
        uint4 gv = *(const uint4*)&g_G[(base + (size_t)i*stride)*64 + c8];
        const __half* gp = (const __half*)&gv;
        #pragma unroll
        for (int q = 0; q < 8; q++) Gl[(c8 + q)*72 + i] = gp[q];
    }
    __syncthreads();

    // ---- scores: S[48,48] = T @ P^T (fp16 mma, K=64 in 4 chunks) ----------
    const int mr = (warp >> 1)*16 + grp;
    float sacc[3][4];
    #pragma unroll
    for (int nt = 0; nt < 3; nt++)
        #pragma unroll
        for (int q = 0; q < 4; q++) sacc[nt][q] = 0.f;
    #pragma unroll
    for (int kc = 0; kc < 4; kc++) {
        unsigned af[4];
        af[0] = *(const unsigned*)&Tl[ mr     *72 + kc*16 + tig*2    ];
        af[1] = *(const unsigned*)&Tl[(mr + 8)*72 + kc*16 + tig*2    ];
        af[2] = *(const unsigned*)&Tl[ mr     *72 + kc*16 + tig*2 + 8];
        af[3] = *(const unsigned*)&Tl[(mr + 8)*72 + kc*16 + tig*2 + 8];
        #pragma unroll
        for (int nt = 0; nt < 3; nt++) {
            const int nr = (warp & 1)*24 + nt*8 + grp;
            unsigned bf[2];
            bf[0] = *(const unsigned*)&Pl[nr*72 + kc*16 + tig*2    ];
            bf[1] = *(const unsigned*)&Pl[nr*72 + kc*16 + tig*2 + 8];
            mma_f16(sacc[nt], af, bf);
        }
    }

    // ---- write raw scores (+diag mask) into Sf ----
    #pragma unroll
    for (int nt = 0; nt < 3; nt++) {
        const int j0 = (warp & 1)*24 + nt*8 + tig*2;
        float c0 = sacc[nt][0], c1 = sacc[nt][1], c2 = sacc[nt][2], c3 = sacc[nt][3];
        if (DIR != 0) {
            if (mr     == j0    ) c0 = -1e30f;
            if (mr     == j0 + 1) c1 = -1e30f;
            if (mr + 8 == j0    ) c2 = -1e30f;
            if (mr + 8 == j0 + 1) c3 = -1e30f;
        }
        Sf[ mr     *68 + j0] = c0; Sf[ mr     *68 + j0 + 1] = c1;
        Sf[(mr + 8)*68 + j0] = c2; Sf[(mr + 8)*68 + j0 + 1] = c3;
    }
    __syncthreads();    // scores done; all Tl/Pl mma reads complete

    // ---- softmax: 4 threads/row, 12 cols each; probs hi/lo (fp16) ---------
    {
        const int r = tid >> 2, q = tid & 3;
        float vals[12];
        float mx = -3.0e38f;
        #pragma unroll
        for (int j = 0; j < 12; j++) {
            vals[j] = Sf[r*68 + q*12 + j];
            mx = fmaxf(mx, vals[j]);
        }
        mx = fmaxf(mx, __shfl_xor_sync(0xffffffffu, mx, 1));
        mx = fmaxf(mx, __shfl_xor_sync(0xffffffffu, mx, 2));
        float sm = 0.f;
        #pragma unroll
        for (int j = 0; j < 12; j++) {
            float e = __expf(vals[j] - mx);
            sm += e;
            __half hh = __float2half(e);
            Tl[r*72 + q*12 + j] = hh;
            Pl[r*72 + q*12 + j] = __float2half(e - __half2float(hh));
        }
        sm += __shfl_xor_sync(0xffffffffu, sm, 1);
        sm += __shfl_xor_sync(0xffffffffu, sm, 2);
        if (DIR == 2) {
            if (q == 0) { rmS[r] = mx; rsS[r] = sm; }
        } else if (q == 0) {
            size_t vx = base + (size_t)r*stride;
            if (DIR == 0) { g_md[vx] = mx; g_sd[vx] = sm; }
            else          { g_mh[vx] = mx; g_sh[vx] = sm; }
        }
    }
    __syncthreads();

    // ---- AV: Y[48,64] = S @ G (fp16 mma, S = hi + lo, K=48 in 3 chunks) ---
    float yacc[4][4];
    #pragma unroll
    for (int nt = 0; nt < 4; nt++)
        #pragma unroll
        for (int q = 0; q < 4; q++) yacc[nt][q] = 0.f;
    #pragma unroll
    for (int kc = 0; kc < 3; kc++) {
        unsigned ah[4], al[4];
        ah[0] = *(const unsigned*)&Tl[ mr     *72 + kc*16 + tig*2    ];
        ah[1] = *(const unsigned*)&Tl[(mr + 8)*72 + kc*16 + tig*2    ];
        ah[2] = *(const unsigned*)&Tl[ mr     *72 + kc*16 + tig*2 + 8];
        ah[3] = *(const unsigned*)&Tl[(mr + 8)*72 + kc*16 + tig*2 + 8];
        al[0] = *(const unsigned*)&Pl[ mr     *72 + kc*16 + tig*2    ];
        al[1] = *(const unsigned*)&Pl[(mr + 8)*72 + kc*16 + tig*2    ];
        al[2] = *(const unsigned*)&Pl[ mr     *72 + kc*16 + tig*2 + 8];
        al[3] = *(const unsigned*)&Pl[(mr + 8)*72 + kc*16 + tig*2 + 8];
        #pragma unroll
        for (int nt = 0; nt < 4; nt++) {
            const int nr = (warp & 1)*32 + nt*8 + grp;
            unsigned bf[2];
            bf[0] = *(const unsigned*)&Gl[nr*72 + kc*16 + tig*2    ];
            bf[1] = *(const unsigned*)&Gl[nr*72 + kc*16 + tig*2 + 8];
            mma_f16(yacc[nt], ah, bf);
            mma_f16(yacc[nt], al, bf);
        }
    }

    if (DIR != 2) {
        __half* Yout = (DIR == 0) ? g_Yd : g_Yh;
        #pragma unroll
        for (int nt = 0; nt < 4; nt++) {
            const int c = (warp & 1)*32 + nt*8 + tig*2;
            *(__half2*)&Yout[(base + (size_t)mr*stride)*64 + c] =
                __floats2half2_rn(yacc[nt][0], yacc[nt][1]);
            *(__half2*)&Yout[(base + (size_t)(mr + 8)*stride)*64 + c] =
                __floats2half2_rn(yacc[nt][2], yacc[nt][3]);
        }
    } else {
        // stage Y into Sf (fp32), then fused 3-way combine, g-major output
        #pragma unroll
        for (int nt = 0; nt < 4; nt++) {
            const int c = (warp & 1)*32 + nt*8 + tig*2;
            Sf[ mr     *68 + c] = yacc[nt][0]; Sf[ mr     *68 + c + 1] = yacc[nt][1];
            Sf[(mr + 8)*68 + c] = yacc[nt][2]; Sf[(mr + 8)*68 + c + 1] = yacc[nt][3];
        }
        __syncthreads();
        const int i = tid >> 2, q = tid & 3;
        const size_t vox = base + i;
        float md = g_md[vox], sd = g_sd[vox];
        float mh = g_mh[vox], sh = g_sh[vox];
        float mw = rmS[i],    sw = rsS[i];
        float m  = fmaxf(md, fmaxf(mh, mw));
        float wd = __expf(md - m), wh = __expf(mh - m), ww = __expf(mw - m);
        float inv = 1.0f / (sd*wd + sh*wh + sw*ww);
        wd *= inv; wh *= inv; ww *= inv;
        const size_t sp0 = base - (size_t)b*SP;
        #pragma unroll
        for (int jj = 0; jj < 4; jj++) {
            const int g = q*16 + jj*4;
            uint2 au = *(const uint2*)&g_Yd[vox*64 + g];
            uint2 hu = *(const uint2*)&g_Yh[vox*64 + g];
            float2 a0 = h2f2(au.x), a1 = h2f2(au.y);
            float2 h0 = h2f2(hu.x), h1 = h2f2(hu.y);
            g_Yw[((size_t)(b*64 + g    ))*SP + sp0 + i] =
                __float2half(a0.x*wd + h0.x*wh + Sf[i*68 + g    ]*ww);
            g_Yw[((size_t)(b*64 + g + 1))*SP + sp0 + i] =
                __float2half(a0.y*wd + h0.y*wh + Sf[i*68 + g + 1]*ww);
            g_Yw[((size_t)(b*64 + g + 2))*SP + sp0 + i] =
                __float2half(a1.x*wd + h1.x*wh + Sf[i*68 + g + 2]*ww);
            g_Yw[((size_t)(b*64 + g + 3))*SP + sp0 + i] =
                __float2half(a1.y*wd + h1.y*wh + Sf[i*68 + g + 3]*ww);
        }
    }
}

// ---------------- zero stat accumulators ------------------------------------
__global__ void zero_gn() { int t = threadIdx.x; if (t < Bb*32) { g_gnsum[t]=0.f; g_gnss[t]=0.f; } }
__global__ void zero_bn() { int t = threadIdx.x; if (t < Cc)    { g_bnsum[t]=0.f; g_bnss[t]=0.f; } }

// ---------------- cross GEMM (tf32 mma): [128ch x 64vox], K=64 + GN sums ---
__global__ __launch_bounds__(256) void cross_kernel(const float* __restrict__ rb)
{
    __shared__ float As[64][136];   // rw [k=g][m=ch], pitch%32==8
    __shared__ float Bs[32][72];    // Y  [k][n],      pitch%32==8
    __shared__ float gsum[32], gss[32];
    const int b = blockIdx.y, n0 = blockIdx.x*64, tid = threadIdx.x;
    const int warp = tid >> 5, lane = tid & 31;
    const int grp = lane >> 2, tig = lane & 3;
    const int m_base = (warp >> 1) * 32, n_base = (warp & 1) * 32;

    float acc[2][4][4];
    #pragma unroll
    for (int mt = 0; mt < 2; mt++)
        #pragma unroll
        for (int nt = 0; nt < 4; nt++)
            #pragma unroll
            for (int q = 0; q < 4; q++) acc[mt][nt][q] = 0.f;

    #pragma unroll 4
    for (int idx = tid; idx < 64*128; idx += 256) {
        int k = idx >> 7, m = idx & 127;
        As[k][m] = totf32(g_rwT[idx]);
    }
    if (tid < 32) { gsum[tid] = 0.f; gss[tid] = 0.f; }

    for (int g0 = 0; g0 < 64; g0 += 32) {
        {
            int idx = tid;
            int kk = idx >> 3, n8 = (idx & 7) * 8;
            uint4 yv = *(const uint4*)&g_Yw[((size_t)b*64 + g0 + kk)*SP + n0 + n8];
            *(float2*)&Bs[kk][n8    ] = h2f2(yv.x);
            *(float2*)&Bs[kk][n8 + 2] = h2f2(yv.y);
            *(float2*)&Bs[kk][n8 + 4] = h2f2(yv.z);
            *(float2*)&Bs[kk][n8 + 6] = h2f2(yv.w);
        }
        __syncthreads();
        #pragma unroll
        for (int ks = 0; ks < 4; ks++) {
            unsigned bf[4][2];
            #pragma unroll
            for (int nt = 0; nt < 4; nt++) {
                bf[nt][0] = BITS(Bs[ks*8 + tig    ][n_base + nt*8 + grp]);
                bf[nt][1] = BITS(Bs[ks*8 + tig + 4][n_base + nt*8 + grp]);
            }
            #pragma unroll
            for (int mt = 0; mt < 2; mt++) {
                const int mr = m_base + mt*16 + grp;
                unsigned af[4];
                af[0] = BITS(As[g0 + ks*8 + tig    ][mr]);
                af[1] = BITS(As[g0 + ks*8 + tig    ][mr + 8]);
                af[2] = BITS(As[g0 + ks*8 + tig + 4][mr]);
                af[3] = BITS(As[g0 + ks*8 + tig + 4][mr + 8]);
                #pragma unroll
                for (int nt = 0; nt < 4; nt++) mma_tf32(acc[mt][nt], af, bf[nt]);
            }
        }
        __syncthreads();
    }

    #pragma unroll
    for (int mt = 0; mt < 2; mt++) {
        #pragma unroll
        for (int rr = 0; rr < 2; rr++) {
            const int r = m_base + mt*16 + rr*8 + grp;
            const float bv = rb[r];
            float ps = 0.f, pss = 0.f;
            #pragma unroll
            for (int nt = 0; nt < 4; nt++) {
                const int c = n_base + nt*8 + tig*2;
                float v0 = acc[mt][nt][rr*2 + 0] + bv;
                float v1 = acc[mt][nt][rr*2 + 1] + bv;
                size_t ob = ((size_t)b*Cc + r)*SP + n0 + c;
                g_cross[ob]     = v0;
                g_cross[ob + 1] = v1;
                ps += v0 + v1; pss += v0*v0 + v1*v1;
            }
            ps  += __shfl_xor_sync(0xffffffffu, ps, 1);
            ps  += __shfl_xor_sync(0xffffffffu, ps, 2);
            pss += __shfl_xor_sync(0xffffffffu, pss, 1);
            pss += __shfl_xor_sync(0xffffffffu, pss, 2);
            if (tig == 0) {
                atomicAdd(&gsum[r >> 2], ps);
                atomicAdd(&gss [r >> 2], pss);
            }
        }
    }
    __syncthreads();
    if (tid < 32) {
        atomicAdd(&g_gnsum[b*32 + tid], gsum[tid]);
        atomicAdd(&g_gnss [b*32 + tid], gss[tid]);
    }
}

// ---------------- GroupNorm + residual (streaming, channel-first) ----------
__global__ __launch_bounds__(256) void gnres_kernel(
    int layer, const float* __restrict__ x,
    const float* __restrict__ gnw, const float* __restrict__ gnb,
    int accum_bn)
{
    const float* resid = layer ? (const float*)g_h : x;
    const int c = blockIdx.y, b = blockIdx.z, chunk = blockIdx.x;
    const size_t base = ((size_t)(b*Cc + c))*SP + (size_t)chunk*(SP/4);
    const int g = c >> 2;
    const float invN = 1.0f / (4.0f * SP);
    float mu  = g_gnsum[b*32 + g] * invN;
    float var = g_gnss[b*32 + g] * invN - mu*mu;
    float rstd = rsqrtf(var + 1e-5f);
    float w = gnw[c], bias = gnb[c];
    float s = 0.f, ss = 0.f;
    for (int j = 0; j < 27; j++) {
        size_t o = base + (size_t)j*1024 + threadIdx.x*4;
        float4 cv = *(const float4*)&g_cross[o];
        float4 rv = *(const float4*)&resid[o];
        float4 h;
        h.x = rv.x + (cv.x - mu)*rstd*w + bias;
        h.y = rv.y + (cv.y - mu)*rstd*w + bias;
        h.z = rv.z + (cv.z - mu)*rstd*w + bias;
        h.w = rv.w + (cv.w - mu)*rstd*w + bias;
        *(float4*)&g_h[o] = h;
        if (accum_bn) {
            s  += h.x + h.y + h.z + h.w;
            ss += h.x*h.x + h.y*h.y + h.z*h.z + h.w*h.w;
        }
    }
    if (accum_bn) {
        #pragma unroll
        for (int o = 16; o > 0; o >>= 1) {
            s  += __shfl_xor_sync(0xffffffffu, s,  o);
            ss += __shfl_xor_sync(0xffffffffu, ss, o);
        }
        __shared__ float ws[8], wss[8];
        int wid = threadIdx.x >> 5, lane = threadIdx.x & 31;
        if (lane == 0) { ws[wid] = s; wss[wid] = ss; }
        __syncthreads();
        if (threadIdx.x == 0) {
            float ts = 0.f, tss = 0.f;
            #pragma unroll
            for (int k = 0; k < 8; k++) { ts += ws[k]; tss += wss[k]; }
            atomicAdd(&g_bnsum[c], ts);
            atomicAdd(&g_bnss[c],  tss);
        }
    }
}

// ---------------- BatchNorm apply + ReLU ------------------------------------
__global__ __launch_bounds__(256) void bnapply_kernel(
    const float* __restrict__ bw, const float* __restrict__ bb, float* __restrict__ out)
{
    size_t i4 = (size_t)blockIdx.x*256 + threadIdx.x;
    if (i4 >= (size_t)Bb*Cc*SP/4) return;
    size_t i = i4 * 4;
    int c = (int)((i / SP) & 127);
    const float invN = 1.0f / ((float)Bb * SP);
    float mu  = g_bnsum[c] * invN;
    float var = g_bnss[c] * invN - mu*mu;
    float rstd = rsqrtf(var + 1e-5f);
    float wv = bw[c], bv = bb[c];
    float4 v = *(const float4*)&g_h[i];
    v.x = fmaxf((v.x - mu)*rstd*wv + bv, 0.f);
    v.y = fmaxf((v.y - mu)*rstd*wv + bv, 0.f);
    v.z = fmaxf((v.z - mu)*rstd*wv + bv, 0.f);
    v.w = fmaxf((v.w - mu)*rstd*wv + bv, 0.f);
    *(float4*)&out[i] = v;
}

// ---------------- launch -----------------------------------------------------
extern "C" void kernel_launch(void* const* d_in, const int* in_sizes, int n_in,
                              void* d_out, int out_size)
{
    const float* x   = (const float*)d_in[0];
    const float* tw  = (const float*)d_in[1];
    const float* tb  = (const float*)d_in[2];
    const float* pw  = (const float*)d_in[3];
    const float* pb  = (const float*)d_in[4];
    const float* gw  = (const float*)d_in[5];
    const float* gb  = (const float*)d_in[6];
    const float* rw  = (const float*)d_in[7];
    const float* rb  = (const float*)d_in[8];
    const float* gnw = (const float*)d_in[9];
    const float* gnb = (const float*)d_in[10];
    const float* bnw = (const float*)d_in[11];
    const float* bnb = (const float*)d_in[12];
    float* out = (float*)d_out;

    wtrans_kernel<<<96, 256>>>(tw, pw, gw, rw);
    zero_bn<<<1, 128>>>();

    for (int layer = 0; layer < 2; layer++) {
        proj_kernel<<<dim3(SP/64, Bb), 256>>>(layer, x, tb, pb, gb);
        attn_kernel<0><<<Bb*Sd*Sd, 192>>>();
        attn_kernel<1><<<Bb*Sd*Sd, 192>>>();
        attn_kernel<2><<<Bb*Sd*Sd, 192>>>();
        zero_gn<<<1, 64>>>();
        cross_kernel<<<dim3(SP/64, Bb), 256>>>(rb);
        gnres_kernel<<<dim3(4, Cc, Bb), 256>>>(layer, x, gnw + layer*Cc, gnb + layer*Cc,
                                               layer == 1 ? 1 : 0);
    }
    bnapply_kernel<<<((Bb*Cc*SP/4) + 255)/256, 256>>>(bnw, bnb, out);
}

// round 10
// speedup vs baseline: 3.0684x; 1.1087x over previous
#include <cuda_runtime.h>
#include <cuda_fp16.h>

#define Sd 48
#define SP (Sd*Sd*Sd)      // 110592
#define Bb 2
#define Cc 128
#define NVx (Bb*SP)        // 221184

// ---------------- mma / ldmatrix helpers ------------------------------------
__device__ __forceinline__ float totf32(float x) {
    float r; asm("cvt.rna.tf32.f32 %0, %1;" : "=f"(r) : "f"(x)); return r;
}
__device__ __forceinline__ void mma_tf32(float* d, const unsigned* a, const unsigned* b) {
    asm volatile(
        "mma.sync.aligned.m16n8k8.row.col.f32.tf32.tf32.f32 "
        "{%0,%1,%2,%3},{%4,%5,%6,%7},{%8,%9},{%0,%1,%2,%3};"
        : "+f"(d[0]), "+f"(d[1]), "+f"(d[2]), "+f"(d[3])
        : "r"(a[0]), "r"(a[1]), "r"(a[2]), "r"(a[3]), "r"(b[0]), "r"(b[1]));
}
__device__ __forceinline__ void mma_f16(float* d, const unsigned* a, const unsigned* b) {
    asm volatile(
        "mma.sync.aligned.m16n8k16.row.col.f32.f16.f16.f32 "
        "{%0,%1,%2,%3},{%4,%5,%6,%7},{%8,%9},{%0,%1,%2,%3};"
        : "+f"(d[0]), "+f"(d[1]), "+f"(d[2]), "+f"(d[3])
        : "r"(a[0]), "r"(a[1]), "r"(a[2]), "r"(a[3]), "r"(b[0]), "r"(b[1]));
}
__device__ __forceinline__ unsigned smaddr(const void* p) {
    unsigned a;
    asm("{ .reg .u64 t; cvta.to.shared.u64 t, %1; cvt.u32.u64 %0, t; }" : "=r"(a) : "l"(p));
    return a;
}
__device__ __forceinline__ void ldsm_x4(unsigned* r, unsigned a) {
    asm volatile("ldmatrix.sync.aligned.m8n8.x4.shared.b16 {%0,%1,%2,%3},[%4];"
        : "=r"(r[0]), "=r"(r[1]), "=r"(r[2]), "=r"(r[3]) : "r"(a));
}
__device__ __forceinline__ void ldsm_x2(unsigned* r, unsigned a) {
    asm volatile("ldmatrix.sync.aligned.m8n8.x2.shared.b16 {%0,%1},[%2];"
        : "=r"(r[0]), "=r"(r[1]) : "r"(a));
}
__device__ __forceinline__ void ldsm_x4_t(unsigned* r, unsigned a) {
    asm volatile("ldmatrix.sync.aligned.m8n8.x4.trans.shared.b16 {%0,%1,%2,%3},[%4];"
        : "=r"(r[0]), "=r"(r[1]), "=r"(r[2]), "=r"(r[3]) : "r"(a));
}
#define BITS(x) __float_as_uint(x)
__device__ __forceinline__ float2 h2f2(unsigned u) {
    __half2 h = *reinterpret_cast<__half2*>(&u);
    return __half22float2(h);
}

// ---------------- scratch --------------------------------------------------
__device__ float  g_h[(size_t)Bb*Cc*SP];
__device__ __half g_T[(size_t)NVx*64];
__device__ __half g_P[(size_t)NVx*64];
__device__ __half g_G[(size_t)NVx*64];
__device__ __half g_Yd[(size_t)NVx*64];        // D-dir partial, vox-major
__device__ __half g_Yh[(size_t)NVx*64];        // H-dir partial, vox-major
__device__ __half g_Yw[(size_t)NVx*64];        // final combined Y, g-major
__device__ float g_md[NVx]; __device__ float g_sd[NVx];
__device__ float g_mh[NVx]; __device__ float g_sh[NVx];
__device__ __half g_cross[(size_t)Bb*Cc*SP];   // channel-first, fp16
__device__ float g_WT[128*192];                // k-major fused theta/phi/G weights
__device__ float g_rwT[64*128];                // k-major r_w
__device__ float g_gnsum[Bb*32]; __device__ float g_gnss[Bb*32];
__device__ float g_bnsum[Cc];    __device__ float g_bnss[Cc];

// ---------------- one-time weight transpose --------------------------------
__global__ __launch_bounds__(256) void wtrans_kernel(
    const float* __restrict__ tw, const float* __restrict__ pw,
    const float* __restrict__ gw, const float* __restrict__ rw)
{
    int idx = blockIdx.x*256 + threadIdx.x;
    if (idx < 128*192) {
        int k = idx / 192, m = idx % 192;
        float v;
        if (m < 64)       v = tw[m*128 + k];
        else if (m < 128) v = pw[(m-64)*128 + k];
        else              v = gw[(m-128)*128 + k];
        g_WT[idx] = v;
    }
    if (idx < 64*128) {
        int k = idx >> 7, m = idx & 127;
        g_rwT[idx] = rw[m*64 + k];
    }
}

// ---------------- projection (tf32 mma): [192m x 64n] tile, K=128 ----------
__global__ __launch_bounds__(256) void proj_kernel(
    int layer, const float* __restrict__ x,
    const float* __restrict__ tb, const float* __restrict__ pb,
    const float* __restrict__ gb)
{
    const float* src = layer ? (const float*)g_h : x;
    __shared__ float As[32][200];   // [k][m], pitch%32==8
    __shared__ float Bs[32][72];    // [k][n], pitch%32==8
    const int b = blockIdx.y, n0 = blockIdx.x*64, tid = threadIdx.x;
    const int warp = tid >> 5, lane = tid & 31;
    const int grp = lane >> 2, tig = lane & 3;
    const int m_base = (warp >> 1) * 48, n_base = (warp & 1) * 32;

    float acc[3][4][4];
    #pragma unroll
    for (int mt = 0; mt < 3; mt++)
        #pragma unroll
        for (int nt = 0; nt < 4; nt++)
            #pragma unroll
            for (int q = 0; q < 4; q++) acc[mt][nt][q] = 0.f;

    for (int k0 = 0; k0 < 128; k0 += 32) {
        #pragma unroll 4
        for (int idx = tid; idx < 32*192; idx += 256) {
            int kk = idx / 192, m = idx - kk*192;
            As[kk][m] = totf32(g_WT[(k0 + kk)*192 + m]);
        }
        #pragma unroll 2
        for (int idx = tid; idx < 32*64; idx += 256) {
            int kk = idx >> 6, n = idx & 63;
            Bs[kk][n] = totf32(src[(size_t)(b*Cc + k0 + kk)*SP + n0 + n]);
        }
        __syncthreads();
        #pragma unroll
        for (int ks = 0; ks < 4; ks++) {
            unsigned bf[4][2];
            #pragma unroll
            for (int nt = 0; nt < 4; nt++) {
                bf[nt][0] = BITS(Bs[ks*8 + tig    ][n_base + nt*8 + grp]);
                bf[nt][1] = BITS(Bs[ks*8 + tig + 4][n_base + nt*8 + grp]);
            }
            #pragma unroll
            for (int mt = 0; mt < 3; mt++) {
                const int mr = m_base + mt*16 + grp;
                unsigned af[4];
                af[0] = BITS(As[ks*8 + tig    ][mr]);
                af[1] = BITS(As[ks*8 + tig    ][mr + 8]);
                af[2] = BITS(As[ks*8 + tig + 4][mr]);
                af[3] = BITS(As[ks*8 + tig + 4][mr + 8]);
                #pragma unroll
                for (int nt = 0; nt < 4; nt++) mma_tf32(acc[mt][nt], af, bf[nt]);
            }
        }
        __syncthreads();
    }

    #pragma unroll
    for (int mt = 0; mt < 3; mt++) {
        #pragma unroll
        for (int rr = 0; rr < 2; rr++) {
            const int r = m_base + mt*16 + rr*8 + grp;
            const float* bias; __half* dst; int mm;
            if (r < 64)       { dst = g_T; mm = r;       bias = tb; }
            else if (r < 128) { dst = g_P; mm = r - 64;  bias = pb; }
            else              { dst = g_G; mm = r - 128; bias = gb; }
            const float bv = bias[mm];
            #pragma unroll
            for (int nt = 0; nt < 4; nt++) {
                const int c = n_base + nt*8 + tig*2;
                const size_t v0 = (size_t)b*SP + n0 + c;
                dst[v0*64 + mm]       = __float2half(acc[mt][nt][rr*2 + 0] + bv);
                dst[(v0 + 1)*64 + mm] = __float2half(acc[mt][nt][rr*2 + 1] + bv);
            }
        }
    }
}

// ---------------- pencil attention (fp16 mma + ldmatrix) --------------------
// DIR 0: D-axis (unmasked). DIR 1: H-axis (diag mask). DIR 2: W-axis (diag
// mask) + fused 3-way combine, writing final Y g-major (fp16) into g_Yw.
template<int DIR>
__global__ __launch_bounds__(192) void attn_kernel() {
    __shared__ __half Tl[48*72];    // T rows [i][k] -> probs [i][j]
    __shared__ __half Pl[48*72];    // P rows [j][k]
    __shared__ __half Gl[48*72];    // G rows [j][c]
    __shared__ float  Sf[48*68];    // raw scores -> (DIR2) Y staging
    __shared__ float  rmS[48], rsS[48];

    const int pid = blockIdx.x;
    const int b = pid / (Sd*Sd);
    const int rr = pid % (Sd*Sd);
    const int u = rr / Sd, v = rr % Sd;
    size_t base; int stride;
    if (DIR == 0)      { base = (size_t)b*SP + u*Sd + v;       stride = Sd*Sd; }
    else if (DIR == 1) { base = (size_t)b*SP + u*Sd*Sd + v;    stride = Sd;    }
    else               { base = (size_t)b*SP + u*Sd*Sd + v*Sd; stride = 1;     }
    const int tid = threadIdx.x;
    const int warp = tid >> 5, lane = tid & 31;
    const int grp = lane >> 2, tig = lane & 3;

    // ---- load T,P,G rows ----
    for (int l = tid; l < 48*8; l += 192) {
        int i = l >> 3, k8 = (l & 7) * 8;
        size_t o = (base + (size_t)i*stride)*64 + k8;
        *(uint4*)&Tl[i*72 + k8] = *(const uint4*)&g_T[o];
        *(uint4*)&Pl[i*72 + k8] = *(const uint4*)&g_P[o];
        *(uint4*)&Gl[i*72 + k8] = *(const uint4*)&g_G[o];
    }
    __syncthreads();

    const int mrow0 = (warp >> 1) * 16;
    const int mr = mrow0 + grp;
    const int nhalf = (warp & 1) * 24;       // scores n-offset
    const int ncol0 = (warp & 1) * 32;       // AV n-offset

    // ldmatrix source addresses
    const unsigned Ta = smaddr(&Tl[(mrow0 + (lane & 15))*72 + (lane >> 4)*8]);
    const unsigned Pa = smaddr(&Pl[(nhalf + (lane & 7))*72 + ((lane >> 3) & 1)*8]);
    const unsigned Ga = smaddr(&Gl[((lane & 7) + ((lane >> 3) & 1)*8)*72
                                   + ncol0 + (lane >> 4)*8]);

    // ---- scores: S[48,48] = T @ P^T ----
    float sacc[3][4];
    #pragma unroll
    for (int nt = 0; nt < 3; nt++)
        #pragma unroll
        for (int q = 0; q < 4; q++) sacc[nt][q] = 0.f;
    #pragma unroll
    for (int kc = 0; kc < 4; kc++) {
        unsigned af[4];
        ldsm_x4(af, Ta + kc*32);
        #pragma unroll
        for (int nt = 0; nt < 3; nt++) {
            unsigned bf[2];
            ldsm_x2(bf, Pa + nt*8*144 + kc*32);
            mma_f16(sacc[nt], af, bf);
        }
    }

    // ---- write raw scores (+diag mask) into Sf ----
    #pragma unroll
    for (int nt = 0; nt < 3; nt++) {
        const int j0 = nhalf + nt*8 + tig*2;
        float c0 = sacc[nt][0], c1 = sacc[nt][1], c2 = sacc[nt][2], c3 = sacc[nt][3];
        if (DIR != 0) {
            if (mr     == j0    ) c0 = -1e30f;
            if (mr     == j0 + 1) c1 = -1e30f;
            if (mr + 8 == j0    ) c2 = -1e30f;
            if (mr + 8 == j0 + 1) c3 = -1e30f;
        }
        Sf[ mr     *68 + j0] = c0; Sf[ mr     *68 + j0 + 1] = c1;
        Sf[(mr + 8)*68 + j0] = c2; Sf[(mr + 8)*68 + j0 + 1] = c3;
    }
    __syncthreads();    // scores done; Tl/Pl mma reads complete

    // ---- softmax: 4 threads/row, 12 cols each; probs fp16 into Tl ---------
    {
        const int r = tid >> 2, q = tid & 3;
        float vals[12];
        float mx = -3.0e38f;
        #pragma unroll
        for (int j = 0; j < 12; j++) {
            vals[j] = Sf[r*68 + q*12 + j];
            mx = fmaxf(mx, vals[j]);
        }
        mx = fmaxf(mx, __shfl_xor_sync(0xffffffffu, mx, 1));
        mx = fmaxf(mx, __shfl_xor_sync(0xffffffffu, mx, 2));
        float sm = 0.f;
        #pragma unroll
        for (int j = 0; j < 12; j++) {
            float e = __expf(vals[j] - mx);
            sm += e;
            Tl[r*72 + q*12 + j] = __float2half(e);
        }
        sm += __shfl_xor_sync(0xffffffffu, sm, 1);
        sm += __shfl_xor_sync(0xffffffffu, sm, 2);
        if (DIR == 2) {
            if (q == 0) { rmS[r] = mx; rsS[r] = sm; }
        } else if (q == 0) {
            size_t vx = base + (size_t)r*stride;
            if (DIR == 0) { g_md[vx] = mx; g_sd[vx] = sm; }
            else          { g_mh[vx] = mx; g_sh[vx] = sm; }
        }
    }
    __syncthreads();

    // ---- AV: Y[48,64] = probs @ G (ldmatrix.trans B, K=48) ----------------
    float yacc[4][4];
    #pragma unroll
    for (int nt = 0; nt < 4; nt++)
        #pragma unroll
        for (int q = 0; q < 4; q++) yacc[nt][q] = 0.f;
    #pragma unroll
    for (int kc = 0; kc < 3; kc++) {
        unsigned af[4];
        ldsm_x4(af, Ta + kc*32);
        #pragma unroll
        for (int pair = 0; pair < 2; pair++) {
            unsigned bv[4];
            ldsm_x4_t(bv, Ga + kc*16*144 + pair*32);
            mma_f16(yacc[pair*2],     af, bv);
            mma_f16(yacc[pair*2 + 1], af, bv + 2);
        }
    }

    if (DIR != 2) {
        __half* Yout = (DIR == 0) ? g_Yd : g_Yh;
        #pragma unroll
        for (int nt = 0; nt < 4; nt++) {
            const int c = ncol0 + nt*8 + tig*2;
            *(__half2*)&Yout[(base + (size_t)mr*stride)*64 + c] =
                __floats2half2_rn(yacc[nt][0], yacc[nt][1]);
            *(__half2*)&Yout[(base + (size_t)(mr + 8)*stride)*64 + c] =
                __floats2half2_rn(yacc[nt][2], yacc[nt][3]);
        }
    } else {
        // stage Y into Sf (fp32), then fused 3-way combine, g-major output
        #pragma unroll
        for (int nt = 0; nt < 4; nt++) {
            const int c = ncol0 + nt*8 + tig*2;
            Sf[ mr     *68 + c] = yacc[nt][0]; Sf[ mr     *68 + c + 1] = yacc[nt][1];
            Sf[(mr + 8)*68 + c] = yacc[nt][2]; Sf[(mr + 8)*68 + c + 1] = yacc[nt][3];
        }
        __syncthreads();
        const int i = tid >> 2, q = tid & 3;
        const size_t vox = base + i;
        float md = g_md[vox], sd = g_sd[vox];
        float mh = g_mh[vox], sh = g_sh[vox];
        float mw = rmS[i],    sw = rsS[i];
        float m  = fmaxf(md, fmaxf(mh, mw));
        float wd = __expf(md - m), wh = __expf(mh - m), ww = __expf(mw - m);
        float inv = 1.0f / (sd*wd + sh*wh + sw*ww);
        wd *= inv; wh *= inv; ww *= inv;
        const size_t sp0 = base - (size_t)b*SP;
        #pragma unroll
        for (int jj = 0; jj < 4; jj++) {
            const int g = q*16 + jj*4;
            uint2 au = *(const uint2*)&g_Yd[vox*64 + g];
            uint2 hu = *(const uint2*)&g_Yh[vox*64 + g];
            float2 a0 = h2f2(au.x), a1 = h2f2(au.y);
            float2 h0 = h2f2(hu.x), h1 = h2f2(hu.y);
            g_Yw[((size_t)(b*64 + g    ))*SP + sp0 + i] =
                __float2half(a0.x*wd + h0.x*wh + Sf[i*68 + g    ]*ww);
            g_Yw[((size_t)(b*64 + g + 1))*SP + sp0 + i] =
                __float2half(a0.y*wd + h0.y*wh + Sf[i*68 + g + 1]*ww);
            g_Yw[((size_t)(b*64 + g + 2))*SP + sp0 + i] =
                __float2half(a1.x*wd + h1.x*wh + Sf[i*68 + g + 2]*ww);
            g_Yw[((size_t)(b*64 + g + 3))*SP + sp0 + i] =
                __float2half(a1.y*wd + h1.y*wh + Sf[i*68 + g + 3]*ww);
        }
    }
}

// ---------------- zero stat accumulators ------------------------------------
__global__ void zero_gn() { int t = threadIdx.x; if (t < Bb*32) { g_gnsum[t]=0.f; g_gnss[t]=0.f; } }
__global__ void zero_bn() { int t = threadIdx.x; if (t < Cc)    { g_bnsum[t]=0.f; g_bnss[t]=0.f; } }

// ---------------- cross GEMM (tf32 mma): [128ch x 64vox], K=64 + GN sums ---
__global__ __launch_bounds__(256) void cross_kernel(const float* __restrict__ rb)
{
    __shared__ float As[64][136];   // rw [k=g][m=ch], pitch%32==8
    __shared__ float Bs[32][72];    // Y  [k][n],      pitch%32==8
    __shared__ float gsum[32], gss[32];
    const int b = blockIdx.y, n0 = blockIdx.x*64, tid = threadIdx.x;
    const int warp = tid >> 5, lane = tid & 31;
    const int grp = lane >> 2, tig = lane & 3;
    const int m_base = (warp >> 1) * 32, n_base = (warp & 1) * 32;

    float acc[2][4][4];
    #pragma unroll
    for (int mt = 0; mt < 2; mt++)
        #pragma unroll
        for (int nt = 0; nt < 4; nt++)
            #pragma unroll
            for (int q = 0; q < 4; q++) acc[mt][nt][q] = 0.f;

    #pragma unroll 4
    for (int idx = tid; idx < 64*128; idx += 256) {
        int k = idx >> 7, m = idx & 127;
        As[k][m] = totf32(g_rwT[idx]);
    }
    if (tid < 32) { gsum[tid] = 0.f; gss[tid] = 0.f; }

    for (int g0 = 0; g0 < 64; g0 += 32) {
        {
            int kk = tid >> 3, n8 = (tid & 7) * 8;
            uint4 yv = *(const uint4*)&g_Yw[((size_t)b*64 + g0 + kk)*SP + n0 + n8];
            *(float2*)&Bs[kk][n8    ] = h2f2(yv.x);
            *(float2*)&Bs[kk][n8 + 2] = h2f2(yv.y);
            *(float2*)&Bs[kk][n8 + 4] = h2f2(yv.z);
            *(float2*)&Bs[kk][n8 + 6] = h2f2(yv.w);
        }
        __syncthreads();
        #pragma unroll
        for (int ks = 0; ks < 4; ks++) {
            unsigned bf[4][2];
            #pragma unroll
            for (int nt = 0; nt < 4; nt++) {
                bf[nt][0] = BITS(Bs[ks*8 + tig    ][n_base + nt*8 + grp]);
                bf[nt][1] = BITS(Bs[ks*8 + tig + 4][n_base + nt*8 + grp]);
            }
            #pragma unroll
            for (int mt = 0; mt < 2; mt++) {
                const int mr = m_base + mt*16 + grp;
                unsigned af[4];
                af[0] = BITS(As[g0 + ks*8 + tig    ][mr]);
                af[1] = BITS(As[g0 + ks*8 + tig    ][mr + 8]);
                af[2] = BITS(As[g0 + ks*8 + tig + 4][mr]);
                af[3] = BITS(As[g0 + ks*8 + tig + 4][mr + 8]);
                #pragma unroll
                for (int nt = 0; nt < 4; nt++) mma_tf32(acc[mt][nt], af, bf[nt]);
            }
        }
        __syncthreads();
    }

    #pragma unroll
    for (int mt = 0; mt < 2; mt++) {
        #pragma unroll
        for (int rr = 0; rr < 2; rr++) {
            const int r = m_base + mt*16 + rr*8 + grp;
            const float bv = rb[r];
            float ps = 0.f, pss = 0.f;
            #pragma unroll
            for (int nt = 0; nt < 4; nt++) {
                const int c = n_base + nt*8 + tig*2;
                float v0 = acc[mt][nt][rr*2 + 0] + bv;
                float v1 = acc[mt][nt][rr*2 + 1] + bv;
                size_t ob = ((size_t)b*Cc + r)*SP + n0 + c;
                *(__half2*)&g_cross[ob] = __floats2half2_rn(v0, v1);
                ps += v0 + v1; pss += v0*v0 + v1*v1;
            }
            ps  += __shfl_xor_sync(0xffffffffu, ps, 1);
            ps  += __shfl_xor_sync(0xffffffffu, ps, 2);
            pss += __shfl_xor_sync(0xffffffffu, pss, 1);
            pss += __shfl_xor_sync(0xffffffffu, pss, 2);
            if (tig == 0) {
                atomicAdd(&gsum[r >> 2], ps);
                atomicAdd(&gss [r >> 2], pss);
            }
        }
    }
    __syncthreads();
    if (tid < 32) {
        atomicAdd(&g_gnsum[b*32 + tid], gsum[tid]);
        atomicAdd(&g_gnss [b*32 + tid], gss[tid]);
    }
}

// ---------------- GroupNorm + residual (streaming, channel-first) ----------
__global__ __launch_bounds__(256) void gnres_kernel(
    int layer, const float* __restrict__ x,
    const float* __restrict__ gnw, const float* __restrict__ gnb,
    int accum_bn)
{
    const float* resid = layer ? (const float*)g_h : x;
    const int c = blockIdx.y, b = blockIdx.z, chunk = blockIdx.x;
    const size_t base = ((size_t)(b*Cc + c))*SP + (size_t)chunk*(SP/4);
    const int g = c >> 2;
    const float invN = 1.0f / (4.0f * SP);
    float mu  = g_gnsum[b*32 + g] * invN;
    float var = g_gnss[b*32 + g] * invN - mu*mu;
    float rstd = rsqrtf(var + 1e-5f);
    float w = gnw[c], bias = gnb[c];
    float s = 0.f, ss = 0.f;
    for (int j = 0; j < 27; j++) {
        size_t o = base + (size_t)j*1024 + threadIdx.x*4;
        uint2 ch = *(const uint2*)&g_cross[o];
        float2 c01 = h2f2(ch.x), c23 = h2f2(ch.y);
        float4 rv = *(const float4*)&resid[o];
        float4 h;
        h.x = rv.x + (c01.x - mu)*rstd*w + bias;
        h.y = rv.y + (c01.y - mu)*rstd*w + bias;
        h.z = rv.z + (c23.x - mu)*rstd*w + bias;
        h.w = rv.w + (c23.y - mu)*rstd*w + bias;
        *(float4*)&g_h[o] = h;
        if (accum_bn) {
            s  += h.x + h.y + h.z + h.w;
            ss += h.x*h.x + h.y*h.y + h.z*h.z + h.w*h.w;
        }
    }
    if (accum_bn) {
        #pragma unroll
        for (int o = 16; o > 0; o >>= 1) {
            s  += __shfl_xor_sync(0xffffffffu, s,  o);
            ss += __shfl_xor_sync(0xffffffffu, ss, o);
        }
        __shared__ float ws[8], wss[8];
        int wid = threadIdx.x >> 5, lane = threadIdx.x & 31;
        if (lane == 0) { ws[wid] = s; wss[wid] = ss; }
        __syncthreads();
        if (threadIdx.x == 0) {
            float ts = 0.f, tss = 0.f;
            #pragma unroll
            for (int k = 0; k < 8; k++) { ts += ws[k]; tss += wss[k]; }
            atomicAdd(&g_bnsum[c], ts);
            atomicAdd(&g_bnss[c],  tss);
        }
    }
}

// ---------------- BatchNorm apply + ReLU ------------------------------------
__global__ __launch_bounds__(256) void bnapply_kernel(
    const float* __restrict__ bw, const float* __restrict__ bb, float* __restrict__ out)
{
    size_t i4 = (size_t)blockIdx.x*256 + threadIdx.x;
    if (i4 >= (size_t)Bb*Cc*SP/4) return;
    size_t i = i4 * 4;
    int c = (int)((i / SP) & 127);
    const float invN = 1.0f / ((float)Bb * SP);
    float mu  = g_bnsum[c] * invN;
    float var = g_bnss[c] * invN - mu*mu;
    float rstd = rsqrtf(var + 1e-5f);
    float wv = bw[c], bv = bb[c];
    float4 v = *(const float4*)&g_h[i];
    v.x = fmaxf((v.x - mu)*rstd*wv + bv, 0.f);
    v.y = fmaxf((v.y - mu)*rstd*wv + bv, 0.f);
    v.z = fmaxf((v.z - mu)*rstd*wv + bv, 0.f);
    v.w = fmaxf((v.w - mu)*rstd*wv + bv, 0.f);
    *(float4*)&out[i] = v;
}

// ---------------- launch -----------------------------------------------------
extern "C" void kernel_launch(void* const* d_in, const int* in_sizes, int n_in,
                              void* d_out, int out_size)
{
    const float* x   = (const float*)d_in[0];
    const float* tw  = (const float*)d_in[1];
    const float* tb  = (const float*)d_in[2];
    const float* pw  = (const float*)d_in[3];
    const float* pb  = (const float*)d_in[4];
    const float* gw  = (const float*)d_in[5];
    const float* gb  = (const float*)d_in[6];
    const float* rw  = (const float*)d_in[7];
    const float* rb  = (const float*)d_in[8];
    const float* gnw = (const float*)d_in[9];
    const float* gnb = (const float*)d_in[10];
    const float* bnw = (const float*)d_in[11];
    const float* bnb = (const float*)d_in[12];
    float* out = (float*)d_out;

    wtrans_kernel<<<96, 256>>>(tw, pw, gw, rw);
    zero_bn<<<1, 128>>>();

    for (int layer = 0; layer < 2; layer++) {
        proj_kernel<<<dim3(SP/64, Bb), 256>>>(layer, x, tb, pb, gb);
        attn_kernel<0><<<Bb*Sd*Sd, 192>>>();
        attn_kernel<1><<<Bb*Sd*Sd, 192>>>();
        attn_kernel<2><<<Bb*Sd*Sd, 192>>>();
        zero_gn<<<1, 64>>>();
        cross_kernel<<<dim3(SP/64, Bb), 256>>>(rb);
        gnres_kernel<<<dim3(4, Cc, Bb), 256>>>(layer, x, gnw + layer*Cc, gnb + layer*Cc,
                                               layer == 1 ? 1 : 0);
    }
    bnapply_kernel<<<((Bb*Cc*SP/4) + 255)/256, 256>>>(bnw, bnb, out);
}

// round 11
// speedup vs baseline: 4.5927x; 1.4968x over previous
#include <cuda_runtime.h>
#include <cuda_fp16.h>

#define Sd 48
#define SP (Sd*Sd*Sd)      // 110592
#define Bb 2
#define Cc 128
#define NVx (Bb*SP)        // 221184

// ---------------- mma / ldmatrix helpers ------------------------------------
__device__ __forceinline__ void mma_f16(float* d, const unsigned* a, const unsigned* b) {
    asm volatile(
        "mma.sync.aligned.m16n8k16.row.col.f32.f16.f16.f32 "
        "{%0,%1,%2,%3},{%4,%5,%6,%7},{%8,%9},{%0,%1,%2,%3};"
        : "+f"(d[0]), "+f"(d[1]), "+f"(d[2]), "+f"(d[3])
        : "r"(a[0]), "r"(a[1]), "r"(a[2]), "r"(a[3]), "r"(b[0]), "r"(b[1]));
}
__device__ __forceinline__ unsigned smaddr(const void* p) {
    unsigned a;
    asm("{ .reg .u64 t; cvta.to.shared.u64 t, %1; cvt.u32.u64 %0, t; }" : "=r"(a) : "l"(p));
    return a;
}
__device__ __forceinline__ void ldsm_x4(unsigned* r, unsigned a) {
    asm volatile("ldmatrix.sync.aligned.m8n8.x4.shared.b16 {%0,%1,%2,%3},[%4];"
        : "=r"(r[0]), "=r"(r[1]), "=r"(r[2]), "=r"(r[3]) : "r"(a));
}
__device__ __forceinline__ void ldsm_x2(unsigned* r, unsigned a) {
    asm volatile("ldmatrix.sync.aligned.m8n8.x2.shared.b16 {%0,%1},[%2];"
        : "=r"(r[0]), "=r"(r[1]) : "r"(a));
}
__device__ __forceinline__ void ldsm_x4_t(unsigned* r, unsigned a) {
    asm volatile("ldmatrix.sync.aligned.m8n8.x4.trans.shared.b16 {%0,%1,%2,%3},[%4];"
        : "=r"(r[0]), "=r"(r[1]), "=r"(r[2]), "=r"(r[3]) : "r"(a));
}
__device__ __forceinline__ float2 h2f2(unsigned u) {
    __half2 h = *reinterpret_cast<__half2*>(&u);
    return __half22float2(h);
}

// ---------------- scratch --------------------------------------------------
__device__ float  g_h[(size_t)Bb*Cc*SP];
__device__ __half g_T[(size_t)NVx*64];
__device__ __half g_P[(size_t)NVx*64];
__device__ __half g_G[(size_t)NVx*64];
__device__ __half g_Yd[(size_t)NVx*64];        // D-dir partial, vox-major
__device__ __half g_Yh[(size_t)NVx*64];        // H-dir partial, vox-major
__device__ __half g_Yw[(size_t)NVx*64];        // final combined Y, g-major
__device__ float g_md[NVx]; __device__ float g_sd[NVx];
__device__ float g_mh[NVx]; __device__ float g_sh[NVx];
__device__ __half g_cross[(size_t)Bb*Cc*SP];   // channel-first, fp16
__device__ __half g_WT16[192*128];             // fused theta/phi/G weights [m][k]
__device__ __half g_rwT16[128*64];             // r_w [m=ch][k=g]
__device__ float g_gnsum[Bb*32]; __device__ float g_gnss[Bb*32];
__device__ float g_bnsum[Cc];    __device__ float g_bnss[Cc];

// ---------------- one-time weight convert (native layouts!) ----------------
__global__ __launch_bounds__(256) void wtrans_kernel(
    const float* __restrict__ tw, const float* __restrict__ pw,
    const float* __restrict__ gw, const float* __restrict__ rw)
{
    int idx = blockIdx.x*256 + threadIdx.x;
    if (idx < 192*128) {
        float v;
        if (idx < 64*128)       v = tw[idx];
        else if (idx < 128*128) v = pw[idx - 64*128];
        else                    v = gw[idx - 128*128];
        g_WT16[idx] = __float2half(v);
    }
    if (idx < 128*64) g_rwT16[idx] = __float2half(rw[idx]);
}

// ---------------- projection (fp16 mma): [192m x 64n] tile, K=128 ----------
// 8 warps: m_base=(warp>>1)*48 (3 x m16), n_base=(warp&1)*32 (4 x n8)
__global__ __launch_bounds__(256) void proj_kernel(
    int layer, const float* __restrict__ x,
    const float* __restrict__ tb, const float* __restrict__ pb,
    const float* __restrict__ gb)
{
    const float* src = layer ? (const float*)g_h : x;
    __shared__ __half As[192*40];   // weights [m][k-chunk], pitch 40
    __shared__ __half Bs[32*72];    // src [k][n], pitch 72
    const int b = blockIdx.y, n0 = blockIdx.x*64, tid = threadIdx.x;
    const int warp = tid >> 5, lane = tid & 31;
    const int grp = lane >> 2, tig = lane & 3;
    const int m_base = (warp >> 1) * 48, n_base = (warp & 1) * 32;

    float acc[3][4][4];
    #pragma unroll
    for (int mt = 0; mt < 3; mt++)
        #pragma unroll
        for (int nt = 0; nt < 4; nt++)
            #pragma unroll
            for (int q = 0; q < 4; q++) acc[mt][nt][q] = 0.f;

    const unsigned Aaddr = smaddr(&As[(m_base + (lane & 15))*40 + (lane >> 4)*8]);
    const unsigned Baddr = smaddr(&Bs[((lane & 7) + ((lane >> 3) & 1)*8)*72
                                      + n_base + (lane >> 4)*8]);

    for (int k0 = 0; k0 < 128; k0 += 32) {
        #pragma unroll
        for (int it = 0; it < 3; it++) {
            int idx = it*256 + tid;           // 0..767
            int m = idx >> 2, kp = (idx & 3)*8;
            *(uint4*)&As[m*40 + kp] = *(const uint4*)&g_WT16[m*128 + k0 + kp];
        }
        {
            int kk = tid >> 3, n8 = (tid & 7)*8;
            const float* s = &src[(size_t)(b*Cc + k0 + kk)*SP + n0 + n8];
            float4 v0 = *(const float4*)s, v1 = *(const float4*)(s + 4);
            __half2 h0 = __floats2half2_rn(v0.x, v0.y);
            __half2 h1 = __floats2half2_rn(v0.z, v0.w);
            __half2 h2 = __floats2half2_rn(v1.x, v1.y);
            __half2 h3 = __floats2half2_rn(v1.z, v1.w);
            uint4 pk;
            pk.x = *(unsigned*)&h0; pk.y = *(unsigned*)&h1;
            pk.z = *(unsigned*)&h2; pk.w = *(unsigned*)&h3;
            *(uint4*)&Bs[kk*72 + n8] = pk;
        }
        __syncthreads();
        #pragma unroll
        for (int kc = 0; kc < 2; kc++) {
            unsigned bv0[4], bv1[4];
            ldsm_x4_t(bv0, Baddr + kc*16*144);
            ldsm_x4_t(bv1, Baddr + kc*16*144 + 32);
            #pragma unroll
            for (int mt = 0; mt < 3; mt++) {
                unsigned af[4];
                ldsm_x4(af, Aaddr + mt*16*80 + kc*32);
                mma_f16(acc[mt][0], af, bv0);
                mma_f16(acc[mt][1], af, bv0 + 2);
                mma_f16(acc[mt][2], af, bv1);
                mma_f16(acc[mt][3], af, bv1 + 2);
            }
        }
        __syncthreads();
    }

    #pragma unroll
    for (int mt = 0; mt < 3; mt++) {
        #pragma unroll
        for (int rr = 0; rr < 2; rr++) {
            const int r = m_base + mt*16 + rr*8 + grp;
            const float* bias; __half* dst; int mm;
            if (r < 64)       { dst = g_T; mm = r;       bias = tb; }
            else if (r < 128) { dst = g_P; mm = r - 64;  bias = pb; }
            else              { dst = g_G; mm = r - 128; bias = gb; }
            const float bv = bias[mm];
            #pragma unroll
            for (int nt = 0; nt < 4; nt++) {
                const int c = n_base + nt*8 + tig*2;
                const size_t v0 = (size_t)b*SP + n0 + c;
                dst[v0*64 + mm]       = __float2half(acc[mt][nt][rr*2 + 0] + bv);
                dst[(v0 + 1)*64 + mm] = __float2half(acc[mt][nt][rr*2 + 1] + bv);
            }
        }
    }
}

// ---------------- pencil attention (fp16 mma + ldmatrix) --------------------
template<int DIR>
__global__ __launch_bounds__(192) void attn_kernel() {
    __shared__ __half Tl[48*72];    // T rows [i][k] -> probs [i][j]
    __shared__ __half Pl[48*72];    // P rows [j][k]
    __shared__ __half Gl[48*72];    // G rows [j][c]
    __shared__ __half Sh[48*72];    // raw scores -> (DIR2) Y staging (fp16)
    __shared__ float  rmS[48], rsS[48];

    const int pid = blockIdx.x;
    const int b = pid / (Sd*Sd);
    const int rr = pid % (Sd*Sd);
    const int u = rr / Sd, v = rr % Sd;
    size_t base; int stride;
    if (DIR == 0)      { base = (size_t)b*SP + u*Sd + v;       stride = Sd*Sd; }
    else if (DIR == 1) { base = (size_t)b*SP + u*Sd*Sd + v;    stride = Sd;    }
    else               { base = (size_t)b*SP + u*Sd*Sd + v*Sd; stride = 1;     }
    const int tid = threadIdx.x;
    const int warp = tid >> 5, lane = tid & 31;
    const int grp = lane >> 2, tig = lane & 3;

    for (int l = tid; l < 48*8; l += 192) {
        int i = l >> 3, k8 = (l & 7) * 8;
        size_t o = (base + (size_t)i*stride)*64 + k8;
        *(uint4*)&Tl[i*72 + k8] = *(const uint4*)&g_T[o];
        *(uint4*)&Pl[i*72 + k8] = *(const uint4*)&g_P[o];
        *(uint4*)&Gl[i*72 + k8] = *(const uint4*)&g_G[o];
    }
    __syncthreads();

    const int mrow0 = (warp >> 1) * 16;
    const int mr = mrow0 + grp;
    const int nhalf = (warp & 1) * 24;
    const int ncol0 = (warp & 1) * 32;

    const unsigned Ta = smaddr(&Tl[(mrow0 + (lane & 15))*72 + (lane >> 4)*8]);
    const unsigned Pa = smaddr(&Pl[(nhalf + (lane & 7))*72 + ((lane >> 3) & 1)*8]);
    const unsigned Ga = smaddr(&Gl[((lane & 7) + ((lane >> 3) & 1)*8)*72
                                   + ncol0 + (lane >> 4)*8]);

    // ---- scores: S[48,48] = T @ P^T ----
    float sacc[3][4];
    #pragma unroll
    for (int nt = 0; nt < 3; nt++)
        #pragma unroll
        for (int q = 0; q < 4; q++) sacc[nt][q] = 0.f;
    #pragma unroll
    for (int kc = 0; kc < 4; kc++) {
        unsigned af[4];
        ldsm_x4(af, Ta + kc*32);
        #pragma unroll
        for (int nt = 0; nt < 3; nt++) {
            unsigned bf[2];
            ldsm_x2(bf, Pa + nt*8*144 + kc*32);
            mma_f16(sacc[nt], af, bf);
        }
    }

    // ---- raw scores (+diag mask) into Sh (fp16) ----
    #pragma unroll
    for (int nt = 0; nt < 3; nt++) {
        const int j0 = nhalf + nt*8 + tig*2;
        float c0 = sacc[nt][0], c1 = sacc[nt][1], c2 = sacc[nt][2], c3 = sacc[nt][3];
        if (DIR != 0) {
            if (mr     == j0    ) c0 = -1e30f;
            if (mr     == j0 + 1) c1 = -1e30f;
            if (mr + 8 == j0    ) c2 = -1e30f;
            if (mr + 8 == j0 + 1) c3 = -1e30f;
        }
        *(__half2*)&Sh[ mr     *72 + j0] = __floats2half2_rn(c0, c1);
        *(__half2*)&Sh[(mr + 8)*72 + j0] = __floats2half2_rn(c2, c3);
    }
    __syncthreads();

    // ---- softmax: 4 threads/row, 12 cols each; probs fp16 into Tl ---------
    {
        const int r = tid >> 2, q = tid & 3;
        float vals[12];
        float mx = -3.0e38f;
        #pragma unroll
        for (int j = 0; j < 12; j += 2) {
            float2 vv = h2f2(*(const unsigned*)&Sh[r*72 + q*12 + j]);
            vals[j] = vv.x; vals[j+1] = vv.y;
            mx = fmaxf(mx, fmaxf(vv.x, vv.y));
        }
        mx = fmaxf(mx, __shfl_xor_sync(0xffffffffu, mx, 1));
        mx = fmaxf(mx, __shfl_xor_sync(0xffffffffu, mx, 2));
        float sm = 0.f;
        #pragma unroll
        for (int j = 0; j < 12; j++) {
            float e = __expf(vals[j] - mx);
            sm += e;
            Tl[r*72 + q*12 + j] = __float2half(e);
        }
        sm += __shfl_xor_sync(0xffffffffu, sm, 1);
        sm += __shfl_xor_sync(0xffffffffu, sm, 2);
        if (DIR == 2) {
            if (q == 0) { rmS[r] = mx; rsS[r] = sm; }
        } else if (q == 0) {
            size_t vx = base + (size_t)r*stride;
            if (DIR == 0) { g_md[vx] = mx; g_sd[vx] = sm; }
            else          { g_mh[vx] = mx; g_sh[vx] = sm; }
        }
    }
    __syncthreads();

    // ---- AV: Y[48,64] = probs @ G ----
    float yacc[4][4];
    #pragma unroll
    for (int nt = 0; nt < 4; nt++)
        #pragma unroll
        for (int q = 0; q < 4; q++) yacc[nt][q] = 0.f;
    #pragma unroll
    for (int kc = 0; kc < 3; kc++) {
        unsigned af[4];
        ldsm_x4(af, Ta + kc*32);
        #pragma unroll
        for (int pair = 0; pair < 2; pair++) {
            unsigned bv[4];
            ldsm_x4_t(bv, Ga + kc*16*144 + pair*32);
            mma_f16(yacc[pair*2],     af, bv);
            mma_f16(yacc[pair*2 + 1], af, bv + 2);
        }
    }

    if (DIR != 2) {
        __half* Yout = (DIR == 0) ? g_Yd : g_Yh;
        #pragma unroll
        for (int nt = 0; nt < 4; nt++) {
            const int c = ncol0 + nt*8 + tig*2;
            *(__half2*)&Yout[(base + (size_t)mr*stride)*64 + c] =
                __floats2half2_rn(yacc[nt][0], yacc[nt][1]);
            *(__half2*)&Yout[(base + (size_t)(mr + 8)*stride)*64 + c] =
                __floats2half2_rn(yacc[nt][2], yacc[nt][3]);
        }
    } else {
        #pragma unroll
        for (int nt = 0; nt < 4; nt++) {
            const int c = ncol0 + nt*8 + tig*2;
            *(__half2*)&Sh[ mr     *72 + c] = __floats2half2_rn(yacc[nt][0], yacc[nt][1]);
            *(__half2*)&Sh[(mr + 8)*72 + c] = __floats2half2_rn(yacc[nt][2], yacc[nt][3]);
        }
        __syncthreads();
        const int i = tid >> 2, q = tid & 3;
        const size_t vox = base + i;
        float md = g_md[vox], sd = g_sd[vox];
        float mh = g_mh[vox], sh = g_sh[vox];
        float mw = rmS[i],    sw = rsS[i];
        float m  = fmaxf(md, fmaxf(mh, mw));
        float wd = __expf(md - m), wh = __expf(mh - m), ww = __expf(mw - m);
        float inv = 1.0f / (sd*wd + sh*wh + sw*ww);
        wd *= inv; wh *= inv; ww *= inv;
        const size_t sp0 = base - (size_t)b*SP;
        #pragma unroll
        for (int jj = 0; jj < 4; jj++) {
            const int g = q*16 + jj*4;
            uint2 au = *(const uint2*)&g_Yd[vox*64 + g];
            uint2 hu = *(const uint2*)&g_Yh[vox*64 + g];
            uint2 yu = *(const uint2*)&Sh[i*72 + g];
            float2 a0 = h2f2(au.x), a1 = h2f2(au.y);
            float2 h0 = h2f2(hu.x), h1 = h2f2(hu.y);
            float2 y0 = h2f2(yu.x), y1 = h2f2(yu.y);
            g_Yw[((size_t)(b*64 + g    ))*SP + sp0 + i] = __float2half(a0.x*wd + h0.x*wh + y0.x*ww);
            g_Yw[((size_t)(b*64 + g + 1))*SP + sp0 + i] = __float2half(a0.y*wd + h0.y*wh + y0.y*ww);
            g_Yw[((size_t)(b*64 + g + 2))*SP + sp0 + i] = __float2half(a1.x*wd + h1.x*wh + y1.x*ww);
            g_Yw[((size_t)(b*64 + g + 3))*SP + sp0 + i] = __float2half(a1.y*wd + h1.y*wh + y1.y*ww);
        }
    }
}

// ---------------- zero stat accumulators ------------------------------------
__global__ void zero_gn() { int t = threadIdx.x; if (t < Bb*32) { g_gnsum[t]=0.f; g_gnss[t]=0.f; } }
__global__ void zero_bn() { int t = threadIdx.x; if (t < Cc)    { g_bnsum[t]=0.f; g_bnss[t]=0.f; } }

// ---------------- cross GEMM (fp16 mma): [128ch x 64vox], K=64 + GN sums ---
__global__ __launch_bounds__(256) void cross_kernel(const float* __restrict__ rb)
{
    __shared__ __half As[128*72];   // rw [m=ch][k=g], pitch 72
    __shared__ __half Bs[32*72];    // Y  [k][n],      pitch 72
    __shared__ float gsum[32], gss[32];
    const int b = blockIdx.y, n0 = blockIdx.x*64, tid = threadIdx.x;
    const int warp = tid >> 5, lane = tid & 31;
    const int grp = lane >> 2, tig = lane & 3;
    const int m_base = (warp >> 1) * 32, n_base = (warp & 1) * 32;

    float acc[2][4][4];
    #pragma unroll
    for (int mt = 0; mt < 2; mt++)
        #pragma unroll
        for (int nt = 0; nt < 4; nt++)
            #pragma unroll
            for (int q = 0; q < 4; q++) acc[mt][nt][q] = 0.f;

    #pragma unroll
    for (int it = 0; it < 4; it++) {
        int idx = it*256 + tid;           // 0..1023
        int m = idx >> 3, kp = (idx & 7)*8;
        *(uint4*)&As[m*72 + kp] = *(const uint4*)&g_rwT16[m*64 + kp];
    }
    if (tid < 32) { gsum[tid] = 0.f; gss[tid] = 0.f; }

    const unsigned Aaddr = smaddr(&As[(m_base + (lane & 15))*72 + (lane >> 4)*8]);
    const unsigned Baddr = smaddr(&Bs[((lane & 7) + ((lane >> 3) & 1)*8)*72
                                      + n_base + (lane >> 4)*8]);

    for (int g0 = 0; g0 < 64; g0 += 32) {
        {
            int kk = tid >> 3, n8 = (tid & 7) * 8;
            *(uint4*)&Bs[kk*72 + n8] =
                *(const uint4*)&g_Yw[((size_t)b*64 + g0 + kk)*SP + n0 + n8];
        }
        __syncthreads();
        #pragma unroll
        for (int kc = 0; kc < 2; kc++) {
            unsigned bv0[4], bv1[4];
            ldsm_x4_t(bv0, Baddr + kc*16*144);
            ldsm_x4_t(bv1, Baddr + kc*16*144 + 32);
            #pragma unroll
            for (int mt = 0; mt < 2; mt++) {
                unsigned af[4];
                ldsm_x4(af, Aaddr + mt*16*144 + g0*2 + kc*32);
                mma_f16(acc[mt][0], af, bv0);
                mma_f16(acc[mt][1], af, bv0 + 2);
                mma_f16(acc[mt][2], af, bv1);
                mma_f16(acc[mt][3], af, bv1 + 2);
            }
        }
        __syncthreads();
    }

    #pragma unroll
    for (int mt = 0; mt < 2; mt++) {
        #pragma unroll
        for (int rr = 0; rr < 2; rr++) {
            const int r = m_base + mt*16 + rr*8 + grp;
            const float bv = rb[r];
            float ps = 0.f, pss = 0.f;
            #pragma unroll
            for (int nt = 0; nt < 4; nt++) {
                const int c = n_base + nt*8 + tig*2;
                float v0 = acc[mt][nt][rr*2 + 0] + bv;
                float v1 = acc[mt][nt][rr*2 + 1] + bv;
                size_t ob = ((size_t)b*Cc + r)*SP + n0 + c;
                *(__half2*)&g_cross[ob] = __floats2half2_rn(v0, v1);
                ps += v0 + v1; pss += v0*v0 + v1*v1;
            }
            ps  += __shfl_xor_sync(0xffffffffu, ps, 1);
            ps  += __shfl_xor_sync(0xffffffffu, ps, 2);
            pss += __shfl_xor_sync(0xffffffffu, pss, 1);
            pss += __shfl_xor_sync(0xffffffffu, pss, 2);
            if (tig == 0) {
                atomicAdd(&gsum[r >> 2], ps);
                atomicAdd(&gss [r >> 2], pss);
            }
        }
    }
    __syncthreads();
    if (tid < 32) {
        atomicAdd(&g_gnsum[b*32 + tid], gsum[tid]);
        atomicAdd(&g_gnss [b*32 + tid], gss[tid]);
    }
}

// ---------------- GroupNorm + residual (streaming, channel-first) ----------
__global__ __launch_bounds__(256) void gnres_kernel(
    int layer, const float* __restrict__ x,
    const float* __restrict__ gnw, const float* __restrict__ gnb,
    int accum_bn)
{
    const float* resid = layer ? (const float*)g_h : x;
    const int c = blockIdx.y, b = blockIdx.z, chunk = blockIdx.x;
    const size_t base = ((size_t)(b*Cc + c))*SP + (size_t)chunk*(SP/4);
    const int g = c >> 2;
    const float invN = 1.0f / (4.0f * SP);
    float mu  = g_gnsum[b*32 + g] * invN;
    float var = g_gnss[b*32 + g] * invN - mu*mu;
    float rstd = rsqrtf(var + 1e-5f);
    float w = gnw[c], bias = gnb[c];
    float s = 0.f, ss = 0.f;
    for (int j = 0; j < 27; j++) {
        size_t o = base + (size_t)j*1024 + threadIdx.x*4;
        uint2 ch = *(const uint2*)&g_cross[o];
        float2 c01 = h2f2(ch.x), c23 = h2f2(ch.y);
        float4 rv = *(const float4*)&resid[o];
        float4 h;
        h.x = rv.x + (c01.x - mu)*rstd*w + bias;
        h.y = rv.y + (c01.y - mu)*rstd*w + bias;
        h.z = rv.z + (c23.x - mu)*rstd*w + bias;
        h.w = rv.w + (c23.y - mu)*rstd*w + bias;
        *(float4*)&g_h[o] = h;
        if (accum_bn) {
            s  += h.x + h.y + h.z + h.w;
            ss += h.x*h.x + h.y*h.y + h.z*h.z + h.w*h.w;
        }
    }
    if (accum_bn) {
        #pragma unroll
        for (int o = 16; o > 0; o >>= 1) {
            s  += __shfl_xor_sync(0xffffffffu, s,  o);
            ss += __shfl_xor_sync(0xffffffffu, ss, o);
        }
        __shared__ float ws[8], wss[8];
        int wid = threadIdx.x >> 5, lane = threadIdx.x & 31;
        if (lane == 0) { ws[wid] = s; wss[wid] = ss; }
        __syncthreads();
        if (threadIdx.x == 0) {
            float ts = 0.f, tss = 0.f;
            #pragma unroll
            for (int k = 0; k < 8; k++) { ts += ws[k]; tss += wss[k]; }
            atomicAdd(&g_bnsum[c], ts);
            atomicAdd(&g_bnss[c],  tss);
        }
    }
}

// ---------------- BatchNorm apply + ReLU ------------------------------------
__global__ __launch_bounds__(256) void bnapply_kernel(
    const float* __restrict__ bw, const float* __restrict__ bb, float* __restrict__ out)
{
    size_t i4 = (size_t)blockIdx.x*256 + threadIdx.x;
    if (i4 >= (size_t)Bb*Cc*SP/4) return;
    size_t i = i4 * 4;
    int c = (int)((i / SP) & 127);
    const float invN = 1.0f / ((float)Bb * SP);
    float mu  = g_bnsum[c] * invN;
    float var = g_bnss[c] * invN - mu*mu;
    float rstd = rsqrtf(var + 1e-5f);
    float wv = bw[c], bv = bb[c];
    float4 v = *(const float4*)&g_h[i];
    v.x = fmaxf((v.x - mu)*rstd*wv + bv, 0.f);
    v.y = fmaxf((v.y - mu)*rstd*wv + bv, 0.f);
    v.z = fmaxf((v.z - mu)*rstd*wv + bv, 0.f);
    v.w = fmaxf((v.w - mu)*rstd*wv + bv, 0.f);
    *(float4*)&out[i] = v;
}

// ---------------- launch -----------------------------------------------------
extern "C" void kernel_launch(void* const* d_in, const int* in_sizes, int n_in,
                              void* d_out, int out_size)
{
    const float* x   = (const float*)d_in[0];
    const float* tw  = (const float*)d_in[1];
    const float* tb  = (const float*)d_in[2];
    const float* pw  = (const float*)d_in[3];
    const float* pb  = (const float*)d_in[4];
    const float* gw  = (const float*)d_in[5];
    const float* gb  = (const float*)d_in[6];
    const float* rw  = (const float*)d_in[7];
    const float* rb  = (const float*)d_in[8];
    const float* gnw = (const float*)d_in[9];
    const float* gnb = (const float*)d_in[10];
    const float* bnw = (const float*)d_in[11];
    const float* bnb = (const float*)d_in[12];
    float* out = (float*)d_out;

    wtrans_kernel<<<96, 256>>>(tw, pw, gw, rw);
    zero_bn<<<1, 128>>>();

    for (int layer = 0; layer < 2; layer++) {
        proj_kernel<<<dim3(SP/64, Bb), 256>>>(layer, x, tb, pb, gb);
        attn_kernel<0><<<Bb*Sd*Sd, 192>>>();
        attn_kernel<1><<<Bb*Sd*Sd, 192>>>();
        attn_kernel<2><<<Bb*Sd*Sd, 192>>>();
        zero_gn<<<1, 64>>>();
        cross_kernel<<<dim3(SP/64, Bb), 256>>>(rb);
        gnres_kernel<<<dim3(4, Cc, Bb), 256>>>(layer, x, gnw + layer*Cc, gnb + layer*Cc,
                                               layer == 1 ? 1 : 0);
    }
    bnapply_kernel<<<((Bb*Cc*SP/4) + 255)/256, 256>>>(bnw, bnb, out);
}

// round 12
// speedup vs baseline: 4.7720x; 1.0390x over previous
#include <cuda_runtime.h>
#include <cuda_fp16.h>

#define Sd 48
#define SP (Sd*Sd*Sd)      // 110592
#define Bb 2
#define Cc 128
#define NVx (Bb*SP)        // 221184

// ---------------- mma / ldmatrix helpers ------------------------------------
__device__ __forceinline__ void mma_f16(float* d, const unsigned* a, const unsigned* b) {
    asm volatile(
        "mma.sync.aligned.m16n8k16.row.col.f32.f16.f16.f32 "
        "{%0,%1,%2,%3},{%4,%5,%6,%7},{%8,%9},{%0,%1,%2,%3};"
        : "+f"(d[0]), "+f"(d[1]), "+f"(d[2]), "+f"(d[3])
        : "r"(a[0]), "r"(a[1]), "r"(a[2]), "r"(a[3]), "r"(b[0]), "r"(b[1]));
}
__device__ __forceinline__ unsigned smaddr(const void* p) {
    unsigned a;
    asm("{ .reg .u64 t; cvta.to.shared.u64 t, %1; cvt.u32.u64 %0, t; }" : "=r"(a) : "l"(p));
    return a;
}
__device__ __forceinline__ void ldsm_x4(unsigned* r, unsigned a) {
    asm volatile("ldmatrix.sync.aligned.m8n8.x4.shared.b16 {%0,%1,%2,%3},[%4];"
        : "=r"(r[0]), "=r"(r[1]), "=r"(r[2]), "=r"(r[3]) : "r"(a));
}
__device__ __forceinline__ void ldsm_x2(unsigned* r, unsigned a) {
    asm volatile("ldmatrix.sync.aligned.m8n8.x2.shared.b16 {%0,%1},[%2];"
        : "=r"(r[0]), "=r"(r[1]) : "r"(a));
}
__device__ __forceinline__ void ldsm_x4_t(unsigned* r, unsigned a) {
    asm volatile("ldmatrix.sync.aligned.m8n8.x4.trans.shared.b16 {%0,%1,%2,%3},[%4];"
        : "=r"(r[0]), "=r"(r[1]), "=r"(r[2]), "=r"(r[3]) : "r"(a));
}
__device__ __forceinline__ float2 h2f2(unsigned u) {
    __half2 h = *reinterpret_cast<__half2*>(&u);
    return __half22float2(h);
}

// ---------------- scratch --------------------------------------------------
__device__ __half g_hh[(size_t)Bb*Cc*SP];      // residual stream h (fp16)
__device__ __half g_T[(size_t)NVx*64];
__device__ __half g_P[(size_t)NVx*64];
__device__ __half g_G[(size_t)NVx*64];
__device__ __half g_Yd[(size_t)NVx*64];        // D-dir partial, vox-major
__device__ __half g_Yh[(size_t)NVx*64];        // H-dir partial, vox-major
__device__ __half g_Yw[(size_t)NVx*64];        // final combined Y, g-major
__device__ float g_md[NVx]; __device__ float g_sd[NVx];
__device__ float g_mh[NVx]; __device__ float g_sh[NVx];
__device__ __half g_cross[(size_t)Bb*Cc*SP];   // channel-first, fp16
__device__ __half g_WT16[192*128];             // fused theta/phi/G weights [m][k]
__device__ __half g_rwT16[128*64];             // r_w [m=ch][k=g]
__device__ float g_gnsum[Bb*32]; __device__ float g_gnss[Bb*32];
__device__ float g_bnsum[Cc];    __device__ float g_bnss[Cc];

// ---------------- one-time weight convert (native layouts) ------------------
__global__ __launch_bounds__(256) void wtrans_kernel(
    const float* __restrict__ tw, const float* __restrict__ pw,
    const float* __restrict__ gw, const float* __restrict__ rw)
{
    int idx = blockIdx.x*256 + threadIdx.x;
    if (idx < 192*128) {
        float v;
        if (idx < 64*128)       v = tw[idx];
        else if (idx < 128*128) v = pw[idx - 64*128];
        else                    v = gw[idx - 128*128];
        g_WT16[idx] = __float2half(v);
    }
    if (idx < 128*64) g_rwT16[idx] = __float2half(rw[idx]);
}

// ---------------- projection (fp16 mma): [192m x 64n] tile, K=128 ----------
__global__ __launch_bounds__(256) void proj_kernel(
    int layer, const float* __restrict__ x,
    const float* __restrict__ tb, const float* __restrict__ pb,
    const float* __restrict__ gb)
{
    __shared__ __half As[192*40];   // weights [m][k-chunk], pitch 40
    __shared__ __half Bs[32*72];    // src [k][n], pitch 72
    const int b = blockIdx.y, n0 = blockIdx.x*64, tid = threadIdx.x;
    const int warp = tid >> 5, lane = tid & 31;
    const int grp = lane >> 2, tig = lane & 3;
    const int m_base = (warp >> 1) * 48, n_base = (warp & 1) * 32;

    float acc[3][4][4];
    #pragma unroll
    for (int mt = 0; mt < 3; mt++)
        #pragma unroll
        for (int nt = 0; nt < 4; nt++)
            #pragma unroll
            for (int q = 0; q < 4; q++) acc[mt][nt][q] = 0.f;

    const unsigned Aaddr = smaddr(&As[(m_base + (lane & 15))*40 + (lane >> 4)*8]);
    const unsigned Baddr = smaddr(&Bs[((lane & 7) + ((lane >> 3) & 1)*8)*72
                                      + n_base + (lane >> 4)*8]);

    for (int k0 = 0; k0 < 128; k0 += 32) {
        #pragma unroll
        for (int it = 0; it < 3; it++) {
            int idx = it*256 + tid;           // 0..767
            int m = idx >> 2, kp = (idx & 3)*8;
            *(uint4*)&As[m*40 + kp] = *(const uint4*)&g_WT16[m*128 + k0 + kp];
        }
        {
            int kk = tid >> 3, n8 = (tid & 7)*8;
            size_t off = (size_t)(b*Cc + k0 + kk)*SP + n0 + n8;
            if (layer) {
                *(uint4*)&Bs[kk*72 + n8] = *(const uint4*)&g_hh[off];
            } else {
                const float* s = &x[off];
                float4 v0 = *(const float4*)s, v1 = *(const float4*)(s + 4);
                __half2 h0 = __floats2half2_rn(v0.x, v0.y);
                __half2 h1 = __floats2half2_rn(v0.z, v0.w);
                __half2 h2 = __floats2half2_rn(v1.x, v1.y);
                __half2 h3 = __floats2half2_rn(v1.z, v1.w);
                uint4 pk;
                pk.x = *(unsigned*)&h0; pk.y = *(unsigned*)&h1;
                pk.z = *(unsigned*)&h2; pk.w = *(unsigned*)&h3;
                *(uint4*)&Bs[kk*72 + n8] = pk;
            }
        }
        __syncthreads();
        #pragma unroll
        for (int kc = 0; kc < 2; kc++) {
            unsigned bv0[4], bv1[4];
            ldsm_x4_t(bv0, Baddr + kc*16*144);
            ldsm_x4_t(bv1, Baddr + kc*16*144 + 32);
            #pragma unroll
            for (int mt = 0; mt < 3; mt++) {
                unsigned af[4];
                ldsm_x4(af, Aaddr + mt*16*80 + kc*32);
                mma_f16(acc[mt][0], af, bv0);
                mma_f16(acc[mt][1], af, bv0 + 2);
                mma_f16(acc[mt][2], af, bv1);
                mma_f16(acc[mt][3], af, bv1 + 2);
            }
        }
        __syncthreads();
    }

    #pragma unroll
    for (int mt = 0; mt < 3; mt++) {
        #pragma unroll
        for (int rr = 0; rr < 2; rr++) {
            const int r = m_base + mt*16 + rr*8 + grp;
            const float* bias; __half* dst; int mm;
            if (r < 64)       { dst = g_T; mm = r;       bias = tb; }
            else if (r < 128) { dst = g_P; mm = r - 64;  bias = pb; }
            else              { dst = g_G; mm = r - 128; bias = gb; }
            const float bv = bias[mm];
            #pragma unroll
            for (int nt = 0; nt < 4; nt++) {
                const int c = n_base + nt*8 + tig*2;
                const size_t v0 = (size_t)b*SP + n0 + c;
                dst[v0*64 + mm]       = __float2half(acc[mt][nt][rr*2 + 0] + bv);
                dst[(v0 + 1)*64 + mm] = __float2half(acc[mt][nt][rr*2 + 1] + bv);
            }
        }
    }
}

// ---------------- pencil attention (fp16 mma + ldmatrix) --------------------
template<int DIR>
__global__ __launch_bounds__(192) void attn_kernel() {
    __shared__ __half Tl[48*72];    // T rows [i][k] -> probs [i][j]
    __shared__ __half Pl[48*72];    // P rows [j][k]
    __shared__ __half Gl[48*72];    // G rows [j][c]
    __shared__ __half Sh[48*72];    // raw scores -> (DIR2) Y staging (fp16)
    __shared__ float  rmS[48], rsS[48];

    const int pid = blockIdx.x;
    const int b = pid / (Sd*Sd);
    const int rr = pid % (Sd*Sd);
    const int u = rr / Sd, v = rr % Sd;
    size_t base; int stride;
    if (DIR == 0)      { base = (size_t)b*SP + u*Sd + v;       stride = Sd*Sd; }
    else if (DIR == 1) { base = (size_t)b*SP + u*Sd*Sd + v;    stride = Sd;    }
    else               { base = (size_t)b*SP + u*Sd*Sd + v*Sd; stride = 1;     }
    const int tid = threadIdx.x;
    const int warp = tid >> 5, lane = tid & 31;
    const int grp = lane >> 2, tig = lane & 3;

    for (int l = tid; l < 48*8; l += 192) {
        int i = l >> 3, k8 = (l & 7) * 8;
        size_t o = (base + (size_t)i*stride)*64 + k8;
        *(uint4*)&Tl[i*72 + k8] = *(const uint4*)&g_T[o];
        *(uint4*)&Pl[i*72 + k8] = *(const uint4*)&g_P[o];
        *(uint4*)&Gl[i*72 + k8] = *(const uint4*)&g_G[o];
    }
    __syncthreads();

    const int mrow0 = (warp >> 1) * 16;
    const int mr = mrow0 + grp;
    const int nhalf = (warp & 1) * 24;
    const int ncol0 = (warp & 1) * 32;

    const unsigned Ta = smaddr(&Tl[(mrow0 + (lane & 15))*72 + (lane >> 4)*8]);
    const unsigned Pa = smaddr(&Pl[(nhalf + (lane & 7))*72 + ((lane >> 3) & 1)*8]);
    const unsigned Ga = smaddr(&Gl[((lane & 7) + ((lane >> 3) & 1)*8)*72
                                   + ncol0 + (lane >> 4)*8]);

    // ---- scores: S[48,48] = T @ P^T ----
    float sacc[3][4];
    #pragma unroll
    for (int nt = 0; nt < 3; nt++)
        #pragma unroll
        for (int q = 0; q < 4; q++) sacc[nt][q] = 0.f;
    #pragma unroll
    for (int kc = 0; kc < 4; kc++) {
        unsigned af[4];
        ldsm_x4(af, Ta + kc*32);
        #pragma unroll
        for (int nt = 0; nt < 3; nt++) {
            unsigned bf[2];
            ldsm_x2(bf, Pa + nt*8*144 + kc*32);
            mma_f16(sacc[nt], af, bf);
        }
    }

    // ---- raw scores (+diag mask) into Sh (fp16) ----
    #pragma unroll
    for (int nt = 0; nt < 3; nt++) {
        const int j0 = nhalf + nt*8 + tig*2;
        float c0 = sacc[nt][0], c1 = sacc[nt][1], c2 = sacc[nt][2], c3 = sacc[nt][3];
        if (DIR != 0) {
            if (mr     == j0    ) c0 = -1e30f;
            if (mr     == j0 + 1) c1 = -1e30f;
            if (mr + 8 == j0    ) c2 = -1e30f;
            if (mr + 8 == j0 + 1) c3 = -1e30f;
        }
        *(__half2*)&Sh[ mr     *72 + j0] = __floats2half2_rn(c0, c1);
        *(__half2*)&Sh[(mr + 8)*72 + j0] = __floats2half2_rn(c2, c3);
    }
    __syncthreads();

    // ---- softmax: 4 threads/row, 12 cols each; probs fp16 into Tl ---------
    {
        const int r = tid >> 2, q = tid & 3;
        float vals[12];
        float mx = -3.0e38f;
        #pragma unroll
        for (int j = 0; j < 12; j += 2) {
            float2 vv = h2f2(*(const unsigned*)&Sh[r*72 + q*12 + j]);
            vals[j] = vv.x; vals[j+1] = vv.y;
            mx = fmaxf(mx, fmaxf(vv.x, vv.y));
        }
        mx = fmaxf(mx, __shfl_xor_sync(0xffffffffu, mx, 1));
        mx = fmaxf(mx, __shfl_xor_sync(0xffffffffu, mx, 2));
        float sm = 0.f;
        #pragma unroll
        for (int j = 0; j < 12; j++) {
            float e = __expf(vals[j] - mx);
            sm += e;
            Tl[r*72 + q*12 + j] = __float2half(e);
        }
        sm += __shfl_xor_sync(0xffffffffu, sm, 1);
        sm += __shfl_xor_sync(0xffffffffu, sm, 2);
        if (DIR == 2) {
            if (q == 0) { rmS[r] = mx; rsS[r] = sm; }
        } else if (q == 0) {
            size_t vx = base + (size_t)r*stride;
            if (DIR == 0) { g_md[vx] = mx; g_sd[vx] = sm; }
            else          { g_mh[vx] = mx; g_sh[vx] = sm; }
        }
    }
    __syncthreads();

    // ---- AV: Y[48,64] = probs @ G ----
    float yacc[4][4];
    #pragma unroll
    for (int nt = 0; nt < 4; nt++)
        #pragma unroll
        for (int q = 0; q < 4; q++) yacc[nt][q] = 0.f;
    #pragma unroll
    for (int kc = 0; kc < 3; kc++) {
        unsigned af[4];
        ldsm_x4(af, Ta + kc*32);
        #pragma unroll
        for (int pair = 0; pair < 2; pair++) {
            unsigned bv[4];
            ldsm_x4_t(bv, Ga + kc*16*144 + pair*32);
            mma_f16(yacc[pair*2],     af, bv);
            mma_f16(yacc[pair*2 + 1], af, bv + 2);
        }
    }

    if (DIR != 2) {
        __half* Yout = (DIR == 0) ? g_Yd : g_Yh;
        #pragma unroll
        for (int nt = 0; nt < 4; nt++) {
            const int c = ncol0 + nt*8 + tig*2;
            *(__half2*)&Yout[(base + (size_t)mr*stride)*64 + c] =
                __floats2half2_rn(yacc[nt][0], yacc[nt][1]);
            *(__half2*)&Yout[(base + (size_t)(mr + 8)*stride)*64 + c] =
                __floats2half2_rn(yacc[nt][2], yacc[nt][3]);
        }
    } else {
        #pragma unroll
        for (int nt = 0; nt < 4; nt++) {
            const int c = ncol0 + nt*8 + tig*2;
            *(__half2*)&Sh[ mr     *72 + c] = __floats2half2_rn(yacc[nt][0], yacc[nt][1]);
            *(__half2*)&Sh[(mr + 8)*72 + c] = __floats2half2_rn(yacc[nt][2], yacc[nt][3]);
        }
        __syncthreads();
        const int i = tid >> 2, q = tid & 3;
        const size_t vox = base + i;
        float md = g_md[vox], sd = g_sd[vox];
        float mh = g_mh[vox], sh = g_sh[vox];
        float mw = rmS[i],    sw = rsS[i];
        float m  = fmaxf(md, fmaxf(mh, mw));
        float wd = __expf(md - m), wh = __expf(mh - m), ww = __expf(mw - m);
        float inv = 1.0f / (sd*wd + sh*wh + sw*ww);
        wd *= inv; wh *= inv; ww *= inv;
        const size_t sp0 = base - (size_t)b*SP;
        #pragma unroll
        for (int jj = 0; jj < 4; jj++) {
            const int g = q*16 + jj*4;
            uint2 au = *(const uint2*)&g_Yd[vox*64 + g];
            uint2 hu = *(const uint2*)&g_Yh[vox*64 + g];
            uint2 yu = *(const uint2*)&Sh[i*72 + g];
            float2 a0 = h2f2(au.x), a1 = h2f2(au.y);
            float2 h0 = h2f2(hu.x), h1 = h2f2(hu.y);
            float2 y0 = h2f2(yu.x), y1 = h2f2(yu.y);
            g_Yw[((size_t)(b*64 + g    ))*SP + sp0 + i] = __float2half(a0.x*wd + h0.x*wh + y0.x*ww);
            g_Yw[((size_t)(b*64 + g + 1))*SP + sp0 + i] = __float2half(a0.y*wd + h0.y*wh + y0.y*ww);
            g_Yw[((size_t)(b*64 + g + 2))*SP + sp0 + i] = __float2half(a1.x*wd + h1.x*wh + y1.x*ww);
            g_Yw[((size_t)(b*64 + g + 3))*SP + sp0 + i] = __float2half(a1.y*wd + h1.y*wh + y1.y*ww);
        }
    }
}

// ---------------- zero stat accumulators ------------------------------------
__global__ void zero_gn() { int t = threadIdx.x; if (t < Bb*32) { g_gnsum[t]=0.f; g_gnss[t]=0.f; } }
__global__ void zero_bn() { int t = threadIdx.x; if (t < Cc)    { g_bnsum[t]=0.f; g_bnss[t]=0.f; } }

// ---------------- cross GEMM (fp16 mma): [128ch x 64vox], K=64 + GN sums ---
__global__ __launch_bounds__(256) void cross_kernel(const float* __restrict__ rb)
{
    __shared__ __half As[128*72];   // rw [m=ch][k=g], pitch 72
    __shared__ __half Bs[32*72];    // Y  [k][n],      pitch 72
    __shared__ float gsum[32], gss[32];
    const int b = blockIdx.y, n0 = blockIdx.x*64, tid = threadIdx.x;
    const int warp = tid >> 5, lane = tid & 31;
    const int grp = lane >> 2, tig = lane & 3;
    const int m_base = (warp >> 1) * 32, n_base = (warp & 1) * 32;

    float acc[2][4][4];
    #pragma unroll
    for (int mt = 0; mt < 2; mt++)
        #pragma unroll
        for (int nt = 0; nt < 4; nt++)
            #pragma unroll
            for (int q = 0; q < 4; q++) acc[mt][nt][q] = 0.f;

    #pragma unroll
    for (int it = 0; it < 4; it++) {
        int idx = it*256 + tid;
        int m = idx >> 3, kp = (idx & 7)*8;
        *(uint4*)&As[m*72 + kp] = *(const uint4*)&g_rwT16[m*64 + kp];
    }
    if (tid < 32) { gsum[tid] = 0.f; gss[tid] = 0.f; }

    const unsigned Aaddr = smaddr(&As[(m_base + (lane & 15))*72 + (lane >> 4)*8]);
    const unsigned Baddr = smaddr(&Bs[((lane & 7) + ((lane >> 3) & 1)*8)*72
                                      + n_base + (lane >> 4)*8]);

    for (int g0 = 0; g0 < 64; g0 += 32) {
        {
            int kk = tid >> 3, n8 = (tid & 7) * 8;
            *(uint4*)&Bs[kk*72 + n8] =
                *(const uint4*)&g_Yw[((size_t)b*64 + g0 + kk)*SP + n0 + n8];
        }
        __syncthreads();
        #pragma unroll
        for (int kc = 0; kc < 2; kc++) {
            unsigned bv0[4], bv1[4];
            ldsm_x4_t(bv0, Baddr + kc*16*144);
            ldsm_x4_t(bv1, Baddr + kc*16*144 + 32);
            #pragma unroll
            for (int mt = 0; mt < 2; mt++) {
                unsigned af[4];
                ldsm_x4(af, Aaddr + mt*16*144 + g0*2 + kc*32);
                mma_f16(acc[mt][0], af, bv0);
                mma_f16(acc[mt][1], af, bv0 + 2);
                mma_f16(acc[mt][2], af, bv1);
                mma_f16(acc[mt][3], af, bv1 + 2);
            }
        }
        __syncthreads();
    }

    #pragma unroll
    for (int mt = 0; mt < 2; mt++) {
        #pragma unroll
        for (int rr = 0; rr < 2; rr++) {
            const int r = m_base + mt*16 + rr*8 + grp;
            const float bv = rb[r];
            float ps = 0.f, pss = 0.f;
            #pragma unroll
            for (int nt = 0; nt < 4; nt++) {
                const int c = n_base + nt*8 + tig*2;
                float v0 = acc[mt][nt][rr*2 + 0] + bv;
                float v1 = acc[mt][nt][rr*2 + 1] + bv;
                size_t ob = ((size_t)b*Cc + r)*SP + n0 + c;
                *(__half2*)&g_cross[ob] = __floats2half2_rn(v0, v1);
                ps += v0 + v1; pss += v0*v0 + v1*v1;
            }
            ps  += __shfl_xor_sync(0xffffffffu, ps, 1);
            ps  += __shfl_xor_sync(0xffffffffu, ps, 2);
            pss += __shfl_xor_sync(0xffffffffu, pss, 1);
            pss += __shfl_xor_sync(0xffffffffu, pss, 2);
            if (tig == 0) {
                atomicAdd(&gsum[r >> 2], ps);
                atomicAdd(&gss [r >> 2], pss);
            }
        }
    }
    __syncthreads();
    if (tid < 32) {
        atomicAdd(&g_gnsum[b*32 + tid], gsum[tid]);
        atomicAdd(&g_gnss [b*32 + tid], gss[tid]);
    }
}

// ---------------- GroupNorm + residual (streaming, channel-first) ----------
// writes h as fp16; resid = x (fp32, layer 0) or g_hh (fp16, layer 1)
__global__ __launch_bounds__(256) void gnres_kernel(
    int layer, const float* __restrict__ x,
    const float* __restrict__ gnw, const float* __restrict__ gnb,
    int accum_bn)
{
    const int c = blockIdx.y, b = blockIdx.z, chunk = blockIdx.x;
    const size_t base = ((size_t)(b*Cc + c))*SP + (size_t)chunk*(SP/4);
    const int g = c >> 2;
    const float invN = 1.0f / (4.0f * SP);
    float mu  = g_gnsum[b*32 + g] * invN;
    float var = g_gnss[b*32 + g] * invN - mu*mu;
    float rstd = rsqrtf(var + 1e-5f);
    float w = gnw[c], bias = gnb[c];
    float s = 0.f, ss = 0.f;
    for (int j = 0; j < 27; j++) {
        size_t o = base + (size_t)j*1024 + threadIdx.x*4;
        uint2 ch = *(const uint2*)&g_cross[o];
        float2 c01 = h2f2(ch.x), c23 = h2f2(ch.y);
        float4 rv;
        if (layer) {
            uint2 hv = *(const uint2*)&g_hh[o];
            float2 r01 = h2f2(hv.x), r23 = h2f2(hv.y);
            rv.x = r01.x; rv.y = r01.y; rv.z = r23.x; rv.w = r23.y;
        } else {
            rv = *(const float4*)&x[o];
        }
        float4 h;
        h.x = rv.x + (c01.x - mu)*rstd*w + bias;
        h.y = rv.y + (c01.y - mu)*rstd*w + bias;
        h.z = rv.z + (c23.x - mu)*rstd*w + bias;
        h.w = rv.w + (c23.y - mu)*rstd*w + bias;
        uint2 hw;
        __half2 w0 = __floats2half2_rn(h.x, h.y);
        __half2 w1 = __floats2half2_rn(h.z, h.w);
        hw.x = *(unsigned*)&w0; hw.y = *(unsigned*)&w1;
        *(uint2*)&g_hh[o] = hw;
        if (accum_bn) {
            s  += h.x + h.y + h.z + h.w;
            ss += h.x*h.x + h.y*h.y + h.z*h.z + h.w*h.w;
        }
    }
    if (accum_bn) {
        #pragma unroll
        for (int o = 16; o > 0; o >>= 1) {
            s  += __shfl_xor_sync(0xffffffffu, s,  o);
            ss += __shfl_xor_sync(0xffffffffu, ss, o);
        }
        __shared__ float ws[8], wss[8];
        int wid = threadIdx.x >> 5, lane = threadIdx.x & 31;
        if (lane == 0) { ws[wid] = s; wss[wid] = ss; }
        __syncthreads();
        if (threadIdx.x == 0) {
            float ts = 0.f, tss = 0.f;
            #pragma unroll
            for (int k = 0; k < 8; k++) { ts += ws[k]; tss += wss[k]; }
            atomicAdd(&g_bnsum[c], ts);
            atomicAdd(&g_bnss[c],  tss);
        }
    }
}

// ---------------- BatchNorm apply + ReLU ------------------------------------
__global__ __launch_bounds__(256) void bnapply_kernel(
    const float* __restrict__ bw, const float* __restrict__ bb, float* __restrict__ out)
{
    size_t i4 = (size_t)blockIdx.x*256 + threadIdx.x;
    if (i4 >= (size_t)Bb*Cc*SP/4) return;
    size_t i = i4 * 4;
    int c = (int)((i / SP) & 127);
    const float invN = 1.0f / ((float)Bb * SP);
    float mu  = g_bnsum[c] * invN;
    float var = g_bnss[c] * invN - mu*mu;
    float rstd = rsqrtf(var + 1e-5f);
    float wv = bw[c], bv = bb[c];
    uint2 hv = *(const uint2*)&g_hh[i];
    float2 v01 = h2f2(hv.x), v23 = h2f2(hv.y);
    float4 v;
    v.x = fmaxf((v01.x - mu)*rstd*wv + bv, 0.f);
    v.y = fmaxf((v01.y - mu)*rstd*wv + bv, 0.f);
    v.z = fmaxf((v23.x - mu)*rstd*wv + bv, 0.f);
    v.w = fmaxf((v23.y - mu)*rstd*wv + bv, 0.f);
    *(float4*)&out[i] = v;
}

// ---------------- launch -----------------------------------------------------
extern "C" void kernel_launch(void* const* d_in, const int* in_sizes, int n_in,
                              void* d_out, int out_size)
{
    const float* x   = (const float*)d_in[0];
    const float* tw  = (const float*)d_in[1];
    const float* tb  = (const float*)d_in[2];
    const float* pw  = (const float*)d_in[3];
    const float* pb  = (const float*)d_in[4];
    const float* gw  = (const float*)d_in[5];
    const float* gb  = (const float*)d_in[6];
    const float* rw  = (const float*)d_in[7];
    const float* rb  = (const float*)d_in[8];
    const float* gnw = (const float*)d_in[9];
    const float* gnb = (const float*)d_in[10];
    const float* bnw = (const float*)d_in[11];
    const float* bnb = (const float*)d_in[12];
    float* out = (float*)d_out;

    wtrans_kernel<<<96, 256>>>(tw, pw, gw, rw);
    zero_bn<<<1, 128>>>();

    for (int layer = 0; layer < 2; layer++) {
        proj_kernel<<<dim3(SP/64, Bb), 256>>>(layer, x, tb, pb, gb);
        attn_kernel<0><<<Bb*Sd*Sd, 192>>>();
        attn_kernel<1><<<Bb*Sd*Sd, 192>>>();
        attn_kernel<2><<<Bb*Sd*Sd, 192>>>();
        zero_gn<<<1, 64>>>();
        cross_kernel<<<dim3(SP/64, Bb), 256>>>(rb);
        gnres_kernel<<<dim3(4, Cc, Bb), 256>>>(layer, x, gnw + layer*Cc, gnb + layer*Cc,
                                               layer == 1 ? 1 : 0);
    }
    bnapply_kernel<<<((Bb*Cc*SP/4) + 255)/256, 256>>>(bnw, bnb, out);
}

// round 13
// speedup vs baseline: 4.9669x; 1.0408x over previous
#include <cuda_runtime.h>
#include <cuda_fp16.h>

#define Sd 48
#define SP (Sd*Sd*Sd)      // 110592
#define Bb 2
#define Cc 128
#define NVx (Bb*SP)        // 221184

// ---------------- mma / ldmatrix helpers ------------------------------------
__device__ __forceinline__ void mma_f16(float* d, const unsigned* a, const unsigned* b) {
    asm volatile(
        "mma.sync.aligned.m16n8k16.row.col.f32.f16.f16.f32 "
        "{%0,%1,%2,%3},{%4,%5,%6,%7},{%8,%9},{%0,%1,%2,%3};"
        : "+f"(d[0]), "+f"(d[1]), "+f"(d[2]), "+f"(d[3])
        : "r"(a[0]), "r"(a[1]), "r"(a[2]), "r"(a[3]), "r"(b[0]), "r"(b[1]));
}
__device__ __forceinline__ unsigned smaddr(const void* p) {
    unsigned a;
    asm("{ .reg .u64 t; cvta.to.shared.u64 t, %1; cvt.u32.u64 %0, t; }" : "=r"(a) : "l"(p));
    return a;
}
__device__ __forceinline__ void ldsm_x4(unsigned* r, unsigned a) {
    asm volatile("ldmatrix.sync.aligned.m8n8.x4.shared.b16 {%0,%1,%2,%3},[%4];"
        : "=r"(r[0]), "=r"(r[1]), "=r"(r[2]), "=r"(r[3]) : "r"(a));
}
__device__ __forceinline__ void ldsm_x2(unsigned* r, unsigned a) {
    asm volatile("ldmatrix.sync.aligned.m8n8.x2.shared.b16 {%0,%1},[%2];"
        : "=r"(r[0]), "=r"(r[1]) : "r"(a));
}
__device__ __forceinline__ void ldsm_x4_t(unsigned* r, unsigned a) {
    asm volatile("ldmatrix.sync.aligned.m8n8.x4.trans.shared.b16 {%0,%1,%2,%3},[%4];"
        : "=r"(r[0]), "=r"(r[1]), "=r"(r[2]), "=r"(r[3]) : "r"(a));
}
__device__ __forceinline__ float2 h2f2(unsigned u) {
    __half2 h = *reinterpret_cast<__half2*>(&u);
    return __half22float2(h);
}

// ---------------- scratch --------------------------------------------------
__device__ __half g_hh[(size_t)Bb*Cc*SP];      // residual stream h (fp16)
__device__ __half g_T[(size_t)NVx*64];
__device__ __half g_P[(size_t)NVx*64];
__device__ __half g_G[(size_t)NVx*64];
__device__ __half g_Yd[(size_t)NVx*64];        // D-dir partial, vox-major
__device__ __half g_Yh[(size_t)NVx*64];        // H-dir partial, vox-major
__device__ __half g_Yw[(size_t)NVx*64];        // final combined Y, g-major
__device__ float g_md[NVx]; __device__ float g_sd[NVx];
__device__ float g_mh[NVx]; __device__ float g_sh[NVx];
__device__ __half g_cross[(size_t)Bb*Cc*SP];   // channel-first, fp16
__device__ __half g_WT16[192*128];             // fused theta/phi/G weights [m][k]
__device__ __half g_rwT16[128*64];             // r_w [m=ch][k=g]
__device__ float g_gnsum[Bb*32]; __device__ float g_gnss[Bb*32];
__device__ float g_bnsum[Cc];    __device__ float g_bnss[Cc];

// ---------------- one-time weight convert + BN-stat zero --------------------
__global__ __launch_bounds__(256) void wtrans_kernel(
    const float* __restrict__ tw, const float* __restrict__ pw,
    const float* __restrict__ gw, const float* __restrict__ rw)
{
    int idx = blockIdx.x*256 + threadIdx.x;
    if (idx < 192*128) {
        float v;
        if (idx < 64*128)       v = tw[idx];
        else if (idx < 128*128) v = pw[idx - 64*128];
        else                    v = gw[idx - 128*128];
        g_WT16[idx] = __float2half(v);
    }
    if (idx < 128*64) g_rwT16[idx] = __float2half(rw[idx]);
    if (idx < Cc) { g_bnsum[idx] = 0.f; g_bnss[idx] = 0.f; }
}

// ---------------- projection (fp16 mma): [192m x 64n] tile, K=128 ----------
// block (0,0) also zeroes GN stats for this layer (consumed later by cross).
__global__ __launch_bounds__(256) void proj_kernel(
    int layer, const float* __restrict__ x,
    const float* __restrict__ tb, const float* __restrict__ pb,
    const float* __restrict__ gb)
{
    __shared__ __half As[192*40];   // weights [m][k-chunk], pitch 40
    __shared__ __half Bs[32*72];    // src [k][n], pitch 72
    const int b = blockIdx.y, n0 = blockIdx.x*64, tid = threadIdx.x;
    if (blockIdx.x == 0 && blockIdx.y == 0 && tid < Bb*32) {
        g_gnsum[tid] = 0.f; g_gnss[tid] = 0.f;
    }
    const int warp = tid >> 5, lane = tid & 31;
    const int grp = lane >> 2, tig = lane & 3;
    const int m_base = (warp >> 1) * 48, n_base = (warp & 1) * 32;

    float acc[3][4][4];
    #pragma unroll
    for (int mt = 0; mt < 3; mt++)
        #pragma unroll
        for (int nt = 0; nt < 4; nt++)
            #pragma unroll
            for (int q = 0; q < 4; q++) acc[mt][nt][q] = 0.f;

    const unsigned Aaddr = smaddr(&As[(m_base + (lane & 15))*40 + (lane >> 4)*8]);
    const unsigned Baddr = smaddr(&Bs[((lane & 7) + ((lane >> 3) & 1)*8)*72
                                      + n_base + (lane >> 4)*8]);

    for (int k0 = 0; k0 < 128; k0 += 32) {
        #pragma unroll
        for (int it = 0; it < 3; it++) {
            int idx = it*256 + tid;           // 0..767
            int m = idx >> 2, kp = (idx & 3)*8;
            *(uint4*)&As[m*40 + kp] = *(const uint4*)&g_WT16[m*128 + k0 + kp];
        }
        {
            int kk = tid >> 3, n8 = (tid & 7)*8;
            size_t off = (size_t)(b*Cc + k0 + kk)*SP + n0 + n8;
            if (layer) {
                *(uint4*)&Bs[kk*72 + n8] = *(const uint4*)&g_hh[off];
            } else {
                const float* s = &x[off];
                float4 v0 = *(const float4*)s, v1 = *(const float4*)(s + 4);
                __half2 h0 = __floats2half2_rn(v0.x, v0.y);
                __half2 h1 = __floats2half2_rn(v0.z, v0.w);
                __half2 h2 = __floats2half2_rn(v1.x, v1.y);
                __half2 h3 = __floats2half2_rn(v1.z, v1.w);
                uint4 pk;
                pk.x = *(unsigned*)&h0; pk.y = *(unsigned*)&h1;
                pk.z = *(unsigned*)&h2; pk.w = *(unsigned*)&h3;
                *(uint4*)&Bs[kk*72 + n8] = pk;
            }
        }
        __syncthreads();
        #pragma unroll
        for (int kc = 0; kc < 2; kc++) {
            unsigned bv0[4], bv1[4];
            ldsm_x4_t(bv0, Baddr + kc*16*144);
            ldsm_x4_t(bv1, Baddr + kc*16*144 + 32);
            #pragma unroll
            for (int mt = 0; mt < 3; mt++) {
                unsigned af[4];
                ldsm_x4(af, Aaddr + mt*16*80 + kc*32);
                mma_f16(acc[mt][0], af, bv0);
                mma_f16(acc[mt][1], af, bv0 + 2);
                mma_f16(acc[mt][2], af, bv1);
                mma_f16(acc[mt][3], af, bv1 + 2);
            }
        }
        __syncthreads();
    }

    #pragma unroll
    for (int mt = 0; mt < 3; mt++) {
        #pragma unroll
        for (int rr = 0; rr < 2; rr++) {
            const int r = m_base + mt*16 + rr*8 + grp;
            const float* bias; __half* dst; int mm;
            if (r < 64)       { dst = g_T; mm = r;       bias = tb; }
            else if (r < 128) { dst = g_P; mm = r - 64;  bias = pb; }
            else              { dst = g_G; mm = r - 128; bias = gb; }
            const float bv = bias[mm];
            #pragma unroll
            for (int nt = 0; nt < 4; nt++) {
                const int c = n_base + nt*8 + tig*2;
                const size_t v0 = (size_t)b*SP + n0 + c;
                dst[v0*64 + mm]       = __float2half(acc[mt][nt][rr*2 + 0] + bv);
                dst[(v0 + 1)*64 + mm] = __float2half(acc[mt][nt][rr*2 + 1] + bv);
            }
        }
    }
}

// ---------------- merged D/H attention (blockIdx.y = direction 0/1) --------
__global__ __launch_bounds__(192) void attn01_kernel() {
    __shared__ __half Tl[48*72];    // T rows [i][k] -> probs [i][j]
    __shared__ __half Pl[48*72];    // P rows [j][k]
    __shared__ __half Gl[48*72];    // G rows [j][c]
    __shared__ __half Sh[48*72];    // raw scores (fp16)

    const int DIR = blockIdx.y;     // 0: D-axis (no mask), 1: H-axis (mask)
    const int pid = blockIdx.x;
    const int b = pid / (Sd*Sd);
    const int rr = pid % (Sd*Sd);
    const int u = rr / Sd, v = rr % Sd;
    size_t base; int stride;
    if (DIR == 0) { base = (size_t)b*SP + u*Sd + v;    stride = Sd*Sd; }
    else          { base = (size_t)b*SP + u*Sd*Sd + v; stride = Sd;    }
    const int tid = threadIdx.x;
    const int warp = tid >> 5, lane = tid & 31;
    const int grp = lane >> 2, tig = lane & 3;

    for (int l = tid; l < 48*8; l += 192) {
        int i = l >> 3, k8 = (l & 7) * 8;
        size_t o = (base + (size_t)i*stride)*64 + k8;
        *(uint4*)&Tl[i*72 + k8] = *(const uint4*)&g_T[o];
        *(uint4*)&Pl[i*72 + k8] = *(const uint4*)&g_P[o];
        *(uint4*)&Gl[i*72 + k8] = *(const uint4*)&g_G[o];
    }
    __syncthreads();

    const int mrow0 = (warp >> 1) * 16;
    const int mr = mrow0 + grp;
    const int nhalf = (warp & 1) * 24;
    const int ncol0 = (warp & 1) * 32;

    const unsigned Ta = smaddr(&Tl[(mrow0 + (lane & 15))*72 + (lane >> 4)*8]);
    const unsigned Pa = smaddr(&Pl[(nhalf + (lane & 7))*72 + ((lane >> 3) & 1)*8]);
    const unsigned Ga = smaddr(&Gl[((lane & 7) + ((lane >> 3) & 1)*8)*72
                                   + ncol0 + (lane >> 4)*8]);

    float sacc[3][4];
    #pragma unroll
    for (int nt = 0; nt < 3; nt++)
        #pragma unroll
        for (int q = 0; q < 4; q++) sacc[nt][q] = 0.f;
    #pragma unroll
    for (int kc = 0; kc < 4; kc++) {
        unsigned af[4];
        ldsm_x4(af, Ta + kc*32);
        #pragma unroll
        for (int nt = 0; nt < 3; nt++) {
            unsigned bf[2];
            ldsm_x2(bf, Pa + nt*8*144 + kc*32);
            mma_f16(sacc[nt], af, bf);
        }
    }

    #pragma unroll
    for (int nt = 0; nt < 3; nt++) {
        const int j0 = nhalf + nt*8 + tig*2;
        float c0 = sacc[nt][0], c1 = sacc[nt][1], c2 = sacc[nt][2], c3 = sacc[nt][3];
        if (DIR != 0) {
            if (mr     == j0    ) c0 = -1e30f;
            if (mr     == j0 + 1) c1 = -1e30f;
            if (mr + 8 == j0    ) c2 = -1e30f;
            if (mr + 8 == j0 + 1) c3 = -1e30f;
        }
        *(__half2*)&Sh[ mr     *72 + j0] = __floats2half2_rn(c0, c1);
        *(__half2*)&Sh[(mr + 8)*72 + j0] = __floats2half2_rn(c2, c3);
    }
    __syncthreads();

    {
        const int r = tid >> 2, q = tid & 3;
        float vals[12];
        float mx = -3.0e38f;
        #pragma unroll
        for (int j = 0; j < 12; j += 2) {
            float2 vv = h2f2(*(const unsigned*)&Sh[r*72 + q*12 + j]);
            vals[j] = vv.x; vals[j+1] = vv.y;
            mx = fmaxf(mx, fmaxf(vv.x, vv.y));
        }
        mx = fmaxf(mx, __shfl_xor_sync(0xffffffffu, mx, 1));
        mx = fmaxf(mx, __shfl_xor_sync(0xffffffffu, mx, 2));
        float sm = 0.f;
        #pragma unroll
        for (int j = 0; j < 12; j++) {
            float e = __expf(vals[j] - mx);
            sm += e;
            Tl[r*72 + q*12 + j] = __float2half(e);
        }
        sm += __shfl_xor_sync(0xffffffffu, sm, 1);
        sm += __shfl_xor_sync(0xffffffffu, sm, 2);
        if (q == 0) {
            size_t vx = base + (size_t)r*stride;
            if (DIR == 0) { g_md[vx] = mx; g_sd[vx] = sm; }
            else          { g_mh[vx] = mx; g_sh[vx] = sm; }
        }
    }
    __syncthreads();

    float yacc[4][4];
    #pragma unroll
    for (int nt = 0; nt < 4; nt++)
        #pragma unroll
        for (int q = 0; q < 4; q++) yacc[nt][q] = 0.f;
    #pragma unroll
    for (int kc = 0; kc < 3; kc++) {
        unsigned af[4];
        ldsm_x4(af, Ta + kc*32);
        #pragma unroll
        for (int pair = 0; pair < 2; pair++) {
            unsigned bv[4];
            ldsm_x4_t(bv, Ga + kc*16*144 + pair*32);
            mma_f16(yacc[pair*2],     af, bv);
            mma_f16(yacc[pair*2 + 1], af, bv + 2);
        }
    }

    __half* Yout = (DIR == 0) ? g_Yd : g_Yh;
    #pragma unroll
    for (int nt = 0; nt < 4; nt++) {
        const int c = ncol0 + nt*8 + tig*2;
        *(__half2*)&Yout[(base + (size_t)mr*stride)*64 + c] =
            __floats2half2_rn(yacc[nt][0], yacc[nt][1]);
        *(__half2*)&Yout[(base + (size_t)(mr + 8)*stride)*64 + c] =
            __floats2half2_rn(yacc[nt][2], yacc[nt][3]);
    }
}

// ---------------- W-direction attention + fused 3-way combine ---------------
__global__ __launch_bounds__(192) void attn2_kernel() {
    __shared__ __half Tl[48*72];
    __shared__ __half Pl[48*72];
    __shared__ __half Gl[48*72];
    __shared__ __half Sh[48*72];    // raw scores -> Y staging (fp16)
    __shared__ float  rmS[48], rsS[48];

    const int pid = blockIdx.x;
    const int b = pid / (Sd*Sd);
    const int rr = pid % (Sd*Sd);
    const int u = rr / Sd, v = rr % Sd;
    const size_t base = (size_t)b*SP + u*Sd*Sd + v*Sd;   // stride 1
    const int tid = threadIdx.x;
    const int warp = tid >> 5, lane = tid & 31;
    const int grp = lane >> 2, tig = lane & 3;

    for (int l = tid; l < 48*8; l += 192) {
        int i = l >> 3, k8 = (l & 7) * 8;
        size_t o = (base + (size_t)i)*64 + k8;
        *(uint4*)&Tl[i*72 + k8] = *(const uint4*)&g_T[o];
        *(uint4*)&Pl[i*72 + k8] = *(const uint4*)&g_P[o];
        *(uint4*)&Gl[i*72 + k8] = *(const uint4*)&g_G[o];
    }
    __syncthreads();

    const int mrow0 = (warp >> 1) * 16;
    const int mr = mrow0 + grp;
    const int nhalf = (warp & 1) * 24;
    const int ncol0 = (warp & 1) * 32;

    const unsigned Ta = smaddr(&Tl[(mrow0 + (lane & 15))*72 + (lane >> 4)*8]);
    const unsigned Pa = smaddr(&Pl[(nhalf + (lane & 7))*72 + ((lane >> 3) & 1)*8]);
    const unsigned Ga = smaddr(&Gl[((lane & 7) + ((lane >> 3) & 1)*8)*72
                                   + ncol0 + (lane >> 4)*8]);

    float sacc[3][4];
    #pragma unroll
    for (int nt = 0; nt < 3; nt++)
        #pragma unroll
        for (int q = 0; q < 4; q++) sacc[nt][q] = 0.f;
    #pragma unroll
    for (int kc = 0; kc < 4; kc++) {
        unsigned af[4];
        ldsm_x4(af, Ta + kc*32);
        #pragma unroll
        for (int nt = 0; nt < 3; nt++) {
            unsigned bf[2];
            ldsm_x2(bf, Pa + nt*8*144 + kc*32);
            mma_f16(sacc[nt], af, bf);
        }
    }

    #pragma unroll
    for (int nt = 0; nt < 3; nt++) {
        const int j0 = nhalf + nt*8 + tig*2;
        float c0 = sacc[nt][0], c1 = sacc[nt][1], c2 = sacc[nt][2], c3 = sacc[nt][3];
        if (mr     == j0    ) c0 = -1e30f;
        if (mr     == j0 + 1) c1 = -1e30f;
        if (mr + 8 == j0    ) c2 = -1e30f;
        if (mr + 8 == j0 + 1) c3 = -1e30f;
        *(__half2*)&Sh[ mr     *72 + j0] = __floats2half2_rn(c0, c1);
        *(__half2*)&Sh[(mr + 8)*72 + j0] = __floats2half2_rn(c2, c3);
    }
    __syncthreads();

    {
        const int r = tid >> 2, q = tid & 3;
        float vals[12];
        float mx = -3.0e38f;
        #pragma unroll
        for (int j = 0; j < 12; j += 2) {
            float2 vv = h2f2(*(const unsigned*)&Sh[r*72 + q*12 + j]);
            vals[j] = vv.x; vals[j+1] = vv.y;
            mx = fmaxf(mx, fmaxf(vv.x, vv.y));
        }
        mx = fmaxf(mx, __shfl_xor_sync(0xffffffffu, mx, 1));
        mx = fmaxf(mx, __shfl_xor_sync(0xffffffffu, mx, 2));
        float sm = 0.f;
        #pragma unroll
        for (int j = 0; j < 12; j++) {
            float e = __expf(vals[j] - mx);
            sm += e;
            Tl[r*72 + q*12 + j] = __float2half(e);
        }
        sm += __shfl_xor_sync(0xffffffffu, sm, 1);
        sm += __shfl_xor_sync(0xffffffffu, sm, 2);
        if (q == 0) { rmS[r] = mx; rsS[r] = sm; }
    }
    __syncthreads();

    float yacc[4][4];
    #pragma unroll
    for (int nt = 0; nt < 4; nt++)
        #pragma unroll
        for (int q = 0; q < 4; q++) yacc[nt][q] = 0.f;
    #pragma unroll
    for (int kc = 0; kc < 3; kc++) {
        unsigned af[4];
        ldsm_x4(af, Ta + kc*32);
        #pragma unroll
        for (int pair = 0; pair < 2; pair++) {
            unsigned bv[4];
            ldsm_x4_t(bv, Ga + kc*16*144 + pair*32);
            mma_f16(yacc[pair*2],     af, bv);
            mma_f16(yacc[pair*2 + 1], af, bv + 2);
        }
    }

    // stage Y into Sh (fp16)
    #pragma unroll
    for (int nt = 0; nt < 4; nt++) {
        const int c = ncol0 + nt*8 + tig*2;
        *(__half2*)&Sh[ mr     *72 + c] = __floats2half2_rn(yacc[nt][0], yacc[nt][1]);
        *(__half2*)&Sh[(mr + 8)*72 + c] = __floats2half2_rn(yacc[nt][2], yacc[nt][3]);
    }
    __syncthreads();

    // fused 3-way combine: thread = (voxel pair, 8 g-values); half2 g-major out
    {
        const int ip = tid >> 3;          // 0..23 -> voxels 2ip, 2ip+1
        const int g0 = (tid & 7) * 8;
        const int i0 = ip*2, i1 = i0 + 1;
        const size_t vox0 = base + i0, vox1 = base + i1;

        float md0 = g_md[vox0], sd0 = g_sd[vox0];
        float mh0 = g_mh[vox0], sh0 = g_sh[vox0];
        float mw0 = rmS[i0],    sw0 = rsS[i0];
        float m0  = fmaxf(md0, fmaxf(mh0, mw0));
        float wd0 = __expf(md0 - m0), wh0 = __expf(mh0 - m0), ww0 = __expf(mw0 - m0);
        float iv0 = 1.0f / (sd0*wd0 + sh0*wh0 + sw0*ww0);
        wd0 *= iv0; wh0 *= iv0; ww0 *= iv0;

        float md1 = g_md[vox1], sd1 = g_sd[vox1];
        float mh1 = g_mh[vox1], sh1 = g_sh[vox1];
        float mw1 = rmS[i1],    sw1 = rsS[i1];
        float m1  = fmaxf(md1, fmaxf(mh1, mw1));
        float wd1 = __expf(md1 - m1), wh1 = __expf(mh1 - m1), ww1 = __expf(mw1 - m1);
        float iv1 = 1.0f / (sd1*wd1 + sh1*wh1 + sw1*ww1);
        wd1 *= iv1; wh1 *= iv1; ww1 *= iv1;

        uint4 a0u = *(const uint4*)&g_Yd[vox0*64 + g0];
        uint4 a1u = *(const uint4*)&g_Yd[vox1*64 + g0];
        uint4 h0u = *(const uint4*)&g_Yh[vox0*64 + g0];
        uint4 h1u = *(const uint4*)&g_Yh[vox1*64 + g0];
        uint4 y0u = *(const uint4*)&Sh[i0*72 + g0];
        uint4 y1u = *(const uint4*)&Sh[i1*72 + g0];
        const unsigned* a0 = (const unsigned*)&a0u;
        const unsigned* a1 = (const unsigned*)&a1u;
        const unsigned* h0 = (const unsigned*)&h0u;
        const unsigned* h1 = (const unsigned*)&h1u;
        const unsigned* y0 = (const unsigned*)&y0u;
        const unsigned* y1 = (const unsigned*)&y1u;

        const size_t sp0 = base - (size_t)b*SP;
        #pragma unroll
        for (int q = 0; q < 4; q++) {
            float2 av0 = h2f2(a0[q]), hv0 = h2f2(h0[q]), yv0 = h2f2(y0[q]);
            float2 av1 = h2f2(a1[q]), hv1 = h2f2(h1[q]), yv1 = h2f2(y1[q]);
            float o0a = av0.x*wd0 + hv0.x*wh0 + yv0.x*ww0;
            float o0b = av0.y*wd0 + hv0.y*wh0 + yv0.y*ww0;
            float o1a = av1.x*wd1 + hv1.x*wh1 + yv1.x*ww1;
            float o1b = av1.y*wd1 + hv1.y*wh1 + yv1.y*ww1;
            int g = g0 + q*2;
            *(__half2*)&g_Yw[((size_t)(b*64 + g    ))*SP + sp0 + i0] =
                __floats2half2_rn(o0a, o1a);
            *(__half2*)&g_Yw[((size_t)(b*64 + g + 1))*SP + sp0 + i0] =
                __floats2half2_rn(o0b, o1b);
        }
    }
}

// ---------------- cross GEMM (fp16 mma): [128ch x 64vox], K=64 + GN sums ---
__global__ __launch_bounds__(256) void cross_kernel(const float* __restrict__ rb)
{
    __shared__ __half As[128*72];   // rw [m=ch][k=g], pitch 72
    __shared__ __half Bs[32*72];    // Y  [k][n],      pitch 72
    __shared__ float gsum[32], gss[32];
    const int b = blockIdx.y, n0 = blockIdx.x*64, tid = threadIdx.x;
    const int warp = tid >> 5, lane = tid & 31;
    const int grp = lane >> 2, tig = lane & 3;
    const int m_base = (warp >> 1) * 32, n_base = (warp & 1) * 32;

    float acc[2][4][4];
    #pragma unroll
    for (int mt = 0; mt < 2; mt++)
        #pragma unroll
        for (int nt = 0; nt < 4; nt++)
            #pragma unroll
            for (int q = 0; q < 4; q++) acc[mt][nt][q] = 0.f;

    #pragma unroll
    for (int it = 0; it < 4; it++) {
        int idx = it*256 + tid;
        int m = idx >> 3, kp = (idx & 7)*8;
        *(uint4*)&As[m*72 + kp] = *(const uint4*)&g_rwT16[m*64 + kp];
    }
    if (tid < 32) { gsum[tid] = 0.f; gss[tid] = 0.f; }

    const unsigned Aaddr = smaddr(&As[(m_base + (lane & 15))*72 + (lane >> 4)*8]);
    const unsigned Baddr = smaddr(&Bs[((lane & 7) + ((lane >> 3) & 1)*8)*72
                                      + n_base + (lane >> 4)*8]);

    for (int g0 = 0; g0 < 64; g0 += 32) {
        {
            int kk = tid >> 3, n8 = (tid & 7) * 8;
            *(uint4*)&Bs[kk*72 + n8] =
                *(const uint4*)&g_Yw[((size_t)b*64 + g0 + kk)*SP + n0 + n8];
        }
        __syncthreads();
        #pragma unroll
        for (int kc = 0; kc < 2; kc++) {
            unsigned bv0[4], bv1[4];
            ldsm_x4_t(bv0, Baddr + kc*16*144);
            ldsm_x4_t(bv1, Baddr + kc*16*144 + 32);
            #pragma unroll
            for (int mt = 0; mt < 2; mt++) {
                unsigned af[4];
                ldsm_x4(af, Aaddr + mt*16*144 + g0*2 + kc*32);
                mma_f16(acc[mt][0], af, bv0);
                mma_f16(acc[mt][1], af, bv0 + 2);
                mma_f16(acc[mt][2], af, bv1);
                mma_f16(acc[mt][3], af, bv1 + 2);
            }
        }
        __syncthreads();
    }

    #pragma unroll
    for (int mt = 0; mt < 2; mt++) {
        #pragma unroll
        for (int rr = 0; rr < 2; rr++) {
            const int r = m_base + mt*16 + rr*8 + grp;
            const float bv = rb[r];
            float ps = 0.f, pss = 0.f;
            #pragma unroll
            for (int nt = 0; nt < 4; nt++) {
                const int c = n_base + nt*8 + tig*2;
                float v0 = acc[mt][nt][rr*2 + 0] + bv;
                float v1 = acc[mt][nt][rr*2 + 1] + bv;
                size_t ob = ((size_t)b*Cc + r)*SP + n0 + c;
                *(__half2*)&g_cross[ob] = __floats2half2_rn(v0, v1);
                ps += v0 + v1; pss += v0*v0 + v1*v1;
            }
            ps  += __shfl_xor_sync(0xffffffffu, ps, 1);
            ps  += __shfl_xor_sync(0xffffffffu, ps, 2);
            pss += __shfl_xor_sync(0xffffffffu, pss, 1);
            pss += __shfl_xor_sync(0xffffffffu, pss, 2);
            if (tig == 0) {
                atomicAdd(&gsum[r >> 2], ps);
                atomicAdd(&gss [r >> 2], pss);
            }
        }
    }
    __syncthreads();
    if (tid < 32) {
        atomicAdd(&g_gnsum[b*32 + tid], gsum[tid]);
        atomicAdd(&g_gnss [b*32 + tid], gss[tid]);
    }
}

// ---------------- GroupNorm + residual (streaming, channel-first) ----------
__global__ __launch_bounds__(256) void gnres_kernel(
    int layer, const float* __restrict__ x,
    const float* __restrict__ gnw, const float* __restrict__ gnb,
    int accum_bn)
{
    const int c = blockIdx.y, b = blockIdx.z, chunk = blockIdx.x;
    const size_t base = ((size_t)(b*Cc + c))*SP + (size_t)chunk*(SP/4);
    const int g = c >> 2;
    const float invN = 1.0f / (4.0f * SP);
    float mu  = g_gnsum[b*32 + g] * invN;
    float var = g_gnss[b*32 + g] * invN - mu*mu;
    float rstd = rsqrtf(var + 1e-5f);
    float w = gnw[c], bias = gnb[c];
    float s = 0.f, ss = 0.f;
    for (int j = 0; j < 27; j++) {
        size_t o = base + (size_t)j*1024 + threadIdx.x*4;
        uint2 ch = *(const uint2*)&g_cross[o];
        float2 c01 = h2f2(ch.x), c23 = h2f2(ch.y);
        float4 rv;
        if (layer) {
            uint2 hv = *(const uint2*)&g_hh[o];
            float2 r01 = h2f2(hv.x), r23 = h2f2(hv.y);
            rv.x = r01.x; rv.y = r01.y; rv.z = r23.x; rv.w = r23.y;
        } else {
            rv = *(const float4*)&x[o];
        }
        float4 h;
        h.x = rv.x + (c01.x - mu)*rstd*w + bias;
        h.y = rv.y + (c01.y - mu)*rstd*w + bias;
        h.z = rv.z + (c23.x - mu)*rstd*w + bias;
        h.w = rv.w + (c23.y - mu)*rstd*w + bias;
        uint2 hw;
        __half2 w0 = __floats2half2_rn(h.x, h.y);
        __half2 w1 = __floats2half2_rn(h.z, h.w);
        hw.x = *(unsigned*)&w0; hw.y = *(unsigned*)&w1;
        *(uint2*)&g_hh[o] = hw;
        if (accum_bn) {
            s  += h.x + h.y + h.z + h.w;
            ss += h.x*h.x + h.y*h.y + h.z*h.z + h.w*h.w;
        }
    }
    if (accum_bn) {
        #pragma unroll
        for (int o = 16; o > 0; o >>= 1) {
            s  += __shfl_xor_sync(0xffffffffu, s,  o);
            ss += __shfl_xor_sync(0xffffffffu, ss, o);
        }
        __shared__ float ws[8], wss[8];
        int wid = threadIdx.x >> 5, lane = threadIdx.x & 31;
        if (lane == 0) { ws[wid] = s; wss[wid] = ss; }
        __syncthreads();
        if (threadIdx.x == 0) {
            float ts = 0.f, tss = 0.f;
            #pragma unroll
            for (int k = 0; k < 8; k++) { ts += ws[k]; tss += wss[k]; }
            atomicAdd(&g_bnsum[c], ts);
            atomicAdd(&g_bnss[c],  tss);
        }
    }
}

// ---------------- BatchNorm apply + ReLU ------------------------------------
__global__ __launch_bounds__(256) void bnapply_kernel(
    const float* __restrict__ bw, const float* __restrict__ bb, float* __restrict__ out)
{
    size_t i4 = (size_t)blockIdx.x*256 + threadIdx.x;
    if (i4 >= (size_t)Bb*Cc*SP/4) return;
    size_t i = i4 * 4;
    int c = (int)((i / SP) & 127);
    const float invN = 1.0f / ((float)Bb * SP);
    float mu  = g_bnsum[c] * invN;
    float var = g_bnss[c] * invN - mu*mu;
    float rstd = rsqrtf(var + 1e-5f);
    float wv = bw[c], bv = bb[c];
    uint2 hv = *(const uint2*)&g_hh[i];
    float2 v01 = h2f2(hv.x), v23 = h2f2(hv.y);
    float4 v;
    v.x = fmaxf((v01.x - mu)*rstd*wv + bv, 0.f);
    v.y = fmaxf((v01.y - mu)*rstd*wv + bv, 0.f);
    v.z = fmaxf((v23.x - mu)*rstd*wv + bv, 0.f);
    v.w = fmaxf((v23.y - mu)*rstd*wv + bv, 0.f);
    *(float4*)&out[i] = v;
}

// ---------------- launch -----------------------------------------------------
extern "C" void kernel_launch(void* const* d_in, const int* in_sizes, int n_in,
                              void* d_out, int out_size)
{
    const float* x   = (const float*)d_in[0];
    const float* tw  = (const float*)d_in[1];
    const float* tb  = (const float*)d_in[2];
    const float* pw  = (const float*)d_in[3];
    const float* pb  = (const float*)d_in[4];
    const float* gw  = (const float*)d_in[5];
    const float* gb  = (const float*)d_in[6];
    const float* rw  = (const float*)d_in[7];
    const float* rb  = (const float*)d_in[8];
    const float* gnw = (const float*)d_in[9];
    const float* gnb = (const float*)d_in[10];
    const float* bnw = (const float*)d_in[11];
    const float* bnb = (const float*)d_in[12];
    float* out = (float*)d_out;

    wtrans_kernel<<<96, 256>>>(tw, pw, gw, rw);

    for (int layer = 0; layer < 2; layer++) {
        proj_kernel<<<dim3(SP/64, Bb), 256>>>(layer, x, tb, pb, gb);
        attn01_kernel<<<dim3(Bb*Sd*Sd, 2), 192>>>();
        attn2_kernel<<<Bb*Sd*Sd, 192>>>();
        cross_kernel<<<dim3(SP/64, Bb), 256>>>(rb);
        gnres_kernel<<<dim3(4, Cc, Bb), 256>>>(layer, x, gnw + layer*Cc, gnb + layer*Cc,
                                               layer == 1 ? 1 : 0);
    }
    bnapply_kernel<<<((Bb*Cc*SP/4) + 255)/256, 256>>>(bnw, bnb, out);
}

// round 14
// speedup vs baseline: 5.1648x; 1.0398x over previous
#include <cuda_runtime.h>
#include <cuda_fp16.h>

#define Sd 48
#define SP (Sd*Sd*Sd)      // 110592
#define Bb 2
#define Cc 128
#define NVx (Bb*SP)        // 221184

// ---------------- mma / ldmatrix helpers ------------------------------------
__device__ __forceinline__ void mma_f16(float* d, const unsigned* a, const unsigned* b) {
    asm volatile(
        "mma.sync.aligned.m16n8k16.row.col.f32.f16.f16.f32 "
        "{%0,%1,%2,%3},{%4,%5,%6,%7},{%8,%9},{%0,%1,%2,%3};"
        : "+f"(d[0]), "+f"(d[1]), "+f"(d[2]), "+f"(d[3])
        : "r"(a[0]), "r"(a[1]), "r"(a[2]), "r"(a[3]), "r"(b[0]), "r"(b[1]));
}
__device__ __forceinline__ unsigned smaddr(const void* p) {
    unsigned a;
    asm("{ .reg .u64 t; cvta.to.shared.u64 t, %1; cvt.u32.u64 %0, t; }" : "=r"(a) : "l"(p));
    return a;
}
__device__ __forceinline__ void ldsm_x4(unsigned* r, unsigned a) {
    asm volatile("ldmatrix.sync.aligned.m8n8.x4.shared.b16 {%0,%1,%2,%3},[%4];"
        : "=r"(r[0]), "=r"(r[1]), "=r"(r[2]), "=r"(r[3]) : "r"(a));
}
__device__ __forceinline__ void ldsm_x2(unsigned* r, unsigned a) {
    asm volatile("ldmatrix.sync.aligned.m8n8.x2.shared.b16 {%0,%1},[%2];"
        : "=r"(r[0]), "=r"(r[1]) : "r"(a));
}
__device__ __forceinline__ void ldsm_x4_t(unsigned* r, unsigned a) {
    asm volatile("ldmatrix.sync.aligned.m8n8.x4.trans.shared.b16 {%0,%1,%2,%3},[%4];"
        : "=r"(r[0]), "=r"(r[1]), "=r"(r[2]), "=r"(r[3]) : "r"(a));
}
__device__ __forceinline__ float2 h2f2(unsigned u) {
    __half2 h = *reinterpret_cast<__half2*>(&u);
    return __half22float2(h);
}

// ---------------- scratch --------------------------------------------------
__device__ __half g_hh[(size_t)Bb*Cc*SP];      // residual stream h (fp16)
__device__ __half g_T[(size_t)NVx*64];
__device__ __half g_P[(size_t)NVx*64];
__device__ __half g_G[(size_t)NVx*64];
__device__ __half g_Yd[(size_t)NVx*64];        // D-dir partial, vox-major
__device__ __half g_Yh[(size_t)NVx*64];        // H-dir partial, vox-major
__device__ __half g_Yw[(size_t)NVx*64];        // final combined Y, g-major
__device__ float g_md[NVx]; __device__ float g_sd[NVx];
__device__ float g_mh[NVx]; __device__ float g_sh[NVx];
__device__ __half g_cross[(size_t)Bb*Cc*SP];   // channel-first, fp16
__device__ __half g_WT16[192*128];             // fused theta/phi/G weights [m][k]
__device__ __half g_rwT16[128*64];             // r_w [m=ch][k=g]
__device__ float g_gnsum[Bb*32]; __device__ float g_gnss[Bb*32];
__device__ float g_bnsum[Cc];    __device__ float g_bnss[Cc];

// ---------------- one-time weight convert + BN-stat zero --------------------
__global__ __launch_bounds__(256) void wtrans_kernel(
    const float* __restrict__ tw, const float* __restrict__ pw,
    const float* __restrict__ gw, const float* __restrict__ rw)
{
    int idx = blockIdx.x*256 + threadIdx.x;
    if (idx < 192*128) {
        float v;
        if (idx < 64*128)       v = tw[idx];
        else if (idx < 128*128) v = pw[idx - 64*128];
        else                    v = gw[idx - 128*128];
        g_WT16[idx] = __float2half(v);
    }
    if (idx < 128*64) g_rwT16[idx] = __float2half(rw[idx]);
    if (idx < Cc) { g_bnsum[idx] = 0.f; g_bnss[idx] = 0.f; }
}

// ---------------- projection (fp16 mma): [192m x 64n] tile, K=128 ----------
// Epilogue: smem transpose staging -> coalesced 128B-row stores of T/P/G.
__global__ __launch_bounds__(256) void proj_kernel(
    int layer, const float* __restrict__ x,
    const float* __restrict__ tb, const float* __restrict__ pb,
    const float* __restrict__ gb)
{
    __shared__ __align__(16) __half U[64*200];    // staging [vox][m]; aliases As/Bs
    __half* As = U;                                // [192][40]
    __half* Bs = U + 192*40;                       // [32][72]
    const int b = blockIdx.y, n0 = blockIdx.x*64, tid = threadIdx.x;
    if (blockIdx.x == 0 && blockIdx.y == 0 && tid < Bb*32) {
        g_gnsum[tid] = 0.f; g_gnss[tid] = 0.f;
    }
    const int warp = tid >> 5, lane = tid & 31;
    const int grp = lane >> 2, tig = lane & 3;
    const int m_base = (warp >> 1) * 48, n_base = (warp & 1) * 32;

    float acc[3][4][4];
    #pragma unroll
    for (int mt = 0; mt < 3; mt++)
        #pragma unroll
        for (int nt = 0; nt < 4; nt++)
            #pragma unroll
            for (int q = 0; q < 4; q++) acc[mt][nt][q] = 0.f;

    const unsigned Aaddr = smaddr(&As[(m_base + (lane & 15))*40 + (lane >> 4)*8]);
    const unsigned Baddr = smaddr(&Bs[((lane & 7) + ((lane >> 3) & 1)*8)*72
                                      + n_base + (lane >> 4)*8]);

    for (int k0 = 0; k0 < 128; k0 += 32) {
        #pragma unroll
        for (int it = 0; it < 3; it++) {
            int idx = it*256 + tid;           // 0..767
            int m = idx >> 2, kp = (idx & 3)*8;
            *(uint4*)&As[m*40 + kp] = *(const uint4*)&g_WT16[m*128 + k0 + kp];
        }
        {
            int kk = tid >> 3, n8 = (tid & 7)*8;
            size_t off = (size_t)(b*Cc + k0 + kk)*SP + n0 + n8;
            if (layer) {
                *(uint4*)&Bs[kk*72 + n8] = *(const uint4*)&g_hh[off];
            } else {
                const float* s = &x[off];
                float4 v0 = *(const float4*)s, v1 = *(const float4*)(s + 4);
                __half2 h0 = __floats2half2_rn(v0.x, v0.y);
                __half2 h1 = __floats2half2_rn(v0.z, v0.w);
                __half2 h2 = __floats2half2_rn(v1.x, v1.y);
                __half2 h3 = __floats2half2_rn(v1.z, v1.w);
                uint4 pk;
                pk.x = *(unsigned*)&h0; pk.y = *(unsigned*)&h1;
                pk.z = *(unsigned*)&h2; pk.w = *(unsigned*)&h3;
                *(uint4*)&Bs[kk*72 + n8] = pk;
            }
        }
        __syncthreads();
        #pragma unroll
        for (int kc = 0; kc < 2; kc++) {
            unsigned bv0[4], bv1[4];
            ldsm_x4_t(bv0, Baddr + kc*16*144);
            ldsm_x4_t(bv1, Baddr + kc*16*144 + 32);
            #pragma unroll
            for (int mt = 0; mt < 3; mt++) {
                unsigned af[4];
                ldsm_x4(af, Aaddr + mt*16*80 + kc*32);
                mma_f16(acc[mt][0], af, bv0);
                mma_f16(acc[mt][1], af, bv0 + 2);
                mma_f16(acc[mt][2], af, bv1);
                mma_f16(acc[mt][3], af, bv1 + 2);
            }
        }
        __syncthreads();
    }

    // ---- stage into U[vox][m] (bias added), then coalesced row stores ----
    #pragma unroll
    for (int mt = 0; mt < 3; mt++) {
        #pragma unroll
        for (int rr = 0; rr < 2; rr++) {
            const int r = m_base + mt*16 + rr*8 + grp;
            const float bv = (r < 64) ? tb[r] : (r < 128 ? pb[r-64] : gb[r-128]);
            #pragma unroll
            for (int nt = 0; nt < 4; nt++) {
                const int c = n_base + nt*8 + tig*2;
                U[ c   *200 + r] = __float2half(acc[mt][nt][rr*2 + 0] + bv);
                U[(c+1)*200 + r] = __float2half(acc[mt][nt][rr*2 + 1] + bv);
            }
        }
    }
    __syncthreads();
    #pragma unroll
    for (int it = 0; it < 6; it++) {
        int idx = it*256 + tid;               // 0..1535
        int seg = idx >> 9;                   // 0:T 1:P 2:G
        int rem = idx & 511;
        int vox = rem >> 3, ch = rem & 7;
        __half* dst = (seg == 0) ? g_T : ((seg == 1) ? g_P : g_G);
        uint4 val = *(const uint4*)&U[vox*200 + seg*64 + ch*8];
        *(uint4*)&dst[((size_t)b*SP + n0 + vox)*64 + ch*8] = val;
    }
}

// ---------------- merged D/H attention (blockIdx.y = direction 0/1) --------
__global__ __launch_bounds__(192) void attn01_kernel() {
    __shared__ __half Tl[48*72];
    __shared__ __half Pl[48*72];
    __shared__ __half Gl[48*72];
    __shared__ __half Sh[48*72];

    const int DIR = blockIdx.y;
    const int pid = blockIdx.x;
    const int b = pid / (Sd*Sd);
    const int rr = pid % (Sd*Sd);
    const int u = rr / Sd, v = rr % Sd;
    size_t base; int stride;
    if (DIR == 0) { base = (size_t)b*SP + u*Sd + v;    stride = Sd*Sd; }
    else          { base = (size_t)b*SP + u*Sd*Sd + v; stride = Sd;    }
    const int tid = threadIdx.x;
    const int warp = tid >> 5, lane = tid & 31;
    const int grp = lane >> 2, tig = lane & 3;

    for (int l = tid; l < 48*8; l += 192) {
        int i = l >> 3, k8 = (l & 7) * 8;
        size_t o = (base + (size_t)i*stride)*64 + k8;
        *(uint4*)&Tl[i*72 + k8] = *(const uint4*)&g_T[o];
        *(uint4*)&Pl[i*72 + k8] = *(const uint4*)&g_P[o];
        *(uint4*)&Gl[i*72 + k8] = *(const uint4*)&g_G[o];
    }
    __syncthreads();

    const int mrow0 = (warp >> 1) * 16;
    const int mr = mrow0 + grp;
    const int nhalf = (warp & 1) * 24;
    const int ncol0 = (warp & 1) * 32;

    const unsigned Ta = smaddr(&Tl[(mrow0 + (lane & 15))*72 + (lane >> 4)*8]);
    const unsigned Pa = smaddr(&Pl[(nhalf + (lane & 7))*72 + ((lane >> 3) & 1)*8]);
    const unsigned Ga = smaddr(&Gl[((lane & 7) + ((lane >> 3) & 1)*8)*72
                                   + ncol0 + (lane >> 4)*8]);

    float sacc[3][4];
    #pragma unroll
    for (int nt = 0; nt < 3; nt++)
        #pragma unroll
        for (int q = 0; q < 4; q++) sacc[nt][q] = 0.f;
    #pragma unroll
    for (int kc = 0; kc < 4; kc++) {
        unsigned af[4];
        ldsm_x4(af, Ta + kc*32);
        #pragma unroll
        for (int nt = 0; nt < 3; nt++) {
            unsigned bf[2];
            ldsm_x2(bf, Pa + nt*8*144 + kc*32);
            mma_f16(sacc[nt], af, bf);
        }
    }

    #pragma unroll
    for (int nt = 0; nt < 3; nt++) {
        const int j0 = nhalf + nt*8 + tig*2;
        float c0 = sacc[nt][0], c1 = sacc[nt][1], c2 = sacc[nt][2], c3 = sacc[nt][3];
        if (DIR != 0) {
            if (mr     == j0    ) c0 = -1e30f;
            if (mr     == j0 + 1) c1 = -1e30f;
            if (mr + 8 == j0    ) c2 = -1e30f;
            if (mr + 8 == j0 + 1) c3 = -1e30f;
        }
        *(__half2*)&Sh[ mr     *72 + j0] = __floats2half2_rn(c0, c1);
        *(__half2*)&Sh[(mr + 8)*72 + j0] = __floats2half2_rn(c2, c3);
    }
    __syncthreads();

    {
        const int r = tid >> 2, q = tid & 3;
        float vals[12];
        float mx = -3.0e38f;
        #pragma unroll
        for (int j = 0; j < 12; j += 2) {
            float2 vv = h2f2(*(const unsigned*)&Sh[r*72 + q*12 + j]);
            vals[j] = vv.x; vals[j+1] = vv.y;
            mx = fmaxf(mx, fmaxf(vv.x, vv.y));
        }
        mx = fmaxf(mx, __shfl_xor_sync(0xffffffffu, mx, 1));
        mx = fmaxf(mx, __shfl_xor_sync(0xffffffffu, mx, 2));
        float sm = 0.f;
        #pragma unroll
        for (int j = 0; j < 12; j++) {
            float e = __expf(vals[j] - mx);
            sm += e;
            Tl[r*72 + q*12 + j] = __float2half(e);
        }
        sm += __shfl_xor_sync(0xffffffffu, sm, 1);
        sm += __shfl_xor_sync(0xffffffffu, sm, 2);
        if (q == 0) {
            size_t vx = base + (size_t)r*stride;
            if (DIR == 0) { g_md[vx] = mx; g_sd[vx] = sm; }
            else          { g_mh[vx] = mx; g_sh[vx] = sm; }
        }
    }
    __syncthreads();

    float yacc[4][4];
    #pragma unroll
    for (int nt = 0; nt < 4; nt++)
        #pragma unroll
        for (int q = 0; q < 4; q++) yacc[nt][q] = 0.f;
    #pragma unroll
    for (int kc = 0; kc < 3; kc++) {
        unsigned af[4];
        ldsm_x4(af, Ta + kc*32);
        #pragma unroll
        for (int pair = 0; pair < 2; pair++) {
            unsigned bv[4];
            ldsm_x4_t(bv, Ga + kc*16*144 + pair*32);
            mma_f16(yacc[pair*2],     af, bv);
            mma_f16(yacc[pair*2 + 1], af, bv + 2);
        }
    }

    __half* Yout = (DIR == 0) ? g_Yd : g_Yh;
    #pragma unroll
    for (int nt = 0; nt < 4; nt++) {
        const int c = ncol0 + nt*8 + tig*2;
        *(__half2*)&Yout[(base + (size_t)mr*stride)*64 + c] =
            __floats2half2_rn(yacc[nt][0], yacc[nt][1]);
        *(__half2*)&Yout[(base + (size_t)(mr + 8)*stride)*64 + c] =
            __floats2half2_rn(yacc[nt][2], yacc[nt][3]);
    }
}

// ---------------- W-direction attention + fused 3-way combine ---------------
__global__ __launch_bounds__(192) void attn2_kernel() {
    __shared__ __half Tl[48*72];
    __shared__ __half Pl[48*72];
    __shared__ __half Gl[48*72];
    __shared__ __half Sh[48*72];
    __shared__ float  rmS[48], rsS[48];

    const int pid = blockIdx.x;
    const int b = pid / (Sd*Sd);
    const int rr = pid % (Sd*Sd);
    const int u = rr / Sd, v = rr % Sd;
    const size_t base = (size_t)b*SP + u*Sd*Sd + v*Sd;   // stride 1
    const int tid = threadIdx.x;
    const int warp = tid >> 5, lane = tid & 31;
    const int grp = lane >> 2, tig = lane & 3;

    for (int l = tid; l < 48*8; l += 192) {
        int i = l >> 3, k8 = (l & 7) * 8;
        size_t o = (base + (size_t)i)*64 + k8;
        *(uint4*)&Tl[i*72 + k8] = *(const uint4*)&g_T[o];
        *(uint4*)&Pl[i*72 + k8] = *(const uint4*)&g_P[o];
        *(uint4*)&Gl[i*72 + k8] = *(const uint4*)&g_G[o];
    }
    __syncthreads();

    const int mrow0 = (warp >> 1) * 16;
    const int mr = mrow0 + grp;
    const int nhalf = (warp & 1) * 24;
    const int ncol0 = (warp & 1) * 32;

    const unsigned Ta = smaddr(&Tl[(mrow0 + (lane & 15))*72 + (lane >> 4)*8]);
    const unsigned Pa = smaddr(&Pl[(nhalf + (lane & 7))*72 + ((lane >> 3) & 1)*8]);
    const unsigned Ga = smaddr(&Gl[((lane & 7) + ((lane >> 3) & 1)*8)*72
                                   + ncol0 + (lane >> 4)*8]);

    float sacc[3][4];
    #pragma unroll
    for (int nt = 0; nt < 3; nt++)
        #pragma unroll
        for (int q = 0; q < 4; q++) sacc[nt][q] = 0.f;
    #pragma unroll
    for (int kc = 0; kc < 4; kc++) {
        unsigned af[4];
        ldsm_x4(af, Ta + kc*32);
        #pragma unroll
        for (int nt = 0; nt < 3; nt++) {
            unsigned bf[2];
            ldsm_x2(bf, Pa + nt*8*144 + kc*32);
            mma_f16(sacc[nt], af, bf);
        }
    }

    #pragma unroll
    for (int nt = 0; nt < 3; nt++) {
        const int j0 = nhalf + nt*8 + tig*2;
        float c0 = sacc[nt][0], c1 = sacc[nt][1], c2 = sacc[nt][2], c3 = sacc[nt][3];
        if (mr     == j0    ) c0 = -1e30f;
        if (mr     == j0 + 1) c1 = -1e30f;
        if (mr + 8 == j0    ) c2 = -1e30f;
        if (mr + 8 == j0 + 1) c3 = -1e30f;
        *(__half2*)&Sh[ mr     *72 + j0] = __floats2half2_rn(c0, c1);
        *(__half2*)&Sh[(mr + 8)*72 + j0] = __floats2half2_rn(c2, c3);
    }
    __syncthreads();

    {
        const int r = tid >> 2, q = tid & 3;
        float vals[12];
        float mx = -3.0e38f;
        #pragma unroll
        for (int j = 0; j < 12; j += 2) {
            float2 vv = h2f2(*(const unsigned*)&Sh[r*72 + q*12 + j]);
            vals[j] = vv.x; vals[j+1] = vv.y;
            mx = fmaxf(mx, fmaxf(vv.x, vv.y));
        }
        mx = fmaxf(mx, __shfl_xor_sync(0xffffffffu, mx, 1));
        mx = fmaxf(mx, __shfl_xor_sync(0xffffffffu, mx, 2));
        float sm = 0.f;
        #pragma unroll
        for (int j = 0; j < 12; j++) {
            float e = __expf(vals[j] - mx);
            sm += e;
            Tl[r*72 + q*12 + j] = __float2half(e);
        }
        sm += __shfl_xor_sync(0xffffffffu, sm, 1);
        sm += __shfl_xor_sync(0xffffffffu, sm, 2);
        if (q == 0) { rmS[r] = mx; rsS[r] = sm; }
    }
    __syncthreads();

    float yacc[4][4];
    #pragma unroll
    for (int nt = 0; nt < 4; nt++)
        #pragma unroll
        for (int q = 0; q < 4; q++) yacc[nt][q] = 0.f;
    #pragma unroll
    for (int kc = 0; kc < 3; kc++) {
        unsigned af[4];
        ldsm_x4(af, Ta + kc*32);
        #pragma unroll
        for (int pair = 0; pair < 2; pair++) {
            unsigned bv[4];
            ldsm_x4_t(bv, Ga + kc*16*144 + pair*32);
            mma_f16(yacc[pair*2],     af, bv);
            mma_f16(yacc[pair*2 + 1], af, bv + 2);
        }
    }

    #pragma unroll
    for (int nt = 0; nt < 4; nt++) {
        const int c = ncol0 + nt*8 + tig*2;
        *(__half2*)&Sh[ mr     *72 + c] = __floats2half2_rn(yacc[nt][0], yacc[nt][1]);
        *(__half2*)&Sh[(mr + 8)*72 + c] = __floats2half2_rn(yacc[nt][2], yacc[nt][3]);
    }
    __syncthreads();

    // fused 3-way combine: thread = (voxel pair, 8 g-values); half2 g-major out
    {
        const int ip = tid >> 3;
        const int g0 = (tid & 7) * 8;
        const int i0 = ip*2, i1 = i0 + 1;
        const size_t vox0 = base + i0, vox1 = base + i1;

        float md0 = g_md[vox0], sd0 = g_sd[vox0];
        float mh0 = g_mh[vox0], sh0 = g_sh[vox0];
        float mw0 = rmS[i0],    sw0 = rsS[i0];
        float m0  = fmaxf(md0, fmaxf(mh0, mw0));
        float wd0 = __expf(md0 - m0), wh0 = __expf(mh0 - m0), ww0 = __expf(mw0 - m0);
        float iv0 = 1.0f / (sd0*wd0 + sh0*wh0 + sw0*ww0);
        wd0 *= iv0; wh0 *= iv0; ww0 *= iv0;

        float md1 = g_md[vox1], sd1 = g_sd[vox1];
        float mh1 = g_mh[vox1], sh1 = g_sh[vox1];
        float mw1 = rmS[i1],    sw1 = rsS[i1];
        float m1  = fmaxf(md1, fmaxf(mh1, mw1));
        float wd1 = __expf(md1 - m1), wh1 = __expf(mh1 - m1), ww1 = __expf(mw1 - m1);
        float iv1 = 1.0f / (sd1*wd1 + sh1*wh1 + sw1*ww1);
        wd1 *= iv1; wh1 *= iv1; ww1 *= iv1;

        uint4 a0u = *(const uint4*)&g_Yd[vox0*64 + g0];
        uint4 a1u = *(const uint4*)&g_Yd[vox1*64 + g0];
        uint4 h0u = *(const uint4*)&g_Yh[vox0*64 + g0];
        uint4 h1u = *(const uint4*)&g_Yh[vox1*64 + g0];
        uint4 y0u = *(const uint4*)&Sh[i0*72 + g0];
        uint4 y1u = *(const uint4*)&Sh[i1*72 + g0];
        const unsigned* a0 = (const unsigned*)&a0u;
        const unsigned* a1 = (const unsigned*)&a1u;
        const unsigned* h0 = (const unsigned*)&h0u;
        const unsigned* h1 = (const unsigned*)&h1u;
        const unsigned* y0 = (const unsigned*)&y0u;
        const unsigned* y1 = (const unsigned*)&y1u;

        const size_t sp0 = base - (size_t)b*SP;
        #pragma unroll
        for (int q = 0; q < 4; q++) {
            float2 av0 = h2f2(a0[q]), hv0 = h2f2(h0[q]), yv0 = h2f2(y0[q]);
            float2 av1 = h2f2(a1[q]), hv1 = h2f2(h1[q]), yv1 = h2f2(y1[q]);
            float o0a = av0.x*wd0 + hv0.x*wh0 + yv0.x*ww0;
            float o0b = av0.y*wd0 + hv0.y*wh0 + yv0.y*ww0;
            float o1a = av1.x*wd1 + hv1.x*wh1 + yv1.x*ww1;
            float o1b = av1.y*wd1 + hv1.y*wh1 + yv1.y*ww1;
            int g = g0 + q*2;
            *(__half2*)&g_Yw[((size_t)(b*64 + g    ))*SP + sp0 + i0] =
                __floats2half2_rn(o0a, o1a);
            *(__half2*)&g_Yw[((size_t)(b*64 + g + 1))*SP + sp0 + i0] =
                __floats2half2_rn(o0b, o1b);
        }
    }
}

// ---------------- cross GEMM (fp16 mma): [128ch x 64vox], K=64 + GN sums ---
// Epilogue: stage into As, then coalesced 128B-row stores of g_cross.
__global__ __launch_bounds__(256) void cross_kernel(const float* __restrict__ rb)
{
    __shared__ __half As[128*72];   // rw [m=ch][k=g] -> output staging [ch][vox]
    __shared__ __half Bs[32*72];    // Y  [k][n]
    __shared__ float gsum[32], gss[32];
    const int b = blockIdx.y, n0 = blockIdx.x*64, tid = threadIdx.x;
    const int warp = tid >> 5, lane = tid & 31;
    const int grp = lane >> 2, tig = lane & 3;
    const int m_base = (warp >> 1) * 32, n_base = (warp & 1) * 32;

    float acc[2][4][4];
    #pragma unroll
    for (int mt = 0; mt < 2; mt++)
        #pragma unroll
        for (int nt = 0; nt < 4; nt++)
            #pragma unroll
            for (int q = 0; q < 4; q++) acc[mt][nt][q] = 0.f;

    #pragma unroll
    for (int it = 0; it < 4; it++) {
        int idx = it*256 + tid;
        int m = idx >> 3, kp = (idx & 7)*8;
        *(uint4*)&As[m*72 + kp] = *(const uint4*)&g_rwT16[m*64 + kp];
    }
    if (tid < 32) { gsum[tid] = 0.f; gss[tid] = 0.f; }

    const unsigned Aaddr = smaddr(&As[(m_base + (lane & 15))*72 + (lane >> 4)*8]);
    const unsigned Baddr = smaddr(&Bs[((lane & 7) + ((lane >> 3) & 1)*8)*72
                                      + n_base + (lane >> 4)*8]);

    for (int g0 = 0; g0 < 64; g0 += 32) {
        {
            int kk = tid >> 3, n8 = (tid & 7) * 8;
            *(uint4*)&Bs[kk*72 + n8] =
                *(const uint4*)&g_Yw[((size_t)b*64 + g0 + kk)*SP + n0 + n8];
        }
        __syncthreads();
        #pragma unroll
        for (int kc = 0; kc < 2; kc++) {
            unsigned bv0[4], bv1[4];
            ldsm_x4_t(bv0, Baddr + kc*16*144);
            ldsm_x4_t(bv1, Baddr + kc*16*144 + 32);
            #pragma unroll
            for (int mt = 0; mt < 2; mt++) {
                unsigned af[4];
                ldsm_x4(af, Aaddr + mt*16*144 + g0*2 + kc*32);
                mma_f16(acc[mt][0], af, bv0);
                mma_f16(acc[mt][1], af, bv0 + 2);
                mma_f16(acc[mt][2], af, bv1);
                mma_f16(acc[mt][3], af, bv1 + 2);
            }
        }
        __syncthreads();
    }

    // ---- stage output tile [ch][vox] into As + GN partial sums ----
    #pragma unroll
    for (int mt = 0; mt < 2; mt++) {
        #pragma unroll
        for (int rr = 0; rr < 2; rr++) {
            const int r = m_base + mt*16 + rr*8 + grp;
            const float bv = rb[r];
            float ps = 0.f, pss = 0.f;
            #pragma unroll
            for (int nt = 0; nt < 4; nt++) {
                const int c = n_base + nt*8 + tig*2;
                float v0 = acc[mt][nt][rr*2 + 0] + bv;
                float v1 = acc[mt][nt][rr*2 + 1] + bv;
                *(__half2*)&As[r*72 + c] = __floats2half2_rn(v0, v1);
                ps += v0 + v1; pss += v0*v0 + v1*v1;
            }
            ps  += __shfl_xor_sync(0xffffffffu, ps, 1);
            ps  += __shfl_xor_sync(0xffffffffu, ps, 2);
            pss += __shfl_xor_sync(0xffffffffu, pss, 1);
            pss += __shfl_xor_sync(0xffffffffu, pss, 2);
            if (tig == 0) {
                atomicAdd(&gsum[r >> 2], ps);
                atomicAdd(&gss [r >> 2], pss);
            }
        }
    }
    __syncthreads();
    #pragma unroll
    for (int it = 0; it < 4; it++) {
        int idx = it*256 + tid;               // 0..1023
        int r = idx >> 3, ch = idx & 7;
        *(uint4*)&g_cross[((size_t)b*Cc + r)*SP + n0 + ch*8] =
            *(const uint4*)&As[r*72 + ch*8];
    }
    if (tid < 32) {
        atomicAdd(&g_gnsum[b*32 + tid], gsum[tid]);
        atomicAdd(&g_gnss [b*32 + tid], gss[tid]);
    }
}

// ---------------- GroupNorm + residual (streaming, channel-first) ----------
__global__ __launch_bounds__(256) void gnres_kernel(
    int layer, const float* __restrict__ x,
    const float* __restrict__ gnw, const float* __restrict__ gnb,
    int accum_bn)
{
    const int c = blockIdx.y, b = blockIdx.z, chunk = blockIdx.x;
    const size_t base = ((size_t)(b*Cc + c))*SP + (size_t)chunk*(SP/4);
    const int g = c >> 2;
    const float invN = 1.0f / (4.0f * SP);
    float mu  = g_gnsum[b*32 + g] * invN;
    float var = g_gnss[b*32 + g] * invN - mu*mu;
    float rstd = rsqrtf(var + 1e-5f);
    float w = gnw[c], bias = gnb[c];
    float s = 0.f, ss = 0.f;
    for (int j = 0; j < 27; j++) {
        size_t o = base + (size_t)j*1024 + threadIdx.x*4;
        uint2 ch = *(const uint2*)&g_cross[o];
        float2 c01 = h2f2(ch.x), c23 = h2f2(ch.y);
        float4 rv;
        if (layer) {
            uint2 hv = *(const uint2*)&g_hh[o];
            float2 r01 = h2f2(hv.x), r23 = h2f2(hv.y);
            rv.x = r01.x; rv.y = r01.y; rv.z = r23.x; rv.w = r23.y;
        } else {
            rv = *(const float4*)&x[o];
        }
        float4 h;
        h.x = rv.x + (c01.x - mu)*rstd*w + bias;
        h.y = rv.y + (c01.y - mu)*rstd*w + bias;
        h.z = rv.z + (c23.x - mu)*rstd*w + bias;
        h.w = rv.w + (c23.y - mu)*rstd*w + bias;
        uint2 hw;
        __half2 w0 = __floats2half2_rn(h.x, h.y);
        __half2 w1 = __floats2half2_rn(h.z, h.w);
        hw.x = *(unsigned*)&w0; hw.y = *(unsigned*)&w1;
        *(uint2*)&g_hh[o] = hw;
        if (accum_bn) {
            s  += h.x + h.y + h.z + h.w;
            ss += h.x*h.x + h.y*h.y + h.z*h.z + h.w*h.w;
        }
    }
    if (accum_bn) {
        #pragma unroll
        for (int o = 16; o > 0; o >>= 1) {
            s  += __shfl_xor_sync(0xffffffffu, s,  o);
            ss += __shfl_xor_sync(0xffffffffu, ss, o);
        }
        __shared__ float ws[8], wss[8];
        int wid = threadIdx.x >> 5, lane = threadIdx.x & 31;
        if (lane == 0) { ws[wid] = s; wss[wid] = ss; }
        __syncthreads();
        if (threadIdx.x == 0) {
            float ts = 0.f, tss = 0.f;
            #pragma unroll
            for (int k = 0; k < 8; k++) { ts += ws[k]; tss += wss[k]; }
            atomicAdd(&g_bnsum[c], ts);
            atomicAdd(&g_bnss[c],  tss);
        }
    }
}

// ---------------- BatchNorm apply + ReLU ------------------------------------
__global__ __launch_bounds__(256) void bnapply_kernel(
    const float* __restrict__ bw, const float* __restrict__ bb, float* __restrict__ out)
{
    size_t i4 = (size_t)blockIdx.x*256 + threadIdx.x;
    if (i4 >= (size_t)Bb*Cc*SP/4) return;
    size_t i = i4 * 4;
    int c = (int)((i / SP) & 127);
    const float invN = 1.0f / ((float)Bb * SP);
    float mu  = g_bnsum[c] * invN;
    float var = g_bnss[c] * invN - mu*mu;
    float rstd = rsqrtf(var + 1e-5f);
    float wv = bw[c], bv = bb[c];
    uint2 hv = *(const uint2*)&g_hh[i];
    float2 v01 = h2f2(hv.x), v23 = h2f2(hv.y);
    float4 v;
    v.x = fmaxf((v01.x - mu)*rstd*wv + bv, 0.f);
    v.y = fmaxf((v01.y - mu)*rstd*wv + bv, 0.f);
    v.z = fmaxf((v23.x - mu)*rstd*wv + bv, 0.f);
    v.w = fmaxf((v23.y - mu)*rstd*wv + bv, 0.f);
    *(float4*)&out[i] = v;
}

// ---------------- launch -----------------------------------------------------
extern "C" void kernel_launch(void* const* d_in, const int* in_sizes, int n_in,
                              void* d_out, int out_size)
{
    const float* x   = (const float*)d_in[0];
    const float* tw  = (const float*)d_in[1];
    const float* tb  = (const float*)d_in[2];
    const float* pw  = (const float*)d_in[3];
    const float* pb  = (const float*)d_in[4];
    const float* gw  = (const float*)d_in[5];
    const float* gb  = (const float*)d_in[6];
    const float* rw  = (const float*)d_in[7];
    const float* rb  = (const float*)d_in[8];
    const float* gnw = (const float*)d_in[9];
    const float* gnb = (const float*)d_in[10];
    const float* bnw = (const float*)d_in[11];
    const float* bnb = (const float*)d_in[12];
    float* out = (float*)d_out;

    wtrans_kernel<<<96, 256>>>(tw, pw, gw, rw);

    for (int layer = 0; layer < 2; layer++) {
        proj_kernel<<<dim3(SP/64, Bb), 256>>>(layer, x, tb, pb, gb);
        attn01_kernel<<<dim3(Bb*Sd*Sd, 2), 192>>>();
        attn2_kernel<<<Bb*Sd*Sd, 192>>>();
        cross_kernel<<<dim3(SP/64, Bb), 256>>>(rb);
        gnres_kernel<<<dim3(4, Cc, Bb), 256>>>(layer, x, gnw + layer*Cc, gnb + layer*Cc,
                                               layer == 1 ? 1 : 0);
    }
    bnapply_kernel<<<((Bb*Cc*SP/4) + 255)/256, 256>>>(bnw, bnb, out);
}

// round 15
// speedup vs baseline: 5.3806x; 1.0418x over previous
#include <cuda_runtime.h>
#include <cuda_fp16.h>

#define Sd 48
#define SP (Sd*Sd*Sd)      // 110592
#define Bb 2
#define Cc 128
#define NVx (Bb*SP)        // 221184

// ---------------- mma / ldmatrix / cp.async helpers -------------------------
__device__ __forceinline__ void mma_f16(float* d, const unsigned* a, const unsigned* b) {
    asm volatile(
        "mma.sync.aligned.m16n8k16.row.col.f32.f16.f16.f32 "
        "{%0,%1,%2,%3},{%4,%5,%6,%7},{%8,%9},{%0,%1,%2,%3};"
        : "+f"(d[0]), "+f"(d[1]), "+f"(d[2]), "+f"(d[3])
        : "r"(a[0]), "r"(a[1]), "r"(a[2]), "r"(a[3]), "r"(b[0]), "r"(b[1]));
}
__device__ __forceinline__ unsigned smaddr(const void* p) {
    unsigned a;
    asm("{ .reg .u64 t; cvta.to.shared.u64 t, %1; cvt.u32.u64 %0, t; }" : "=r"(a) : "l"(p));
    return a;
}
__device__ __forceinline__ void ldsm_x4(unsigned* r, unsigned a) {
    asm volatile("ldmatrix.sync.aligned.m8n8.x4.shared.b16 {%0,%1,%2,%3},[%4];"
        : "=r"(r[0]), "=r"(r[1]), "=r"(r[2]), "=r"(r[3]) : "r"(a));
}
__device__ __forceinline__ void ldsm_x2(unsigned* r, unsigned a) {
    asm volatile("ldmatrix.sync.aligned.m8n8.x2.shared.b16 {%0,%1},[%2];"
        : "=r"(r[0]), "=r"(r[1]) : "r"(a));
}
__device__ __forceinline__ void ldsm_x4_t(unsigned* r, unsigned a) {
    asm volatile("ldmatrix.sync.aligned.m8n8.x4.trans.shared.b16 {%0,%1,%2,%3},[%4];"
        : "=r"(r[0]), "=r"(r[1]), "=r"(r[2]), "=r"(r[3]) : "r"(a));
}
__device__ __forceinline__ float2 h2f2(unsigned u) {
    __half2 h = *reinterpret_cast<__half2*>(&u);
    return __half22float2(h);
}
__device__ __forceinline__ void cpa16(void* smem, const void* gmem) {
    unsigned s = smaddr(smem);
    asm volatile("cp.async.cg.shared.global [%0], [%1], 16;" :: "r"(s), "l"(gmem));
}
#define CPA_COMMIT() asm volatile("cp.async.commit_group;")
#define CPA_WAIT0()  asm volatile("cp.async.wait_group 0;")

// ---------------- scratch --------------------------------------------------
__device__ __half g_hh[(size_t)Bb*Cc*SP];      // residual stream h (fp16)
__device__ __half g_T[(size_t)NVx*64];
__device__ __half g_P[(size_t)NVx*64];
__device__ __half g_G[(size_t)NVx*64];
__device__ __half g_Yd[(size_t)NVx*64];        // D-dir partial, vox-major
__device__ __half g_Yh[(size_t)NVx*64];        // H-dir partial, vox-major
__device__ __half g_Yw[(size_t)NVx*64];        // final combined Y, g-major
__device__ float g_md[NVx]; __device__ float g_sd[NVx];
__device__ float g_mh[NVx]; __device__ float g_sh[NVx];
__device__ __half g_cross[(size_t)Bb*Cc*SP];   // channel-first, fp16
__device__ __half g_WT16[192*128];             // fused theta/phi/G weights [m][k]
__device__ __half g_rwT16[128*64];             // r_w [m=ch][k=g]
__device__ float g_gnsum[Bb*32]; __device__ float g_gnss[Bb*32];
__device__ float g_bnsum[Cc];    __device__ float g_bnss[Cc];

// ---------------- one-time weight convert + BN-stat zero --------------------
__global__ __launch_bounds__(256) void wtrans_kernel(
    const float* __restrict__ tw, const float* __restrict__ pw,
    const float* __restrict__ gw, const float* __restrict__ rw)
{
    int idx = blockIdx.x*256 + threadIdx.x;
    if (idx < 192*128) {
        float v;
        if (idx < 64*128)       v = tw[idx];
        else if (idx < 128*128) v = pw[idx - 64*128];
        else                    v = gw[idx - 128*128];
        g_WT16[idx] = __float2half(v);
    }
    if (idx < 128*64) g_rwT16[idx] = __float2half(rw[idx]);
    if (idx < Cc) { g_bnsum[idx] = 0.f; g_bnss[idx] = 0.f; }
}

// ---------------- projection (fp16 mma): [192m x 64n] tile, K=128 ----------
// As double-buffered via cp.async; epilogue stages in smem for coalesced out.
__global__ __launch_bounds__(256) void proj_kernel(
    int layer, const float* __restrict__ x,
    const float* __restrict__ tb, const float* __restrict__ pb,
    const float* __restrict__ gb)
{
    __shared__ __align__(16) __half SM[192*40*2 + 32*72];
    __half* As0 = SM;                  // [192][40]
    __half* As1 = SM + 192*40;
    __half* Bs  = SM + 192*40*2;       // [32][72]
    __half* U   = SM;                  // staging [vox 64][m 200] (aliases As)
    const int b = blockIdx.y, n0 = blockIdx.x*64, tid = threadIdx.x;
    if (blockIdx.x == 0 && blockIdx.y == 0 && tid < Bb*32) {
        g_gnsum[tid] = 0.f; g_gnss[tid] = 0.f;
    }
    const int warp = tid >> 5, lane = tid & 31;
    const int grp = lane >> 2, tig = lane & 3;
    const int m_base = (warp >> 1) * 48, n_base = (warp & 1) * 32;

    float acc[3][4][4];
    #pragma unroll
    for (int mt = 0; mt < 3; mt++)
        #pragma unroll
        for (int nt = 0; nt < 4; nt++)
            #pragma unroll
            for (int q = 0; q < 4; q++) acc[mt][nt][q] = 0.f;

    const unsigned A0addr = smaddr(&As0[(m_base + (lane & 15))*40 + (lane >> 4)*8]);
    const unsigned Baddr  = smaddr(&Bs[((lane & 7) + ((lane >> 3) & 1)*8)*72
                                       + n_base + (lane >> 4)*8]);

    // preload As chunk 0 (buf 0)
    {
        const int m = tid >> 2, kp = (tid & 3)*8;   // wait, 256 threads -> 768 chunks
    }
    #pragma unroll
    for (int it = 0; it < 3; it++) {
        int idx = it*256 + tid;
        int m = idx >> 2, kp = (idx & 3)*8;
        cpa16(&As0[m*40 + kp], &g_WT16[m*128 + kp]);
    }
    CPA_COMMIT();

    for (int k0 = 0; k0 < 128; k0 += 32) {
        const int buf = (k0 >> 5) & 1;
        __half* Acur = buf ? As1 : As0;
        // Bs chunk load (sync loads; layer0 converts fp32->fp16)
        {
            int kk = tid >> 3, n8 = (tid & 7)*8;
            size_t off = (size_t)(b*Cc + k0 + kk)*SP + n0 + n8;
            if (layer) {
                *(uint4*)&Bs[kk*72 + n8] = *(const uint4*)&g_hh[off];
            } else {
                const float* s = &x[off];
                float4 v0 = *(const float4*)s, v1 = *(const float4*)(s + 4);
                __half2 h0 = __floats2half2_rn(v0.x, v0.y);
                __half2 h1 = __floats2half2_rn(v0.z, v0.w);
                __half2 h2 = __floats2half2_rn(v1.x, v1.y);
                __half2 h3 = __floats2half2_rn(v1.z, v1.w);
                uint4 pk;
                pk.x = *(unsigned*)&h0; pk.y = *(unsigned*)&h1;
                pk.z = *(unsigned*)&h2; pk.w = *(unsigned*)&h3;
                *(uint4*)&Bs[kk*72 + n8] = pk;
            }
        }
        CPA_WAIT0();
        __syncthreads();
        // prefetch next As chunk into alternate buffer
        if (k0 + 32 < 128) {
            __half* Anext = buf ? As0 : As1;
            #pragma unroll
            for (int it = 0; it < 3; it++) {
                int idx = it*256 + tid;
                int m = idx >> 2, kp = (idx & 3)*8;
                cpa16(&Anext[m*40 + kp], &g_WT16[m*128 + k0 + 32 + kp]);
            }
            CPA_COMMIT();
        }
        const unsigned Aaddr = A0addr + (buf ? 192*40*2 : 0);
        #pragma unroll
        for (int kc = 0; kc < 2; kc++) {
            unsigned bv0[4], bv1[4];
            ldsm_x4_t(bv0, Baddr + kc*16*144);
            ldsm_x4_t(bv1, Baddr + kc*16*144 + 32);
            #pragma unroll
            for (int mt = 0; mt < 3; mt++) {
                unsigned af[4];
                ldsm_x4(af, Aaddr + mt*16*80 + kc*32);
                mma_f16(acc[mt][0], af, bv0);
                mma_f16(acc[mt][1], af, bv0 + 2);
                mma_f16(acc[mt][2], af, bv1);
                mma_f16(acc[mt][3], af, bv1 + 2);
            }
        }
        __syncthreads();
    }

    // ---- stage into U[vox][m] (bias added), then coalesced row stores ----
    #pragma unroll
    for (int mt = 0; mt < 3; mt++) {
        #pragma unroll
        for (int rr = 0; rr < 2; rr++) {
            const int r = m_base + mt*16 + rr*8 + grp;
            const float bv = (r < 64) ? tb[r] : (r < 128 ? pb[r-64] : gb[r-128]);
            #pragma unroll
            for (int nt = 0; nt < 4; nt++) {
                const int c = n_base + nt*8 + tig*2;
                U[ c   *200 + r] = __float2half(acc[mt][nt][rr*2 + 0] + bv);
                U[(c+1)*200 + r] = __float2half(acc[mt][nt][rr*2 + 1] + bv);
            }
        }
    }
    __syncthreads();
    #pragma unroll
    for (int it = 0; it < 6; it++) {
        int idx = it*256 + tid;               // 0..1535
        int seg = idx >> 9;                   // 0:T 1:P 2:G
        int rem = idx & 511;
        int vox = rem >> 3, ch = rem & 7;
        __half* dst = (seg == 0) ? g_T : ((seg == 1) ? g_P : g_G);
        uint4 val = *(const uint4*)&U[vox*200 + seg*64 + ch*8];
        *(uint4*)&dst[((size_t)b*SP + n0 + vox)*64 + ch*8] = val;
    }
}

// ---------------- merged D/H attention (blockIdx.y = direction 0/1) --------
__global__ __launch_bounds__(192) void attn01_kernel() {
    __shared__ __half Tl[48*72];
    __shared__ __half Pl[48*72];
    __shared__ __half Gl[48*72];
    __shared__ __half Sh[48*72];

    const int DIR = blockIdx.y;
    const int pid = blockIdx.x;
    const int b = pid / (Sd*Sd);
    const int rr = pid % (Sd*Sd);
    const int u = rr / Sd, v = rr % Sd;
    size_t base; int stride;
    if (DIR == 0) { base = (size_t)b*SP + u*Sd + v;    stride = Sd*Sd; }
    else          { base = (size_t)b*SP + u*Sd*Sd + v; stride = Sd;    }
    const int tid = threadIdx.x;
    const int warp = tid >> 5, lane = tid & 31;
    const int grp = lane >> 2, tig = lane & 3;

    for (int l = tid; l < 48*8; l += 192) {
        int i = l >> 3, k8 = (l & 7) * 8;
        size_t o = (base + (size_t)i*stride)*64 + k8;
        cpa16(&Gl[i*72 + k8], &g_G[o]);          // async; needed only for AV
        *(uint4*)&Tl[i*72 + k8] = *(const uint4*)&g_T[o];
        *(uint4*)&Pl[i*72 + k8] = *(const uint4*)&g_P[o];
    }
    CPA_COMMIT();
    __syncthreads();

    const int mrow0 = (warp >> 1) * 16;
    const int mr = mrow0 + grp;
    const int nhalf = (warp & 1) * 24;
    const int ncol0 = (warp & 1) * 32;

    const unsigned Ta = smaddr(&Tl[(mrow0 + (lane & 15))*72 + (lane >> 4)*8]);
    const unsigned Pa = smaddr(&Pl[(nhalf + (lane & 7))*72 + ((lane >> 3) & 1)*8]);
    const unsigned Ga = smaddr(&Gl[((lane & 7) + ((lane >> 3) & 1)*8)*72
                                   + ncol0 + (lane >> 4)*8]);

    float sacc[3][4];
    #pragma unroll
    for (int nt = 0; nt < 3; nt++)
        #pragma unroll
        for (int q = 0; q < 4; q++) sacc[nt][q] = 0.f;
    #pragma unroll
    for (int kc = 0; kc < 4; kc++) {
        unsigned af[4];
        ldsm_x4(af, Ta + kc*32);
        #pragma unroll
        for (int nt = 0; nt < 3; nt++) {
            unsigned bf[2];
            ldsm_x2(bf, Pa + nt*8*144 + kc*32);
            mma_f16(sacc[nt], af, bf);
        }
    }

    #pragma unroll
    for (int nt = 0; nt < 3; nt++) {
        const int j0 = nhalf + nt*8 + tig*2;
        float c0 = sacc[nt][0], c1 = sacc[nt][1], c2 = sacc[nt][2], c3 = sacc[nt][3];
        if (DIR != 0) {
            if (mr     == j0    ) c0 = -1e30f;
            if (mr     == j0 + 1) c1 = -1e30f;
            if (mr + 8 == j0    ) c2 = -1e30f;
            if (mr + 8 == j0 + 1) c3 = -1e30f;
        }
        *(__half2*)&Sh[ mr     *72 + j0] = __floats2half2_rn(c0, c1);
        *(__half2*)&Sh[(mr + 8)*72 + j0] = __floats2half2_rn(c2, c3);
    }
    __syncthreads();

    {
        const int r = tid >> 2, q = tid & 3;
        float vals[12];
        float mx = -3.0e38f;
        #pragma unroll
        for (int j = 0; j < 12; j += 2) {
            float2 vv = h2f2(*(const unsigned*)&Sh[r*72 + q*12 + j]);
            vals[j] = vv.x; vals[j+1] = vv.y;
            mx = fmaxf(mx, fmaxf(vv.x, vv.y));
        }
        mx = fmaxf(mx, __shfl_xor_sync(0xffffffffu, mx, 1));
        mx = fmaxf(mx, __shfl_xor_sync(0xffffffffu, mx, 2));
        float sm = 0.f;
        #pragma unroll
        for (int j = 0; j < 12; j++) {
            float e = __expf(vals[j] - mx);
            sm += e;
            Tl[r*72 + q*12 + j] = __float2half(e);
        }
        sm += __shfl_xor_sync(0xffffffffu, sm, 1);
        sm += __shfl_xor_sync(0xffffffffu, sm, 2);
        if (q == 0) {
            size_t vx = base + (size_t)r*stride;
            if (DIR == 0) { g_md[vx] = mx; g_sd[vx] = sm; }
            else          { g_mh[vx] = mx; g_sh[vx] = sm; }
        }
    }
    CPA_WAIT0();             // G tile now required
    __syncthreads();

    float yacc[4][4];
    #pragma unroll
    for (int nt = 0; nt < 4; nt++)
        #pragma unroll
        for (int q = 0; q < 4; q++) yacc[nt][q] = 0.f;
    #pragma unroll
    for (int kc = 0; kc < 3; kc++) {
        unsigned af[4];
        ldsm_x4(af, Ta + kc*32);
        #pragma unroll
        for (int pair = 0; pair < 2; pair++) {
            unsigned bv[4];
            ldsm_x4_t(bv, Ga + kc*16*144 + pair*32);
            mma_f16(yacc[pair*2],     af, bv);
            mma_f16(yacc[pair*2 + 1], af, bv + 2);
        }
    }

    __half* Yout = (DIR == 0) ? g_Yd : g_Yh;
    #pragma unroll
    for (int nt = 0; nt < 4; nt++) {
        const int c = ncol0 + nt*8 + tig*2;
        *(__half2*)&Yout[(base + (size_t)mr*stride)*64 + c] =
            __floats2half2_rn(yacc[nt][0], yacc[nt][1]);
        *(__half2*)&Yout[(base + (size_t)(mr + 8)*stride)*64 + c] =
            __floats2half2_rn(yacc[nt][2], yacc[nt][3]);
    }
}

// ---------------- W-direction attention + fused 3-way combine ---------------
__global__ __launch_bounds__(192) void attn2_kernel() {
    __shared__ __half Tl[48*72];
    __shared__ __half Pl[48*72];
    __shared__ __half Gl[48*72];
    __shared__ __half Sh[48*72];
    __shared__ float  rmS[48], rsS[48];

    const int pid = blockIdx.x;
    const int b = pid / (Sd*Sd);
    const int rr = pid % (Sd*Sd);
    const int u = rr / Sd, v = rr % Sd;
    const size_t base = (size_t)b*SP + u*Sd*Sd + v*Sd;   // stride 1
    const int tid = threadIdx.x;
    const int warp = tid >> 5, lane = tid & 31;
    const int grp = lane >> 2, tig = lane & 3;

    for (int l = tid; l < 48*8; l += 192) {
        int i = l >> 3, k8 = (l & 7) * 8;
        size_t o = (base + (size_t)i)*64 + k8;
        cpa16(&Gl[i*72 + k8], &g_G[o]);
        *(uint4*)&Tl[i*72 + k8] = *(const uint4*)&g_T[o];
        *(uint4*)&Pl[i*72 + k8] = *(const uint4*)&g_P[o];
    }
    CPA_COMMIT();
    __syncthreads();

    const int mrow0 = (warp >> 1) * 16;
    const int mr = mrow0 + grp;
    const int nhalf = (warp & 1) * 24;
    const int ncol0 = (warp & 1) * 32;

    const unsigned Ta = smaddr(&Tl[(mrow0 + (lane & 15))*72 + (lane >> 4)*8]);
    const unsigned Pa = smaddr(&Pl[(nhalf + (lane & 7))*72 + ((lane >> 3) & 1)*8]);
    const unsigned Ga = smaddr(&Gl[((lane & 7) + ((lane >> 3) & 1)*8)*72
                                   + ncol0 + (lane >> 4)*8]);

    float sacc[3][4];
    #pragma unroll
    for (int nt = 0; nt < 3; nt++)
        #pragma unroll
        for (int q = 0; q < 4; q++) sacc[nt][q] = 0.f;
    #pragma unroll
    for (int kc = 0; kc < 4; kc++) {
        unsigned af[4];
        ldsm_x4(af, Ta + kc*32);
        #pragma unroll
        for (int nt = 0; nt < 3; nt++) {
            unsigned bf[2];
            ldsm_x2(bf, Pa + nt*8*144 + kc*32);
            mma_f16(sacc[nt], af, bf);
        }
    }

    #pragma unroll
    for (int nt = 0; nt < 3; nt++) {
        const int j0 = nhalf + nt*8 + tig*2;
        float c0 = sacc[nt][0], c1 = sacc[nt][1], c2 = sacc[nt][2], c3 = sacc[nt][3];
        if (mr     == j0    ) c0 = -1e30f;
        if (mr     == j0 + 1) c1 = -1e30f;
        if (mr + 8 == j0    ) c2 = -1e30f;
        if (mr + 8 == j0 + 1) c3 = -1e30f;
        *(__half2*)&Sh[ mr     *72 + j0] = __floats2half2_rn(c0, c1);
        *(__half2*)&Sh[(mr + 8)*72 + j0] = __floats2half2_rn(c2, c3);
    }
    __syncthreads();

    {
        const int r = tid >> 2, q = tid & 3;
        float vals[12];
        float mx = -3.0e38f;
        #pragma unroll
        for (int j = 0; j < 12; j += 2) {
            float2 vv = h2f2(*(const unsigned*)&Sh[r*72 + q*12 + j]);
            vals[j] = vv.x; vals[j+1] = vv.y;
            mx = fmaxf(mx, fmaxf(vv.x, vv.y));
        }
        mx = fmaxf(mx, __shfl_xor_sync(0xffffffffu, mx, 1));
        mx = fmaxf(mx, __shfl_xor_sync(0xffffffffu, mx, 2));
        float sm = 0.f;
        #pragma unroll
        for (int j = 0; j < 12; j++) {
            float e = __expf(vals[j] - mx);
            sm += e;
            Tl[r*72 + q*12 + j] = __float2half(e);
        }
        sm += __shfl_xor_sync(0xffffffffu, sm, 1);
        sm += __shfl_xor_sync(0xffffffffu, sm, 2);
        if (q == 0) { rmS[r] = mx; rsS[r] = sm; }
    }
    CPA_WAIT0();
    __syncthreads();

    float yacc[4][4];
    #pragma unroll
    for (int nt = 0; nt < 4; nt++)
        #pragma unroll
        for (int q = 0; q < 4; q++) yacc[nt][q] = 0.f;
    #pragma unroll
    for (int kc = 0; kc < 3; kc++) {
        unsigned af[4];
        ldsm_x4(af, Ta + kc*32);
        #pragma unroll
        for (int pair = 0; pair < 2; pair++) {
            unsigned bv[4];
            ldsm_x4_t(bv, Ga + kc*16*144 + pair*32);
            mma_f16(yacc[pair*2],     af, bv);
            mma_f16(yacc[pair*2 + 1], af, bv + 2);
        }
    }

    #pragma unroll
    for (int nt = 0; nt < 4; nt++) {
        const int c = ncol0 + nt*8 + tig*2;
        *(__half2*)&Sh[ mr     *72 + c] = __floats2half2_rn(yacc[nt][0], yacc[nt][1]);
        *(__half2*)&Sh[(mr + 8)*72 + c] = __floats2half2_rn(yacc[nt][2], yacc[nt][3]);
    }
    __syncthreads();

    // fused 3-way combine: thread = (voxel pair, 8 g-values); half2 g-major out
    {
        const int ip = tid >> 3;
        const int g0 = (tid & 7) * 8;
        const int i0 = ip*2, i1 = i0 + 1;
        const size_t vox0 = base + i0, vox1 = base + i1;

        float md0 = g_md[vox0], sd0 = g_sd[vox0];
        float mh0 = g_mh[vox0], sh0 = g_sh[vox0];
        float mw0 = rmS[i0],    sw0 = rsS[i0];
        float m0  = fmaxf(md0, fmaxf(mh0, mw0));
        float wd0 = __expf(md0 - m0), wh0 = __expf(mh0 - m0), ww0 = __expf(mw0 - m0);
        float iv0 = 1.0f / (sd0*wd0 + sh0*wh0 + sw0*ww0);
        wd0 *= iv0; wh0 *= iv0; ww0 *= iv0;

        float md1 = g_md[vox1], sd1 = g_sd[vox1];
        float mh1 = g_mh[vox1], sh1 = g_sh[vox1];
        float mw1 = rmS[i1],    sw1 = rsS[i1];
        float m1  = fmaxf(md1, fmaxf(mh1, mw1));
        float wd1 = __expf(md1 - m1), wh1 = __expf(mh1 - m1), ww1 = __expf(mw1 - m1);
        float iv1 = 1.0f / (sd1*wd1 + sh1*wh1 + sw1*ww1);
        wd1 *= iv1; wh1 *= iv1; ww1 *= iv1;

        uint4 a0u = *(const uint4*)&g_Yd[vox0*64 + g0];
        uint4 a1u = *(const uint4*)&g_Yd[vox1*64 + g0];
        uint4 h0u = *(const uint4*)&g_Yh[vox0*64 + g0];
        uint4 h1u = *(const uint4*)&g_Yh[vox1*64 + g0];
        uint4 y0u = *(const uint4*)&Sh[i0*72 + g0];
        uint4 y1u = *(const uint4*)&Sh[i1*72 + g0];
        const unsigned* a0 = (const unsigned*)&a0u;
        const unsigned* a1 = (const unsigned*)&a1u;
        const unsigned* h0 = (const unsigned*)&h0u;
        const unsigned* h1 = (const unsigned*)&h1u;
        const unsigned* y0 = (const unsigned*)&y0u;
        const unsigned* y1 = (const unsigned*)&y1u;

        const size_t sp0 = base - (size_t)b*SP;
        #pragma unroll
        for (int q = 0; q < 4; q++) {
            float2 av0 = h2f2(a0[q]), hv0 = h2f2(h0[q]), yv0 = h2f2(y0[q]);
            float2 av1 = h2f2(a1[q]), hv1 = h2f2(h1[q]), yv1 = h2f2(y1[q]);
            float o0a = av0.x*wd0 + hv0.x*wh0 + yv0.x*ww0;
            float o0b = av0.y*wd0 + hv0.y*wh0 + yv0.y*ww0;
            float o1a = av1.x*wd1 + hv1.x*wh1 + yv1.x*ww1;
            float o1b = av1.y*wd1 + hv1.y*wh1 + yv1.y*ww1;
            int g = g0 + q*2;
            *(__half2*)&g_Yw[((size_t)(b*64 + g    ))*SP + sp0 + i0] =
                __floats2half2_rn(o0a, o1a);
            *(__half2*)&g_Yw[((size_t)(b*64 + g + 1))*SP + sp0 + i0] =
                __floats2half2_rn(o0b, o1b);
        }
    }
}

// ---------------- cross GEMM (fp16 mma): [128ch x 64vox], K=64 + GN sums ---
// Full-K Bs load (single sync); epilogue stages in As, coalesced row stores.
__global__ __launch_bounds__(256) void cross_kernel(const float* __restrict__ rb)
{
    __shared__ __half As[128*72];   // rw [m=ch][k=g] -> output staging [ch][vox]
    __shared__ __half Bs[64*72];    // Y  [k=g 64][n]
    __shared__ float gsum[32], gss[32];
    const int b = blockIdx.y, n0 = blockIdx.x*64, tid = threadIdx.x;
    const int warp = tid >> 5, lane = tid & 31;
    const int grp = lane >> 2, tig = lane & 3;
    const int m_base = (warp >> 1) * 32, n_base = (warp & 1) * 32;

    float acc[2][4][4];
    #pragma unroll
    for (int mt = 0; mt < 2; mt++)
        #pragma unroll
        for (int nt = 0; nt < 4; nt++)
            #pragma unroll
            for (int q = 0; q < 4; q++) acc[mt][nt][q] = 0.f;

    #pragma unroll
    for (int it = 0; it < 4; it++) {
        int idx = it*256 + tid;
        int m = idx >> 3, kp = (idx & 7)*8;
        *(uint4*)&As[m*72 + kp] = *(const uint4*)&g_rwT16[m*64 + kp];
    }
    #pragma unroll
    for (int it = 0; it < 2; it++) {
        int idx = it*256 + tid;                 // 0..511
        int kk = idx >> 3, n8 = (idx & 7)*8;
        *(uint4*)&Bs[kk*72 + n8] =
            *(const uint4*)&g_Yw[((size_t)b*64 + kk)*SP + n0 + n8];
    }
    if (tid < 32) { gsum[tid] = 0.f; gss[tid] = 0.f; }

    const unsigned Aaddr = smaddr(&As[(m_base + (lane & 15))*72 + (lane >> 4)*8]);
    const unsigned Baddr = smaddr(&Bs[((lane & 7) + ((lane >> 3) & 1)*8)*72
                                      + n_base + (lane >> 4)*8]);
    __syncthreads();

    #pragma unroll
    for (int kk = 0; kk < 4; kk++) {
        unsigned bv0[4], bv1[4];
        ldsm_x4_t(bv0, Baddr + kk*16*144);
        ldsm_x4_t(bv1, Baddr + kk*16*144 + 32);
        #pragma unroll
        for (int mt = 0; mt < 2; mt++) {
            unsigned af[4];
            ldsm_x4(af, Aaddr + mt*16*144 + kk*32);
            mma_f16(acc[mt][0], af, bv0);
            mma_f16(acc[mt][1], af, bv0 + 2);
            mma_f16(acc[mt][2], af, bv1);
            mma_f16(acc[mt][3], af, bv1 + 2);
        }
    }
    __syncthreads();

    // ---- stage output tile [ch][vox] into As + GN partial sums ----
    #pragma unroll
    for (int mt = 0; mt < 2; mt++) {
        #pragma unroll
        for (int rr = 0; rr < 2; rr++) {
            const int r = m_base + mt*16 + rr*8 + grp;
            const float bv = rb[r];
            float ps = 0.f, pss = 0.f;
            #pragma unroll
            for (int nt = 0; nt < 4; nt++) {
                const int c = n_base + nt*8 + tig*2;
                float v0 = acc[mt][nt][rr*2 + 0] + bv;
                float v1 = acc[mt][nt][rr*2 + 1] + bv;
                *(__half2*)&As[r*72 + c] = __floats2half2_rn(v0, v1);
                ps += v0 + v1; pss += v0*v0 + v1*v1;
            }
            ps  += __shfl_xor_sync(0xffffffffu, ps, 1);
            ps  += __shfl_xor_sync(0xffffffffu, ps, 2);
            pss += __shfl_xor_sync(0xffffffffu, pss, 1);
            pss += __shfl_xor_sync(0xffffffffu, pss, 2);
            if (tig == 0) {
                atomicAdd(&gsum[r >> 2], ps);
                atomicAdd(&gss [r >> 2], pss);
            }
        }
    }
    __syncthreads();
    #pragma unroll
    for (int it = 0; it < 4; it++) {
        int idx = it*256 + tid;               // 0..1023
        int r = idx >> 3, ch = idx & 7;
        *(uint4*)&g_cross[((size_t)b*Cc + r)*SP + n0 + ch*8] =
            *(const uint4*)&As[r*72 + ch*8];
    }
    if (tid < 32) {
        atomicAdd(&g_gnsum[b*32 + tid], gsum[tid]);
        atomicAdd(&g_gnss [b*32 + tid], gss[tid]);
    }
}

// ---------------- GroupNorm + residual (streaming, channel-first) ----------
__global__ __launch_bounds__(256) void gnres_kernel(
    int layer, const float* __restrict__ x,
    const float* __restrict__ gnw, const float* __restrict__ gnb,
    int accum_bn)
{
    const int c = blockIdx.y, b = blockIdx.z, chunk = blockIdx.x;
    const size_t base = ((size_t)(b*Cc + c))*SP + (size_t)chunk*(SP/4);
    const int g = c >> 2;
    const float invN = 1.0f / (4.0f * SP);
    float mu  = g_gnsum[b*32 + g] * invN;
    float var = g_gnss[b*32 + g] * invN - mu*mu;
    float rstd = rsqrtf(var + 1e-5f);
    float w = gnw[c], bias = gnb[c];
    float s = 0.f, ss = 0.f;
    for (int j = 0; j < 27; j++) {
        size_t o = base + (size_t)j*1024 + threadIdx.x*4;
        uint2 ch = *(const uint2*)&g_cross[o];
        float2 c01 = h2f2(ch.x), c23 = h2f2(ch.y);
        float4 rv;
        if (layer) {
            uint2 hv = *(const uint2*)&g_hh[o];
            float2 r01 = h2f2(hv.x), r23 = h2f2(hv.y);
            rv.x = r01.x; rv.y = r01.y; rv.z = r23.x; rv.w = r23.y;
        } else {
            rv = *(const float4*)&x[o];
        }
        float4 h;
        h.x = rv.x + (c01.x - mu)*rstd*w + bias;
        h.y = rv.y + (c01.y - mu)*rstd*w + bias;
        h.z = rv.z + (c23.x - mu)*rstd*w + bias;
        h.w = rv.w + (c23.y - mu)*rstd*w + bias;
        uint2 hw;
        __half2 w0 = __floats2half2_rn(h.x, h.y);
        __half2 w1 = __floats2half2_rn(h.z, h.w);
        hw.x = *(unsigned*)&w0; hw.y = *(unsigned*)&w1;
        *(uint2*)&g_hh[o] = hw;
        if (accum_bn) {
            s  += h.x + h.y + h.z + h.w;
            ss += h.x*h.x + h.y*h.y + h.z*h.z + h.w*h.w;
        }
    }
    if (accum_bn) {
        #pragma unroll
        for (int o = 16; o > 0; o >>= 1) {
            s  += __shfl_xor_sync(0xffffffffu, s,  o);
            ss += __shfl_xor_sync(0xffffffffu, ss, o);
        }
        __shared__ float ws[8], wss[8];
        int wid = threadIdx.x >> 5, lane = threadIdx.x & 31;
        if (lane == 0) { ws[wid] = s; wss[wid] = ss; }
        __syncthreads();
        if (threadIdx.x == 0) {
            float ts = 0.f, tss = 0.f;
            #pragma unroll
            for (int k = 0; k < 8; k++) { ts += ws[k]; tss += wss[k]; }
            atomicAdd(&g_bnsum[c], ts);
            atomicAdd(&g_bnss[c],  tss);
        }
    }
}

// ---------------- BatchNorm apply + ReLU ------------------------------------
__global__ __launch_bounds__(256) void bnapply_kernel(
    const float* __restrict__ bw, const float* __restrict__ bb, float* __restrict__ out)
{
    size_t i4 = (size_t)blockIdx.x*256 + threadIdx.x;
    if (i4 >= (size_t)Bb*Cc*SP/4) return;
    size_t i = i4 * 4;
    int c = (int)((i / SP) & 127);
    const float invN = 1.0f / ((float)Bb * SP);
    float mu  = g_bnsum[c] * invN;
    float var = g_bnss[c] * invN - mu*mu;
    float rstd = rsqrtf(var + 1e-5f);
    float wv = bw[c], bv = bb[c];
    uint2 hv = *(const uint2*)&g_hh[i];
    float2 v01 = h2f2(hv.x), v23 = h2f2(hv.y);
    float4 v;
    v.x = fmaxf((v01.x - mu)*rstd*wv + bv, 0.f);
    v.y = fmaxf((v01.y - mu)*rstd*wv + bv, 0.f);
    v.z = fmaxf((v23.x - mu)*rstd*wv + bv, 0.f);
    v.w = fmaxf((v23.y - mu)*rstd*wv + bv, 0.f);
    *(float4*)&out[i] = v;
}

// ---------------- launch -----------------------------------------------------
extern "C" void kernel_launch(void* const* d_in, const int* in_sizes, int n_in,
                              void* d_out, int out_size)
{
    const float* x   = (const float*)d_in[0];
    const float* tw  = (const float*)d_in[1];
    const float* tb  = (const float*)d_in[2];
    const float* pw  = (const float*)d_in[3];
    const float* pb  = (const float*)d_in[4];
    const float* gw  = (const float*)d_in[5];
    const float* gb  = (const float*)d_in[6];
    const float* rw  = (const float*)d_in[7];
    const float* rb  = (const float*)d_in[8];
    const float* gnw = (const float*)d_in[9];
    const float* gnb = (const float*)d_in[10];
    const float* bnw = (const float*)d_in[11];
    const float* bnb = (const float*)d_in[12];
    float* out = (float*)d_out;

    wtrans_kernel<<<96, 256>>>(tw, pw, gw, rw);

    for (int layer = 0; layer < 2; layer++) {
        proj_kernel<<<dim3(SP/64, Bb), 256>>>(layer, x, tb, pb, gb);
        attn01_kernel<<<dim3(Bb*Sd*Sd, 2), 192>>>();
        attn2_kernel<<<Bb*Sd*Sd, 192>>>();
        cross_kernel<<<dim3(SP/64, Bb), 256>>>(rb);
        gnres_kernel<<<dim3(4, Cc, Bb), 256>>>(layer, x, gnw + layer*Cc, gnb + layer*Cc,
                                               layer == 1 ? 1 : 0);
    }
    bnapply_kernel<<<((Bb*Cc*SP/4) + 255)/256, 256>>>(bnw, bnb, out);
}